// round 3
// baseline (speedup 1.0000x reference)
#include <cuda_runtime.h>
#include <math.h>

// ---------------- problem constants ----------------
#define BP_  2
#define L_   32
#define N_   16
#define O_   64
#define D_   1024
#define AD_  1024
#define AAN_ 8
#define HEAD_ 128
#define W_   256
#define FH_  2048
#define M_   48      // O - N
#define E_   64
#define S_   2048    // L * E
#define EPS_ 1e-5f

// ---------------- device scratch (allocation-free) ----------------
__device__ float g_x   [BP_ * S_ * AD_];
__device__ float g_h   [BP_ * S_ * AD_];
__device__ float g_qkv [BP_ * S_ * 3 * AD_];
__device__ float g_attn[BP_ * S_ * AD_];
__device__ float g_up  [BP_ * S_ * 2 * FH_];
__device__ float g_gate[BP_ * S_ * FH_];
__device__ float g_xold[BP_ * L_ * M_ * AD_];
__device__ float g_xnew[BP_ * L_ * N_ * AD_];
__device__ float g_xarn[BP_ * L_ * N_ * D_];
__device__ float g_xden[BP_ * L_ * N_ * D_];
__device__ float g_y   [BP_ * L_ * N_ * AD_];
__device__ float g_y2  [BP_ * L_ * N_ * AD_];
__device__ unsigned char g_mask[BP_ * S_ * S_];

// ---------------- block reductions ----------------
__device__ __forceinline__ float blk_sum(float v, float* red) {
    int lane = threadIdx.x & 31, w = threadIdx.x >> 5;
#pragma unroll
    for (int o = 16; o; o >>= 1) v += __shfl_xor_sync(0xffffffffu, v, o);
    if (lane == 0) red[w] = v;
    __syncthreads();
    int nw = (blockDim.x + 31) >> 5;
    if (threadIdx.x < 32) {
        float r = (threadIdx.x < nw) ? red[threadIdx.x] : 0.f;
#pragma unroll
        for (int o = 16; o; o >>= 1) r += __shfl_xor_sync(0xffffffffu, r, o);
        if (lane == 0) red[0] = r;
    }
    __syncthreads();
    float r = red[0];
    __syncthreads();
    return r;
}

__device__ __forceinline__ float blk_max(float v, float* red) {
    int lane = threadIdx.x & 31, w = threadIdx.x >> 5;
#pragma unroll
    for (int o = 16; o; o >>= 1) v = fmaxf(v, __shfl_xor_sync(0xffffffffu, v, o));
    if (lane == 0) red[w] = v;
    __syncthreads();
    int nw = (blockDim.x + 31) >> 5;
    if (threadIdx.x < 32) {
        float r = (threadIdx.x < nw) ? red[threadIdx.x] : -INFINITY;
#pragma unroll
        for (int o = 16; o; o >>= 1) r = fmaxf(r, __shfl_xor_sync(0xffffffffu, r, o));
        if (lane == 0) red[0] = r;
    }
    __syncthreads();
    float r = red[0];
    __syncthreads();
    return r;
}

// ---------------- SGEMM: C[M,N] = A[M,K] @ B[N,K]^T (optionally +=) ----------------
// 128x128 tile, BK=8, 256 threads, 8x8 per thread. M,N multiples of 128, K of 8.
template<bool ACC>
__global__ void __launch_bounds__(256) sgemm_k(const float* __restrict__ A,
                                               const float* __restrict__ B,
                                               float* __restrict__ C,
                                               int M, int N, int K) {
    __shared__ float As[8][136];   // 136*4 = 544 bytes/row, 16B multiple -> aligned LDS.128
    __shared__ float Bs[8][136];
    int tid  = threadIdx.x;
    int brow = blockIdx.y * 128;
    int bcol = blockIdx.x * 128;
    int lr = tid >> 1;             // 0..127
    int lk = (tid & 1) << 2;       // 0 or 4
    int ty = tid >> 4, tx = tid & 15;

    const float* Ap = A + (size_t)(brow + lr) * K + lk;
    const float* Bp = B + (size_t)(bcol + lr) * K + lk;

    float acc[8][8];
#pragma unroll
    for (int i = 0; i < 8; i++)
#pragma unroll
        for (int j = 0; j < 8; j++) acc[i][j] = 0.f;

    for (int k0 = 0; k0 < K; k0 += 8) {
        float4 av = *(const float4*)(Ap + k0);
        float4 bv = *(const float4*)(Bp + k0);
        As[lk + 0][lr] = av.x; As[lk + 1][lr] = av.y;
        As[lk + 2][lr] = av.z; As[lk + 3][lr] = av.w;
        Bs[lk + 0][lr] = bv.x; Bs[lk + 1][lr] = bv.y;
        Bs[lk + 2][lr] = bv.z; Bs[lk + 3][lr] = bv.w;
        __syncthreads();
#pragma unroll
        for (int kk = 0; kk < 8; kk++) {
            float ar[8], br[8];
            *(float4*)&ar[0] = *(const float4*)&As[kk][ty * 8];
            *(float4*)&ar[4] = *(const float4*)&As[kk][ty * 8 + 4];
            *(float4*)&br[0] = *(const float4*)&Bs[kk][tx * 8];
            *(float4*)&br[4] = *(const float4*)&Bs[kk][tx * 8 + 4];
#pragma unroll
            for (int i = 0; i < 8; i++)
#pragma unroll
                for (int j = 0; j < 8; j++) acc[i][j] += ar[i] * br[j];
        }
        __syncthreads();
    }

#pragma unroll
    for (int i = 0; i < 8; i++) {
        float* cp = C + (size_t)(brow + ty * 8 + i) * N + bcol + tx * 8;
        float4 c0 = make_float4(acc[i][0], acc[i][1], acc[i][2], acc[i][3]);
        float4 c1 = make_float4(acc[i][4], acc[i][5], acc[i][6], acc[i][7]);
        if (ACC) {
            float4 o0 = *(const float4*)cp;
            float4 o1 = *(const float4*)(cp + 4);
            c0.x += o0.x; c0.y += o0.y; c0.z += o0.z; c0.w += o0.w;
            c1.x += o1.x; c1.y += o1.y; c1.z += o1.z; c1.w += o1.w;
        }
        *(float4*)cp = c0;
        *(float4*)(cp + 4) = c1;
    }
}

// ---------------- rmsnorm: out[r,:] = in[map(r),:] * rsqrt(mean sq + eps) * w ----------------
__global__ void rmsnorm_k(const float* __restrict__ in, const float* __restrict__ w,
                          float* __restrict__ out, int gsize, int gstride, int goff) {
    __shared__ float red[32];
    int r = blockIdx.x;
    int inrow = (r / gsize) * gstride + goff + (r % gsize);
    const float* x = in + (size_t)inrow * 1024;
    float* o = out + (size_t)r * 1024;
    float v[4]; float ss = 0.f;
#pragma unroll
    for (int i = 0; i < 4; i++) { v[i] = x[threadIdx.x + i * 256]; ss += v[i] * v[i]; }
    ss = blk_sum(ss, red);
    float sc = rsqrtf(ss * (1.f / 1024.f) + EPS_);
#pragma unroll
    for (int i = 0; i < 4; i++) {
        int idx = threadIdx.x + i * 256;
        o[idx] = v[i] * sc * w[idx];
    }
}

// ---------------- fused shifted-y + rmsnorm (refresh path) ----------------
// begin is read as 4-byte elements (int32 or float32 bit pattern): nonzero test.
__global__ void yfrms_k(const float* __restrict__ y, const int* __restrict__ begin,
                        const float* __restrict__ pad_emb, const float* __restrict__ w,
                        float* __restrict__ out) {
    __shared__ float red[32];
    int r = blockIdx.x;            // 0..1023 : b*512 + t
    int b = r >> 9, t = r & 511;
    int n = t & 15, l = t >> 4;
    bool cond = (n == 0) && (begin[b * 32 + l] != 0);
    const float* x = cond ? pad_emb
                          : (y + ((size_t)b * 512 + ((t + 511) & 511)) * 1024);
    float* o = out + (size_t)r * 1024;
    float v[4]; float ss = 0.f;
#pragma unroll
    for (int i = 0; i < 4; i++) { v[i] = x[threadIdx.x + i * 256]; ss += v[i] * v[i]; }
    ss = blk_sum(ss, red);
    float sc = rsqrtf(ss * (1.f / 1024.f) + EPS_);
#pragma unroll
    for (int i = 0; i < 4; i++) {
        int idx = threadIdx.x + i * 256;
        o[idx] = v[i] * sc * w[idx];
    }
}

// ---------------- l2norm + rotary on q,k in-place in qkv ----------------
__global__ void qk_rope_k(float* __restrict__ qkv) {
    __shared__ float red[32];
    __shared__ float sh[128];
    int s = blockIdx.x, hk = blockIdx.y, b = blockIdx.z;
    int h = hk >> 1;
    int off = (hk & 1) ? 1024 : 0;
    float* p = qkv + ((size_t)(b * 2048 + s)) * 3072 + off + h * 128;
    int tid = threadIdx.x;
    float v = p[tid];
    float ss = blk_sum(v * v, red);
    float scl = 1.f / fmaxf(sqrtf(ss), EPS_);
    sh[tid] = v * scl;
    __syncthreads();
    int j = tid & 63;
    double invf_d = exp(-(double)j * (9.210340371976184 / 64.0));
    float invf = (float)invf_d;
    float ang = (float)s * invf;
    float c = cosf(ang), sn = sinf(ang);
    float x1 = sh[j], x2 = sh[j + 64];
    float outv = (tid < 64) ? (x1 * c + x2 * sn) : (-x1 * sn + x2 * c);
    p[tid] = outv;
}

// ---------------- mask build ----------------
__global__ void mask_k(const int* __restrict__ doc, unsigned char* __restrict__ mask) {
    int q = blockIdx.x, b = blockIdx.y;
    int qb = q >> 6, qr = q & 63;
    bool newq = qr >= 48;
    int docq = doc[b * 32 + qb];
    int posq = qr + qb * 16;
    unsigned char* mrow = mask + ((size_t)(b * 2048 + q)) * 2048;
#pragma unroll
    for (int i = 0; i < 8; i++) {
        int k = threadIdx.x + i * 256;
        int kb = k >> 6, kr = k & 63;
        bool newk = kr >= 48;
        int dock  = doc[b * 32 + kb];
        int dockp = doc[b * 32 + (kb > 0 ? kb - 1 : 0)];
        int posk = kr + kb * 16;
        bool nn = newq && newk && (q >= k) && (posq < posk + W_) && (docq == dock);
        bool ao = ((newq && (docq == dockp)) || !newq) && !newk && (qb == kb);
        mrow[k] = (nn || ao) ? 1 : 0;
    }
}

// ---------------- attention: one block per (b, h, q) ----------------
__global__ void __launch_bounds__(128) attn_k(const float* __restrict__ qkv,
                                              const unsigned char* __restrict__ mask,
                                              float* __restrict__ out) {
    __shared__ float qs[128];
    __shared__ float sc[2048];
    __shared__ float red[32];
    int q = blockIdx.x, h = blockIdx.y, b = blockIdx.z;
    int tid = threadIdx.x;
    int lane = tid & 31, warp = tid >> 5;

    const float* qp = qkv + ((size_t)(b * 2048 + q)) * 3072 + h * 128;
    qs[tid] = qp[tid];
    __syncthreads();
    float4 q4 = *(const float4*)&qs[lane * 4];

    // scores
    const float* Kb = qkv + (size_t)b * 2048 * 3072 + 1024 + h * 128 + lane * 4;
    for (int kk = warp; kk < 2048; kk += 4) {
        float4 kv = *(const float4*)(Kb + (size_t)kk * 3072);
        float d = q4.x * kv.x + q4.y * kv.y + q4.z * kv.z + q4.w * kv.w;
#pragma unroll
        for (int o = 16; o; o >>= 1) d += __shfl_xor_sync(0xffffffffu, d, o);
        if (lane == 0) sc[kk] = d;
    }
    __syncthreads();

    // masked softmax
    const unsigned char* mrow = mask + ((size_t)(b * 2048 + q)) * 2048;
    const float scale = 0.088388347648318447f;  // 1/sqrt(128)
    float vals[16];
    float mx = -INFINITY;
#pragma unroll
    for (int i = 0; i < 16; i++) {
        int k = tid + i * 128;
        float v = mrow[k] ? sc[k] * scale : -INFINITY;
        vals[i] = v;
        mx = fmaxf(mx, v);
    }
    mx = blk_max(mx, red);
    float sum = 0.f;
#pragma unroll
    for (int i = 0; i < 16; i++) {
        int k = tid + i * 128;
        float p = (vals[i] > -INFINITY) ? expf(vals[i] - mx) : 0.f;
        sc[k] = p;
        sum += p;
    }
    sum = blk_sum(sum, red);
    float inv = 1.f / sum;

    // probs @ V  (thread = output dim)
    const float* Vb = qkv + (size_t)b * 2048 * 3072 + 2048 + h * 128 + tid;
    float a0 = 0.f, a1 = 0.f, a2 = 0.f, a3 = 0.f;
    for (int k = 0; k < 2048; k += 4) {
        a0 += sc[k    ] * Vb[(size_t)(k    ) * 3072];
        a1 += sc[k + 1] * Vb[(size_t)(k + 1) * 3072];
        a2 += sc[k + 2] * Vb[(size_t)(k + 2) * 3072];
        a3 += sc[k + 3] * Vb[(size_t)(k + 3) * 3072];
    }
    out[((size_t)(b * 2048 + q)) * 1024 + h * 128 + tid] = (a0 + a1 + a2 + a3) * inv;
}

// ---------------- silu-gate ----------------
__global__ void silu_gate_k(const float* __restrict__ up, float* __restrict__ gate) {
    int idx = blockIdx.x * blockDim.x + threadIdx.x;
    if (idx >= BP_ * S_ * FH_) return;
    int r = idx >> 11, c = idx & 2047;
    float a = up[(size_t)r * 4096 + c];
    float bb = up[(size_t)r * 4096 + 2048 + c];
    gate[idx] = (a / (1.f + expf(-a))) * bb;
}

// ---------------- assemble x from x_old / x_new ----------------
__global__ void assemble_k(float* __restrict__ x, const float* __restrict__ xold,
                           const float* __restrict__ xnew) {
    int idx = blockIdx.x * blockDim.x + threadIdx.x;
    if (idx >= BP_ * S_ * 256) return;
    int d4 = idx & 255;
    int gr = idx >> 8;
    int b = gr >> 11, s = gr & 2047;
    int l = s >> 6, rr = s & 63;
    float4 v;
    if (rr < 48)
        v = ((const float4*)xold)[((size_t)((b * 32 + l) * 48 + rr)) * 256 + d4];
    else
        v = ((const float4*)xnew)[((size_t)((b * 32 + l) * 16 + (rr - 48))) * 256 + d4];
    ((float4*)x)[idx] = v;
}

// ---------------- extract y = x[:, :, M:, :] ----------------
__global__ void extract_y_k(const float* __restrict__ x, float* __restrict__ y) {
    int idx = blockIdx.x * blockDim.x + threadIdx.x;
    if (idx >= BP_ * 512 * 256) return;
    int d4 = idx & 255;
    int r = idx >> 8;
    int b = r >> 9, t = r & 511;
    int l = t >> 4, n = t & 15;
    int xr = b * 2048 + l * 64 + 48 + n;
    ((float4*)y)[idx] = ((const float4*)x)[(size_t)xr * 256 + d4];
}

// ---------------- host-side launch ----------------
static void gemm(const float* A, const float* B, float* C, int M, int N, int K, bool acc) {
    dim3 grid(N / 128, M / 128);
    if (acc) sgemm_k<true><<<grid, 256>>>(A, B, C, M, N, K);
    else     sgemm_k<false><<<grid, 256>>>(A, B, C, M, N, K);
}

extern "C" void kernel_launch(void* const* d_in, const int* in_sizes, int n_in,
                              void* d_out, int out_size) {
    (void)in_sizes; (void)n_in; (void)out_size;
    const float* x_input     = (const float*)d_in[0];
    const float* x_ar        = (const float*)d_in[1];
    const int*   doc         = (const int*)d_in[2];
    const int*   begin       = (const int*)d_in[3];   // bool coerced to 4-byte elems
    const float* old_norm_w  = (const float*)d_in[4];
    const float* new_norm_w  = (const float*)d_in[5];
    const float* w_old       = (const float*)d_in[6];
    const float* w_ar        = (const float*)d_in[7];
    const float* w_de        = (const float*)d_in[8];
    const float* w_ar1       = (const float*)d_in[9];
    const float* w_de1       = (const float*)d_in[10];
    const float* w_y1        = (const float*)d_in[11];
    const float* pad_emb     = (const float*)d_in[12];
    const float* w_agg       = (const float*)d_in[13];
    const float* attn_norm_w = (const float*)d_in[14];
    const float* ffn_norm_w  = (const float*)d_in[15];
    const float* w_qkv       = (const float*)d_in[16];
    const float* w_o         = (const float*)d_in[17];
    const float* w_up        = (const float*)d_in[18];
    const float* w_down      = (const float*)d_in[19];
    float* out = (float*)d_out;

    float *x, *h, *qkv, *attn, *up, *gate, *xold, *xnew, *xarn, *xden, *y, *y2;
    unsigned char* mask;
    cudaGetSymbolAddress((void**)&x,    g_x);
    cudaGetSymbolAddress((void**)&h,    g_h);
    cudaGetSymbolAddress((void**)&qkv,  g_qkv);
    cudaGetSymbolAddress((void**)&attn, g_attn);
    cudaGetSymbolAddress((void**)&up,   g_up);
    cudaGetSymbolAddress((void**)&gate, g_gate);
    cudaGetSymbolAddress((void**)&xold, g_xold);
    cudaGetSymbolAddress((void**)&xnew, g_xnew);
    cudaGetSymbolAddress((void**)&xarn, g_xarn);
    cudaGetSymbolAddress((void**)&xden, g_xden);
    cudaGetSymbolAddress((void**)&y,    g_y);
    cudaGetSymbolAddress((void**)&y2,   g_y2);
    cudaGetSymbolAddress((void**)&mask, g_mask);

    // mask (reused by all layer passes)
    mask_k<<<dim3(2048, 2), 256>>>(doc, mask);

    // input projections
    rmsnorm_k<<<3072, 256>>>(x_input, old_norm_w, h, 48, 64, 0);     // x_old_n
    gemm(h, w_old, xold, 3072, 1024, 1024, false);
    rmsnorm_k<<<1024, 256>>>(x_ar, new_norm_w, xarn, 16, 16, 0);     // x_ar_n
    rmsnorm_k<<<1024, 256>>>(x_input, new_norm_w, xden, 16, 64, 48); // x_de_n
    gemm(xarn, w_ar, xnew, 1024, 1024, 1024, false);
    gemm(xden, w_de, xnew, 1024, 1024, 1024, true);
    assemble_k<<<(BP_ * S_ * 256 + 255) / 256, 256>>>(x, xold, xnew);

    for (int it = 0; it < 2; it++) {
        for (int li = 0; li < 2; li++) {
            rmsnorm_k<<<4096, 256>>>(x, attn_norm_w + li * 1024, h, 1, 1, 0);
            gemm(h, w_qkv + (size_t)li * 3072 * 1024, qkv, 4096, 3072, 1024, false);
            qk_rope_k<<<dim3(2048, 16, 2), 128>>>(qkv);
            attn_k<<<dim3(2048, 8, 2), 128>>>(qkv, mask, attn);
            gemm(attn, w_o + (size_t)li * 1024 * 1024, x, 4096, 1024, 1024, true);
            rmsnorm_k<<<4096, 256>>>(x, ffn_norm_w + li * 1024, h, 1, 1, 0);
            gemm(h, w_up + (size_t)li * 4096 * 1024, up, 4096, 4096, 1024, false);
            silu_gate_k<<<(BP_ * S_ * FH_ + 255) / 256, 256>>>(up, gate);
            gemm(gate, w_down + (size_t)li * 1024 * 2048, x, 4096, 1024, 2048, true);
        }
        extract_y_k<<<(BP_ * 512 * 256 + 255) / 256, 256>>>(x, y);
        if (it == 0) {
            yfrms_k<<<1024, 256>>>(y, begin, pad_emb, new_norm_w, y2);
            gemm(xarn, w_ar1, xnew, 1024, 1024, 1024, false);
            gemm(y2,   w_y1,  xnew, 1024, 1024, 1024, true);
            gemm(xden, w_de1, xnew, 1024, 1024, 1024, true);
            assemble_k<<<(BP_ * S_ * 256 + 255) / 256, 256>>>(x, xold, xnew);
        }
    }

    gemm(y, w_agg, out, 1024, 1024, 1024, false);
}

// round 4
// speedup vs baseline: 2.5054x; 2.5054x over previous
#include <cuda_runtime.h>
#include <math.h>

// ---------------- problem constants ----------------
#define BP_  2
#define L_   32
#define N_   16
#define O_   64
#define D_   1024
#define AD_  1024
#define AAN_ 8
#define HEAD_ 128
#define W_   256
#define FH_  2048
#define M_   48      // O - N
#define E_   64
#define S_   2048    // L * E
#define EPS_ 1e-5f

// ---------------- device scratch (allocation-free) ----------------
__device__ float g_x   [BP_ * S_ * AD_];
__device__ float g_h   [BP_ * S_ * AD_];
__device__ float g_qkv [BP_ * S_ * 3 * AD_];
__device__ float g_attn[BP_ * S_ * AD_];
__device__ float g_up  [BP_ * S_ * 2 * FH_];
__device__ float g_gate[BP_ * S_ * FH_];
__device__ float g_xold[BP_ * L_ * M_ * AD_];
__device__ float g_xnew[BP_ * L_ * N_ * AD_];
__device__ float g_xarn[BP_ * L_ * N_ * D_];
__device__ float g_xden[BP_ * L_ * N_ * D_];
__device__ float g_y   [BP_ * L_ * N_ * AD_];
__device__ float g_y2  [BP_ * L_ * N_ * AD_];
__device__ unsigned char g_mask[BP_ * S_ * S_];
__device__ float g_invf[64];   // rotary inverse frequencies (computed once)

// ---------------- block reductions ----------------
__device__ __forceinline__ float blk_sum(float v, float* red) {
    int lane = threadIdx.x & 31, w = threadIdx.x >> 5;
#pragma unroll
    for (int o = 16; o; o >>= 1) v += __shfl_xor_sync(0xffffffffu, v, o);
    if (lane == 0) red[w] = v;
    __syncthreads();
    int nw = (blockDim.x + 31) >> 5;
    if (threadIdx.x < 32) {
        float r = (threadIdx.x < nw) ? red[threadIdx.x] : 0.f;
#pragma unroll
        for (int o = 16; o; o >>= 1) r += __shfl_xor_sync(0xffffffffu, r, o);
        if (lane == 0) red[0] = r;
    }
    __syncthreads();
    float r = red[0];
    __syncthreads();
    return r;
}

__device__ __forceinline__ float blk_max(float v, float* red) {
    int lane = threadIdx.x & 31, w = threadIdx.x >> 5;
#pragma unroll
    for (int o = 16; o; o >>= 1) v = fmaxf(v, __shfl_xor_sync(0xffffffffu, v, o));
    if (lane == 0) red[w] = v;
    __syncthreads();
    int nw = (blockDim.x + 31) >> 5;
    if (threadIdx.x < 32) {
        float r = (threadIdx.x < nw) ? red[threadIdx.x] : -INFINITY;
#pragma unroll
        for (int o = 16; o; o >>= 1) r = fmaxf(r, __shfl_xor_sync(0xffffffffu, r, o));
        if (lane == 0) red[0] = r;
    }
    __syncthreads();
    float r = red[0];
    __syncthreads();
    return r;
}

// ---------------- one-time inv_freq table (double-rounded, matches reference) ----------------
__global__ void init_invf_k() {
    int j = threadIdx.x;   // 0..63
    if (j < 64) {
        double invf_d = exp(-(double)j * (9.210340371976184 / 64.0));
        g_invf[j] = (float)invf_d;
    }
}

// ---------------- SGEMM: C[M,N] = A[M,K] @ B[N,K]^T (optionally +=) ----------------
// 128x128 tile, BK=8, 256 threads, 8x8 per thread, double-buffered smem.
template<bool ACC>
__global__ void __launch_bounds__(256) sgemm_k(const float* __restrict__ A,
                                               const float* __restrict__ B,
                                               float* __restrict__ C,
                                               int M, int N, int K) {
    __shared__ float As[2][8][136];   // 544B rows: 16B-aligned LDS.128
    __shared__ float Bs[2][8][136];
    int tid  = threadIdx.x;
    int brow = blockIdx.y * 128;
    int bcol = blockIdx.x * 128;
    int lr = tid >> 1;             // 0..127
    int lk = (tid & 1) << 2;       // 0 or 4
    int ty = tid >> 4, tx = tid & 15;

    const float* Ap = A + (size_t)(brow + lr) * K + lk;
    const float* Bp = B + (size_t)(bcol + lr) * K + lk;

    float acc[8][8];
#pragma unroll
    for (int i = 0; i < 8; i++)
#pragma unroll
        for (int j = 0; j < 8; j++) acc[i][j] = 0.f;

    // preload tile 0
    {
        float4 av = *(const float4*)Ap;
        float4 bv = *(const float4*)Bp;
        As[0][lk + 0][lr] = av.x; As[0][lk + 1][lr] = av.y;
        As[0][lk + 2][lr] = av.z; As[0][lk + 3][lr] = av.w;
        Bs[0][lk + 0][lr] = bv.x; Bs[0][lk + 1][lr] = bv.y;
        Bs[0][lk + 2][lr] = bv.z; Bs[0][lk + 3][lr] = bv.w;
    }
    __syncthreads();

    int buf = 0;
    for (int k0 = 8; k0 < K + 8; k0 += 8) {
        float4 av, bv;
        bool more = (k0 < K);
        if (more) {
            av = *(const float4*)(Ap + k0);
            bv = *(const float4*)(Bp + k0);
        }
#pragma unroll
        for (int kk = 0; kk < 8; kk++) {
            float ar[8], br[8];
            *(float4*)&ar[0] = *(const float4*)&As[buf][kk][ty * 8];
            *(float4*)&ar[4] = *(const float4*)&As[buf][kk][ty * 8 + 4];
            *(float4*)&br[0] = *(const float4*)&Bs[buf][kk][tx * 8];
            *(float4*)&br[4] = *(const float4*)&Bs[buf][kk][tx * 8 + 4];
#pragma unroll
            for (int i = 0; i < 8; i++)
#pragma unroll
                for (int j = 0; j < 8; j++) acc[i][j] += ar[i] * br[j];
        }
        if (more) {
            int nb = buf ^ 1;
            As[nb][lk + 0][lr] = av.x; As[nb][lk + 1][lr] = av.y;
            As[nb][lk + 2][lr] = av.z; As[nb][lk + 3][lr] = av.w;
            Bs[nb][lk + 0][lr] = bv.x; Bs[nb][lk + 1][lr] = bv.y;
            Bs[nb][lk + 2][lr] = bv.z; Bs[nb][lk + 3][lr] = bv.w;
        }
        __syncthreads();
        buf ^= 1;
    }

#pragma unroll
    for (int i = 0; i < 8; i++) {
        float* cp = C + (size_t)(brow + ty * 8 + i) * N + bcol + tx * 8;
        float4 c0 = make_float4(acc[i][0], acc[i][1], acc[i][2], acc[i][3]);
        float4 c1 = make_float4(acc[i][4], acc[i][5], acc[i][6], acc[i][7]);
        if (ACC) {
            float4 o0 = *(const float4*)cp;
            float4 o1 = *(const float4*)(cp + 4);
            c0.x += o0.x; c0.y += o0.y; c0.z += o0.z; c0.w += o0.w;
            c1.x += o1.x; c1.y += o1.y; c1.z += o1.z; c1.w += o1.w;
        }
        *(float4*)cp = c0;
        *(float4*)(cp + 4) = c1;
    }
}

// ---------------- rmsnorm: out[r,:] = in[map(r),:] * rsqrt(mean sq + eps) * w ----------------
__global__ void rmsnorm_k(const float* __restrict__ in, const float* __restrict__ w,
                          float* __restrict__ out, int gsize, int gstride, int goff) {
    __shared__ float red[32];
    int r = blockIdx.x;
    int inrow = (r / gsize) * gstride + goff + (r % gsize);
    const float* x = in + (size_t)inrow * 1024;
    float* o = out + (size_t)r * 1024;
    float v[4]; float ss = 0.f;
#pragma unroll
    for (int i = 0; i < 4; i++) { v[i] = x[threadIdx.x + i * 256]; ss += v[i] * v[i]; }
    ss = blk_sum(ss, red);
    float sc = rsqrtf(ss * (1.f / 1024.f) + EPS_);
#pragma unroll
    for (int i = 0; i < 4; i++) {
        int idx = threadIdx.x + i * 256;
        o[idx] = v[i] * sc * w[idx];
    }
}

// ---------------- fused shifted-y + rmsnorm (refresh path) ----------------
__global__ void yfrms_k(const float* __restrict__ y, const int* __restrict__ begin,
                        const float* __restrict__ pad_emb, const float* __restrict__ w,
                        float* __restrict__ out) {
    __shared__ float red[32];
    int r = blockIdx.x;            // 0..1023 : b*512 + t
    int b = r >> 9, t = r & 511;
    int n = t & 15, l = t >> 4;
    bool cond = (n == 0) && (begin[b * 32 + l] != 0);
    const float* x = cond ? pad_emb
                          : (y + ((size_t)b * 512 + ((t + 511) & 511)) * 1024);
    float* o = out + (size_t)r * 1024;
    float v[4]; float ss = 0.f;
#pragma unroll
    for (int i = 0; i < 4; i++) { v[i] = x[threadIdx.x + i * 256]; ss += v[i] * v[i]; }
    ss = blk_sum(ss, red);
    float sc = rsqrtf(ss * (1.f / 1024.f) + EPS_);
#pragma unroll
    for (int i = 0; i < 4; i++) {
        int idx = threadIdx.x + i * 256;
        o[idx] = v[i] * sc * w[idx];
    }
}

// ---------------- l2norm + rotary on q,k in-place in qkv ----------------
__global__ void qk_rope_k(float* __restrict__ qkv) {
    __shared__ float red[32];
    __shared__ float sh[128];
    int s = blockIdx.x, hk = blockIdx.y, b = blockIdx.z;
    int h = hk >> 1;
    int off = (hk & 1) ? 1024 : 0;
    float* p = qkv + ((size_t)(b * 2048 + s)) * 3072 + off + h * 128;
    int tid = threadIdx.x;
    float v = p[tid];
    float ss = blk_sum(v * v, red);
    float scl = 1.f / fmaxf(sqrtf(ss), EPS_);
    sh[tid] = v * scl;
    __syncthreads();
    int j = tid & 63;
    float invf = g_invf[j];
    float ang = (float)s * invf;
    float c = cosf(ang), sn = sinf(ang);
    float x1 = sh[j], x2 = sh[j + 64];
    float outv = (tid < 64) ? (x1 * c + x2 * sn) : (-x1 * sn + x2 * c);
    p[tid] = outv;
}

// ---------------- mask build ----------------
__global__ void mask_k(const int* __restrict__ doc, unsigned char* __restrict__ mask) {
    int q = blockIdx.x, b = blockIdx.y;
    int qb = q >> 6, qr = q & 63;
    bool newq = qr >= 48;
    int docq = doc[b * 32 + qb];
    int posq = qr + qb * 16;
    unsigned char* mrow = mask + ((size_t)(b * 2048 + q)) * 2048;
#pragma unroll
    for (int i = 0; i < 8; i++) {
        int k = threadIdx.x + i * 256;
        int kb = k >> 6, kr = k & 63;
        bool newk = kr >= 48;
        int dock  = doc[b * 32 + kb];
        int dockp = doc[b * 32 + (kb > 0 ? kb - 1 : 0)];
        int posk = kr + kb * 16;
        bool nn = newq && newk && (q >= k) && (posq < posk + W_) && (docq == dock);
        bool ao = ((newq && (docq == dockp)) || !newq) && !newk && (qb == kb);
        mrow[k] = (nn || ao) ? 1 : 0;
    }
}

// ---------------- sparse attention: one block per (b, h, q) ----------------
// Mask structure: old q (qr<48) attends only its block's 48 old keys.
// New q attends a subset of: new keys of blocks [qb-16, qb-1] (16 each) +
// own-block keys 0..qr. Max 16*16 + 64 = 320 candidates; g_mask gates exactly.
__global__ void __launch_bounds__(128) attn_k(const float* __restrict__ qkv,
                                              const unsigned char* __restrict__ mask,
                                              float* __restrict__ out) {
    __shared__ float qs[128];
    __shared__ float ps[320];
    __shared__ short klist[320];
    __shared__ float red[32];
    int q = blockIdx.x, h = blockIdx.y, b = blockIdx.z;
    int qb = q >> 6, qr = q & 63;
    int tid = threadIdx.x;
    int lane = tid & 31, warp = tid >> 5;

    const float* base = qkv + (size_t)b * 2048 * 3072;
    qs[tid] = base[(size_t)q * 3072 + h * 128 + tid];

    int nk, nprior = 0, npb = 0;
    if (qr < 48) {
        nk = 48;
    } else {
        npb = min(16, qb);
        nprior = npb * 16;
        nk = nprior + qr + 1;     // prior-block new keys + own block keys 0..qr
    }
    for (int i = tid; i < nk; i += 128) {
        int k;
        if (qr < 48)           k = qb * 64 + i;
        else if (i < nprior) { int kb = qb - npb + (i >> 4); k = kb * 64 + 48 + (i & 15); }
        else                   k = qb * 64 + (i - nprior);
        klist[i] = (short)k;
    }
    __syncthreads();

    float4 q4 = *(const float4*)&qs[lane * 4];
    const unsigned char* mrow = mask + ((size_t)(b * 2048 + q)) * 2048;
    const float scale = 0.088388347648318447f;  // 1/sqrt(128)

    // scores: warp-per-key
    const float* Kb = base + 1024 + h * 128 + lane * 4;
    for (int i = warp; i < nk; i += 4) {
        int k = klist[i];
        float4 kv = *(const float4*)(Kb + (size_t)k * 3072);
        float d = q4.x * kv.x + q4.y * kv.y + q4.z * kv.z + q4.w * kv.w;
#pragma unroll
        for (int o = 16; o; o >>= 1) d += __shfl_xor_sync(0xffffffffu, d, o);
        if (lane == 0) ps[i] = mrow[k] ? d * scale : -INFINITY;
    }
    __syncthreads();

    // softmax over ps[0..nk)
    float vloc[3];
    float mx = -INFINITY;
#pragma unroll
    for (int jj = 0; jj < 3; jj++) {
        int i = tid + jj * 128;
        vloc[jj] = (i < nk) ? ps[i] : -INFINITY;
        mx = fmaxf(mx, vloc[jj]);
    }
    mx = blk_max(mx, red);
    float sum = 0.f;
#pragma unroll
    for (int jj = 0; jj < 3; jj++) {
        int i = tid + jj * 128;
        if (i < nk) {
            float p = (vloc[jj] > -INFINITY) ? expf(vloc[jj] - mx) : 0.f;
            ps[i] = p;
            sum += p;
        }
    }
    sum = blk_sum(sum, red);   // its barriers also publish ps[]
    float inv = 1.f / sum;

    // probs @ V : thread = output dim
    const float* Vb = base + 2048 + h * 128 + tid;
    float a0 = 0.f, a1 = 0.f, a2 = 0.f, a3 = 0.f;
    int i = 0;
    for (; i + 4 <= nk; i += 4) {
        a0 += ps[i    ] * Vb[(size_t)klist[i    ] * 3072];
        a1 += ps[i + 1] * Vb[(size_t)klist[i + 1] * 3072];
        a2 += ps[i + 2] * Vb[(size_t)klist[i + 2] * 3072];
        a3 += ps[i + 3] * Vb[(size_t)klist[i + 3] * 3072];
    }
    for (; i < nk; i++) a0 += ps[i] * Vb[(size_t)klist[i] * 3072];
    out[((size_t)(b * 2048 + q)) * 1024 + h * 128 + tid] = (a0 + a1 + a2 + a3) * inv;
}

// ---------------- silu-gate ----------------
__global__ void silu_gate_k(const float* __restrict__ up, float* __restrict__ gate) {
    int idx = blockIdx.x * blockDim.x + threadIdx.x;
    if (idx >= BP_ * S_ * FH_) return;
    int r = idx >> 11, c = idx & 2047;
    float a = up[(size_t)r * 4096 + c];
    float bb = up[(size_t)r * 4096 + 2048 + c];
    gate[idx] = (a / (1.f + expf(-a))) * bb;
}

// ---------------- assemble x from x_old / x_new ----------------
__global__ void assemble_k(float* __restrict__ x, const float* __restrict__ xold,
                           const float* __restrict__ xnew) {
    int idx = blockIdx.x * blockDim.x + threadIdx.x;
    if (idx >= BP_ * S_ * 256) return;
    int d4 = idx & 255;
    int gr = idx >> 8;
    int b = gr >> 11, s = gr & 2047;
    int l = s >> 6, rr = s & 63;
    float4 v;
    if (rr < 48)
        v = ((const float4*)xold)[((size_t)((b * 32 + l) * 48 + rr)) * 256 + d4];
    else
        v = ((const float4*)xnew)[((size_t)((b * 32 + l) * 16 + (rr - 48))) * 256 + d4];
    ((float4*)x)[idx] = v;
}

// ---------------- extract y = x[:, :, M:, :] ----------------
__global__ void extract_y_k(const float* __restrict__ x, float* __restrict__ y) {
    int idx = blockIdx.x * blockDim.x + threadIdx.x;
    if (idx >= BP_ * 512 * 256) return;
    int d4 = idx & 255;
    int r = idx >> 8;
    int b = r >> 9, t = r & 511;
    int l = t >> 4, n = t & 15;
    int xr = b * 2048 + l * 64 + 48 + n;
    ((float4*)y)[idx] = ((const float4*)x)[(size_t)xr * 256 + d4];
}

// ---------------- host-side launch ----------------
static void gemm(const float* A, const float* B, float* C, int M, int N, int K, bool acc) {
    dim3 grid(N / 128, M / 128);
    if (acc) sgemm_k<true><<<grid, 256>>>(A, B, C, M, N, K);
    else     sgemm_k<false><<<grid, 256>>>(A, B, C, M, N, K);
}

extern "C" void kernel_launch(void* const* d_in, const int* in_sizes, int n_in,
                              void* d_out, int out_size) {
    (void)in_sizes; (void)n_in; (void)out_size;
    const float* x_input     = (const float*)d_in[0];
    const float* x_ar        = (const float*)d_in[1];
    const int*   doc         = (const int*)d_in[2];
    const int*   begin       = (const int*)d_in[3];   // bool coerced to 4-byte elems
    const float* old_norm_w  = (const float*)d_in[4];
    const float* new_norm_w  = (const float*)d_in[5];
    const float* w_old       = (const float*)d_in[6];
    const float* w_ar        = (const float*)d_in[7];
    const float* w_de        = (const float*)d_in[8];
    const float* w_ar1       = (const float*)d_in[9];
    const float* w_de1       = (const float*)d_in[10];
    const float* w_y1        = (const float*)d_in[11];
    const float* pad_emb     = (const float*)d_in[12];
    const float* w_agg       = (const float*)d_in[13];
    const float* attn_norm_w = (const float*)d_in[14];
    const float* ffn_norm_w  = (const float*)d_in[15];
    const float* w_qkv       = (const float*)d_in[16];
    const float* w_o         = (const float*)d_in[17];
    const float* w_up        = (const float*)d_in[18];
    const float* w_down      = (const float*)d_in[19];
    float* out = (float*)d_out;

    float *x, *h, *qkv, *attn, *up, *gate, *xold, *xnew, *xarn, *xden, *y, *y2;
    unsigned char* mask;
    cudaGetSymbolAddress((void**)&x,    g_x);
    cudaGetSymbolAddress((void**)&h,    g_h);
    cudaGetSymbolAddress((void**)&qkv,  g_qkv);
    cudaGetSymbolAddress((void**)&attn, g_attn);
    cudaGetSymbolAddress((void**)&up,   g_up);
    cudaGetSymbolAddress((void**)&gate, g_gate);
    cudaGetSymbolAddress((void**)&xold, g_xold);
    cudaGetSymbolAddress((void**)&xnew, g_xnew);
    cudaGetSymbolAddress((void**)&xarn, g_xarn);
    cudaGetSymbolAddress((void**)&xden, g_xden);
    cudaGetSymbolAddress((void**)&y,    g_y);
    cudaGetSymbolAddress((void**)&y2,   g_y2);
    cudaGetSymbolAddress((void**)&mask, g_mask);

    // one-time tables + mask (cheap; recomputed every call for determinism)
    init_invf_k<<<1, 64>>>();
    mask_k<<<dim3(2048, 2), 256>>>(doc, mask);

    // input projections
    rmsnorm_k<<<3072, 256>>>(x_input, old_norm_w, h, 48, 64, 0);     // x_old_n
    gemm(h, w_old, xold, 3072, 1024, 1024, false);
    rmsnorm_k<<<1024, 256>>>(x_ar, new_norm_w, xarn, 16, 16, 0);     // x_ar_n
    rmsnorm_k<<<1024, 256>>>(x_input, new_norm_w, xden, 16, 64, 48); // x_de_n
    gemm(xarn, w_ar, xnew, 1024, 1024, 1024, false);
    gemm(xden, w_de, xnew, 1024, 1024, 1024, true);
    assemble_k<<<(BP_ * S_ * 256 + 255) / 256, 256>>>(x, xold, xnew);

    for (int it = 0; it < 2; it++) {
        for (int li = 0; li < 2; li++) {
            rmsnorm_k<<<4096, 256>>>(x, attn_norm_w + li * 1024, h, 1, 1, 0);
            gemm(h, w_qkv + (size_t)li * 3072 * 1024, qkv, 4096, 3072, 1024, false);
            qk_rope_k<<<dim3(2048, 16, 2), 128>>>(qkv);
            attn_k<<<dim3(2048, 8, 2), 128>>>(qkv, mask, attn);
            gemm(attn, w_o + (size_t)li * 1024 * 1024, x, 4096, 1024, 1024, true);
            rmsnorm_k<<<4096, 256>>>(x, ffn_norm_w + li * 1024, h, 1, 1, 0);
            gemm(h, w_up + (size_t)li * 4096 * 1024, up, 4096, 4096, 1024, false);
            silu_gate_k<<<(BP_ * S_ * FH_ + 255) / 256, 256>>>(up, gate);
            gemm(gate, w_down + (size_t)li * 1024 * 2048, x, 4096, 1024, 2048, true);
        }
        extract_y_k<<<(BP_ * 512 * 256 + 255) / 256, 256>>>(x, y);
        if (it == 0) {
            yfrms_k<<<1024, 256>>>(y, begin, pad_emb, new_norm_w, y2);
            gemm(xarn, w_ar1, xnew, 1024, 1024, 1024, false);
            gemm(y2,   w_y1,  xnew, 1024, 1024, 1024, true);
            gemm(xden, w_de1, xnew, 1024, 1024, 1024, true);
            assemble_k<<<(BP_ * S_ * 256 + 255) / 256, 256>>>(x, xold, xnew);
        }
    }

    gemm(y, w_agg, out, 1024, 1024, 1024, false);
}

// round 6
// speedup vs baseline: 5.4414x; 2.1718x over previous
#include <cuda_runtime.h>
#include <cuda_bf16.h>
#include <math.h>
#include <stdint.h>

// ---------------- problem constants ----------------
#define BP_  2
#define L_   32
#define N_   16
#define O_   64
#define D_   1024
#define AD_  1024
#define HEAD_ 128
#define W_   256
#define FH_  2048
#define M_   48
#define E_   64
#define S_   2048
#define EPS_ 1e-5f
#define MB1 (1u<<20)

// ---------------- device scratch (allocation-free) ----------------
__device__ float g_x   [BP_ * S_ * AD_];
__device__ float g_qkv [BP_ * S_ * 3 * AD_];
__device__ float g_up  [BP_ * S_ * 2 * FH_];
__device__ float g_xold[BP_ * L_ * M_ * AD_];
__device__ float g_xnew[BP_ * L_ * N_ * AD_];
__device__ float g_y   [BP_ * L_ * N_ * AD_];
__device__ unsigned char g_mask[BP_ * S_ * S_];
__device__ float g_invf[64];

// bf16 split activation buffers
__device__ __nv_bfloat16 g_hh[BP_ * S_ * AD_],  g_hl[BP_ * S_ * AD_];
__device__ __nv_bfloat16 g_ah[BP_ * S_ * AD_],  g_al[BP_ * S_ * AD_];
__device__ __nv_bfloat16 g_gh[BP_ * S_ * FH_],  g_gl[BP_ * S_ * FH_];
__device__ __nv_bfloat16 g_xarnh[MB1], g_xarnl[MB1];
__device__ __nv_bfloat16 g_xdenh[MB1], g_xdenl[MB1];
__device__ __nv_bfloat16 g_y2h[MB1],   g_y2l[MB1];
__device__ __nv_bfloat16 g_yh[MB1],    g_yl[MB1];
// bf16 split weights: 27M elems (offsets in MB1 units)
__device__ __nv_bfloat16 g_whi[27u * MB1], g_wlo[27u * MB1];

#define OFF_WOLD  0
#define OFF_WAR   1
#define OFF_WDE   2
#define OFF_WAR1  3
#define OFF_WDE1  4
#define OFF_WY1   5
#define OFF_WAGG  6
#define OFF_WQKV  7
#define OFF_WO    13
#define OFF_WUP   15
#define OFF_WDOWN 23

// ---------------- small helpers ----------------
__device__ __forceinline__ void bsplit(float f, __nv_bfloat16& h, __nv_bfloat16& l) {
    h = __float2bfloat16(f);
    l = __float2bfloat16(f - __bfloat162float(h));
}

__device__ __forceinline__ float blk_sum(float v, float* red) {
    int lane = threadIdx.x & 31, w = threadIdx.x >> 5;
#pragma unroll
    for (int o = 16; o; o >>= 1) v += __shfl_xor_sync(0xffffffffu, v, o);
    if (lane == 0) red[w] = v;
    __syncthreads();
    int nw = (blockDim.x + 31) >> 5;
    if (threadIdx.x < 32) {
        float r = (threadIdx.x < nw) ? red[threadIdx.x] : 0.f;
#pragma unroll
        for (int o = 16; o; o >>= 1) r += __shfl_xor_sync(0xffffffffu, r, o);
        if (lane == 0) red[0] = r;
    }
    __syncthreads();
    float r = red[0];
    __syncthreads();
    return r;
}

__device__ __forceinline__ float blk_max(float v, float* red) {
    int lane = threadIdx.x & 31, w = threadIdx.x >> 5;
#pragma unroll
    for (int o = 16; o; o >>= 1) v = fmaxf(v, __shfl_xor_sync(0xffffffffu, v, o));
    if (lane == 0) red[w] = v;
    __syncthreads();
    int nw = (blockDim.x + 31) >> 5;
    if (threadIdx.x < 32) {
        float r = (threadIdx.x < nw) ? red[threadIdx.x] : -INFINITY;
#pragma unroll
        for (int o = 16; o; o >>= 1) r = fmaxf(r, __shfl_xor_sync(0xffffffffu, r, o));
        if (lane == 0) red[0] = r;
    }
    __syncthreads();
    float r = red[0];
    __syncthreads();
    return r;
}

// ---------------- PTX helpers (all compute_103-legal: sm_80+ features) ----------------
#define SWZ64(o) ((o) ^ (((o) >> 3) & 0x30))

static __device__ __forceinline__ uint32_t smem_u32(const void* p) {
    uint32_t a;
    asm("{ .reg .u64 t; cvta.to.shared.u64 t, %1; cvt.u32.u64 %0, t; }" : "=r"(a) : "l"(p));
    return a;
}
static __device__ __forceinline__ void cpa16(uint32_t dst, const void* src) {
    asm volatile("cp.async.cg.shared.global [%0], [%1], 16;" :: "r"(dst), "l"(src) : "memory");
}
static __device__ __forceinline__ void ldm4(uint32_t& r0, uint32_t& r1, uint32_t& r2,
                                            uint32_t& r3, uint32_t addr) {
    asm volatile("ldmatrix.sync.aligned.m8n8.x4.shared.b16 {%0,%1,%2,%3}, [%4];"
                 : "=r"(r0), "=r"(r1), "=r"(r2), "=r"(r3) : "r"(addr));
}
#define MMA16816(d, a, b) \
    asm volatile("mma.sync.aligned.m16n8k16.row.col.f32.bf16.bf16.f32 " \
        "{%0,%1,%2,%3}, {%4,%5,%6,%7}, {%8,%9}, {%0,%1,%2,%3};" \
        : "+f"((d)[0]), "+f"((d)[1]), "+f"((d)[2]), "+f"((d)[3]) \
        : "r"((a)[0]), "r"((a)[1]), "r"((a)[2]), "r"((a)[3]), "r"((b)[0]), "r"((b)[1]))

// ---------------- tensor-core split-bf16 GEMM ----------------
// C[M,N] (+)= Ah@Bh^T + Ah@Bl^T + Al@Bh^T  (fp32 mma accum; ll term dropped, <=2^-18)
// M,N multiples of 128; K multiple of 32. 256 threads, warp grid 2(m) x 4(n).
// Stage: Ah|Al|Bh|Bl tiles, each 128 rows x 32 bf16 (64B rows, SW64 swizzle), 8KB each.
template<bool ACC>
__global__ void __launch_bounds__(256) tgemm_k(
    const __nv_bfloat16* __restrict__ Ah, const __nv_bfloat16* __restrict__ Al,
    const __nv_bfloat16* __restrict__ Bh, const __nv_bfloat16* __restrict__ Bl,
    float* __restrict__ C, int M, int N, int K)
{
    extern __shared__ char smem[];
    uint32_t sb = smem_u32(smem);
    int tid = threadIdx.x, lane = tid & 31, wid = tid >> 5;
    int wm = wid & 1, wn = wid >> 1;
    int brow = blockIdx.y << 7, bcol = blockIdx.x << 7;

    const __nv_bfloat16* src0 = Ah + (size_t)brow * K;
    const __nv_bfloat16* src1 = Al + (size_t)brow * K;
    const __nv_bfloat16* src2 = Bh + (size_t)bcol * K;
    const __nv_bfloat16* src3 = Bl + (size_t)bcol * K;

    float d[4][4][4];
#pragma unroll
    for (int mi = 0; mi < 4; mi++)
#pragma unroll
        for (int ni = 0; ni < 4; ni++)
#pragma unroll
            for (int q = 0; q < 4; q++) d[mi][ni][q] = 0.f;

    const int nch = K >> 5;

    auto load_stage = [&](uint32_t stb, int k0) {
#pragma unroll
        for (int j = 0; j < 2; j++) {
            int u = tid + (j << 8);
            int row = u >> 2, un = u & 3;
            uint32_t doff = SWZ64((uint32_t)(row * 64 + un * 16));
            size_t goff = (size_t)row * K + k0 + un * 8;
            cpa16(stb +     0 + doff, src0 + goff);
            cpa16(stb +  8192 + doff, src1 + goff);
            cpa16(stb + 16384 + doff, src2 + goff);
            cpa16(stb + 24576 + doff, src3 + goff);
        }
        asm volatile("cp.async.commit_group;" ::: "memory");
    };

    load_stage(sb, 0);

    int g = lane >> 3, r = lane & 7;
    for (int i = 0; i < nch; i++) {
        uint32_t stb = sb + (uint32_t)((i & 1) << 15);
        if (i + 1 < nch) {
            load_stage(sb + (uint32_t)(((i + 1) & 1) << 15), (i + 1) << 5);
            asm volatile("cp.async.wait_group 1;" ::: "memory");
        } else {
            asm volatile("cp.async.wait_group 0;" ::: "memory");
        }
        __syncthreads();

#pragma unroll
        for (int ks = 0; ks < 2; ks++) {
            uint32_t ah[4][4], al[4][4], bh[4][2], bl[4][2];
            // A fragments: 4 m-tiles of 16 rows
#pragma unroll
            for (int mi = 0; mi < 4; mi++) {
                int row = wm * 64 + mi * 16 + (g & 1) * 8 + r;
                int colb = ks * 32 + (g >> 1) * 16;
                uint32_t off = SWZ64((uint32_t)(row * 64 + colb));
                ldm4(ah[mi][0], ah[mi][1], ah[mi][2], ah[mi][3], stb + off);
                ldm4(al[mi][0], al[mi][1], al[mi][2], al[mi][3], stb + 8192 + off);
            }
            // B fragments: 4 n-tiles of 8 (two x4 loads cover 2 n-tiles each)
#pragma unroll
            for (int n2 = 0; n2 < 2; n2++) {
                int rown = wn * 32 + n2 * 16 + (g >> 1) * 8 + r;
                int colb = ks * 32 + (g & 1) * 16;
                uint32_t off = SWZ64((uint32_t)(rown * 64 + colb));
                ldm4(bh[2*n2][0], bh[2*n2][1], bh[2*n2+1][0], bh[2*n2+1][1], stb + 16384 + off);
                ldm4(bl[2*n2][0], bl[2*n2][1], bl[2*n2+1][0], bl[2*n2+1][1], stb + 24576 + off);
            }
            // hh then hl then lh (16 independent accumulators inside each pass)
#pragma unroll
            for (int mi = 0; mi < 4; mi++)
#pragma unroll
                for (int ni = 0; ni < 4; ni++) MMA16816(d[mi][ni], ah[mi], bh[ni]);
#pragma unroll
            for (int mi = 0; mi < 4; mi++)
#pragma unroll
                for (int ni = 0; ni < 4; ni++) MMA16816(d[mi][ni], ah[mi], bl[ni]);
#pragma unroll
            for (int mi = 0; mi < 4; mi++)
#pragma unroll
                for (int ni = 0; ni < 4; ni++) MMA16816(d[mi][ni], al[mi], bh[ni]);
        }
        __syncthreads();
    }

    // epilogue: registers -> global (float2 per fragment half)
#pragma unroll
    for (int mi = 0; mi < 4; mi++)
#pragma unroll
        for (int ni = 0; ni < 4; ni++) {
            int row = brow + wm * 64 + mi * 16 + (lane >> 2);
            int col = bcol + wn * 32 + ni * 8 + 2 * (lane & 3);
            float* p0 = C + (size_t)row * N + col;
            float* p1 = C + (size_t)(row + 8) * N + col;
            float2 v0 = make_float2(d[mi][ni][0], d[mi][ni][1]);
            float2 v1 = make_float2(d[mi][ni][2], d[mi][ni][3]);
            if (ACC) {
                float2 o0 = *(const float2*)p0, o1 = *(const float2*)p1;
                v0.x += o0.x; v0.y += o0.y; v1.x += o1.x; v1.y += o1.y;
            }
            *(float2*)p0 = v0;
            *(float2*)p1 = v1;
        }
}

// ---------------- fp32 -> (hi, lo) bf16 split ----------------
__global__ void split_k(const float* __restrict__ in, __nv_bfloat16* __restrict__ hi,
                        __nv_bfloat16* __restrict__ lo, int n4) {
    int i = blockIdx.x * 256 + threadIdx.x;
    if (i >= n4) return;
    float4 v = ((const float4*)in)[i];
    __nv_bfloat16 h0, h1, h2, h3, l0, l1, l2, l3;
    bsplit(v.x, h0, l0); bsplit(v.y, h1, l1); bsplit(v.z, h2, l2); bsplit(v.w, h3, l3);
    __nv_bfloat162* H = (__nv_bfloat162*)hi;
    __nv_bfloat162* Lo = (__nv_bfloat162*)lo;
    H[2 * i]      = __nv_bfloat162(h0, h1);
    H[2 * i + 1]  = __nv_bfloat162(h2, h3);
    Lo[2 * i]     = __nv_bfloat162(l0, l1);
    Lo[2 * i + 1] = __nv_bfloat162(l2, l3);
}

// ---------------- one-time inv_freq table ----------------
__global__ void init_invf_k() {
    int j = threadIdx.x;
    if (j < 64) {
        double invf_d = exp(-(double)j * (9.210340371976184 / 64.0));
        g_invf[j] = (float)invf_d;
    }
}

// ---------------- rmsnorm -> split bf16 ----------------
__global__ void rmsnorm_k(const float* __restrict__ in, const float* __restrict__ w,
                          __nv_bfloat16* __restrict__ oh, __nv_bfloat16* __restrict__ ol,
                          int gsize, int gstride, int goff) {
    __shared__ float red[32];
    int r = blockIdx.x;
    int inrow = (r / gsize) * gstride + goff + (r % gsize);
    const float* x = in + (size_t)inrow * 1024;
    float v[4]; float ss = 0.f;
#pragma unroll
    for (int i = 0; i < 4; i++) { v[i] = x[threadIdx.x + i * 256]; ss += v[i] * v[i]; }
    ss = blk_sum(ss, red);
    float sc = rsqrtf(ss * (1.f / 1024.f) + EPS_);
#pragma unroll
    for (int i = 0; i < 4; i++) {
        int idx = threadIdx.x + i * 256;
        float f = v[i] * sc * w[idx];
        __nv_bfloat16 h, l; bsplit(f, h, l);
        size_t o = (size_t)r * 1024 + idx;
        oh[o] = h; ol[o] = l;
    }
}

// ---------------- fused shifted-y + rmsnorm (refresh) -> split ----------------
__global__ void yfrms_k(const float* __restrict__ y, const int* __restrict__ begin,
                        const float* __restrict__ pad_emb, const float* __restrict__ w,
                        __nv_bfloat16* __restrict__ oh, __nv_bfloat16* __restrict__ ol) {
    __shared__ float red[32];
    int r = blockIdx.x;
    int b = r >> 9, t = r & 511;
    int n = t & 15, l = t >> 4;
    bool cond = (n == 0) && (begin[b * 32 + l] != 0);
    const float* x = cond ? pad_emb : (y + ((size_t)b * 512 + ((t + 511) & 511)) * 1024);
    float v[4]; float ss = 0.f;
#pragma unroll
    for (int i = 0; i < 4; i++) { v[i] = x[threadIdx.x + i * 256]; ss += v[i] * v[i]; }
    ss = blk_sum(ss, red);
    float sc = rsqrtf(ss * (1.f / 1024.f) + EPS_);
#pragma unroll
    for (int i = 0; i < 4; i++) {
        int idx = threadIdx.x + i * 256;
        float f = v[i] * sc * w[idx];
        __nv_bfloat16 h, lo; bsplit(f, h, lo);
        size_t o = (size_t)r * 1024 + idx;
        oh[o] = h; ol[o] = lo;
    }
}

// ---------------- l2norm + rotary on q,k in-place ----------------
__global__ void qk_rope_k(float* __restrict__ qkv) {
    __shared__ float red[32];
    __shared__ float sh[128];
    int s = blockIdx.x, hk = blockIdx.y, b = blockIdx.z;
    int h = hk >> 1;
    int off = (hk & 1) ? 1024 : 0;
    float* p = qkv + ((size_t)(b * 2048 + s)) * 3072 + off + h * 128;
    int tid = threadIdx.x;
    float v = p[tid];
    float ss = blk_sum(v * v, red);
    float scl = 1.f / fmaxf(sqrtf(ss), EPS_);
    sh[tid] = v * scl;
    __syncthreads();
    int j = tid & 63;
    float ang = (float)s * g_invf[j];
    float c = cosf(ang), sn = sinf(ang);
    float x1 = sh[j], x2 = sh[j + 64];
    p[tid] = (tid < 64) ? (x1 * c + x2 * sn) : (-x1 * sn + x2 * c);
}

// ---------------- mask build ----------------
__global__ void mask_k(const int* __restrict__ doc, unsigned char* __restrict__ mask) {
    int q = blockIdx.x, b = blockIdx.y;
    int qb = q >> 6, qr = q & 63;
    bool newq = qr >= 48;
    int docq = doc[b * 32 + qb];
    int posq = qr + qb * 16;
    unsigned char* mrow = mask + ((size_t)(b * 2048 + q)) * 2048;
#pragma unroll
    for (int i = 0; i < 8; i++) {
        int k = threadIdx.x + i * 256;
        int kb = k >> 6, kr = k & 63;
        bool newk = kr >= 48;
        int dock  = doc[b * 32 + kb];
        int dockp = doc[b * 32 + (kb > 0 ? kb - 1 : 0)];
        int posk = kr + kb * 16;
        bool nn = newq && newk && (q >= k) && (posq < posk + W_) && (docq == dock);
        bool ao = ((newq && (docq == dockp)) || !newq) && !newk && (qb == kb);
        mrow[k] = (nn || ao) ? 1 : 0;
    }
}

// ---------------- sparse attention (output split bf16) ----------------
__global__ void __launch_bounds__(128) attn_k(const float* __restrict__ qkv,
                                              const unsigned char* __restrict__ mask,
                                              __nv_bfloat16* __restrict__ oh,
                                              __nv_bfloat16* __restrict__ ol) {
    __shared__ float qs[128];
    __shared__ float ps[320];
    __shared__ short klist[320];
    __shared__ float red[32];
    int q = blockIdx.x, h = blockIdx.y, b = blockIdx.z;
    int qb = q >> 6, qr = q & 63;
    int tid = threadIdx.x;
    int lane = tid & 31, warp = tid >> 5;

    const float* base = qkv + (size_t)b * 2048 * 3072;
    qs[tid] = base[(size_t)q * 3072 + h * 128 + tid];

    int nk, nprior = 0, npb = 0;
    if (qr < 48) {
        nk = 48;
    } else {
        npb = min(16, qb);
        nprior = npb * 16;
        nk = nprior + qr + 1;
    }
    for (int i = tid; i < nk; i += 128) {
        int k;
        if (qr < 48)           k = qb * 64 + i;
        else if (i < nprior) { int kb = qb - npb + (i >> 4); k = kb * 64 + 48 + (i & 15); }
        else                   k = qb * 64 + (i - nprior);
        klist[i] = (short)k;
    }
    __syncthreads();

    float4 q4 = *(const float4*)&qs[lane * 4];
    const unsigned char* mrow = mask + ((size_t)(b * 2048 + q)) * 2048;
    const float scale = 0.088388347648318447f;

    const float* Kb = base + 1024 + h * 128 + lane * 4;
    for (int i = warp; i < nk; i += 4) {
        int k = klist[i];
        float4 kv = *(const float4*)(Kb + (size_t)k * 3072);
        float d = q4.x * kv.x + q4.y * kv.y + q4.z * kv.z + q4.w * kv.w;
#pragma unroll
        for (int o = 16; o; o >>= 1) d += __shfl_xor_sync(0xffffffffu, d, o);
        if (lane == 0) ps[i] = mrow[k] ? d * scale : -INFINITY;
    }
    __syncthreads();

    float vloc[3];
    float mx = -INFINITY;
#pragma unroll
    for (int jj = 0; jj < 3; jj++) {
        int i = tid + jj * 128;
        vloc[jj] = (i < nk) ? ps[i] : -INFINITY;
        mx = fmaxf(mx, vloc[jj]);
    }
    mx = blk_max(mx, red);
    float sum = 0.f;
#pragma unroll
    for (int jj = 0; jj < 3; jj++) {
        int i = tid + jj * 128;
        if (i < nk) {
            float p = (vloc[jj] > -INFINITY) ? expf(vloc[jj] - mx) : 0.f;
            ps[i] = p;
            sum += p;
        }
    }
    sum = blk_sum(sum, red);
    float inv = 1.f / sum;

    const float* Vb = base + 2048 + h * 128 + tid;
    float a0 = 0.f, a1 = 0.f, a2 = 0.f, a3 = 0.f;
    int i = 0;
    for (; i + 4 <= nk; i += 4) {
        a0 += ps[i    ] * Vb[(size_t)klist[i    ] * 3072];
        a1 += ps[i + 1] * Vb[(size_t)klist[i + 1] * 3072];
        a2 += ps[i + 2] * Vb[(size_t)klist[i + 2] * 3072];
        a3 += ps[i + 3] * Vb[(size_t)klist[i + 3] * 3072];
    }
    for (; i < nk; i++) a0 += ps[i] * Vb[(size_t)klist[i] * 3072];
    float f = (a0 + a1 + a2 + a3) * inv;
    __nv_bfloat16 hh, ll; bsplit(f, hh, ll);
    size_t o = ((size_t)(b * 2048 + q)) * 1024 + h * 128 + tid;
    oh[o] = hh; ol[o] = ll;
}

// ---------------- silu-gate -> split bf16 ----------------
__global__ void silu_gate_k(const float* __restrict__ up,
                            __nv_bfloat16* __restrict__ gh, __nv_bfloat16* __restrict__ gl) {
    int idx = blockIdx.x * blockDim.x + threadIdx.x;
    if (idx >= BP_ * S_ * FH_) return;
    int r = idx >> 11, c = idx & 2047;
    float a  = up[(size_t)r * 4096 + c];
    float bb = up[(size_t)r * 4096 + 2048 + c];
    float f = (a / (1.f + expf(-a))) * bb;
    __nv_bfloat16 h, l; bsplit(f, h, l);
    gh[idx] = h; gl[idx] = l;
}

// ---------------- assemble x from x_old / x_new ----------------
__global__ void assemble_k(float* __restrict__ x, const float* __restrict__ xold,
                           const float* __restrict__ xnew) {
    int idx = blockIdx.x * blockDim.x + threadIdx.x;
    if (idx >= BP_ * S_ * 256) return;
    int d4 = idx & 255;
    int gr = idx >> 8;
    int b = gr >> 11, s = gr & 2047;
    int l = s >> 6, rr = s & 63;
    float4 v;
    if (rr < 48)
        v = ((const float4*)xold)[((size_t)((b * 32 + l) * 48 + rr)) * 256 + d4];
    else
        v = ((const float4*)xnew)[((size_t)((b * 32 + l) * 16 + (rr - 48))) * 256 + d4];
    ((float4*)x)[idx] = v;
}

// ---------------- extract y = x[:,:,M:,:] (fp32 + split) ----------------
__global__ void extract_y_k(const float* __restrict__ x, float* __restrict__ y,
                            __nv_bfloat16* __restrict__ yh, __nv_bfloat16* __restrict__ yl) {
    int idx = blockIdx.x * blockDim.x + threadIdx.x;
    if (idx >= BP_ * 512 * 256) return;
    int d4 = idx & 255;
    int r = idx >> 8;
    int b = r >> 9, t = r & 511;
    int l = t >> 4, n = t & 15;
    int xr = b * 2048 + l * 64 + 48 + n;
    float4 v = ((const float4*)x)[(size_t)xr * 256 + d4];
    ((float4*)y)[idx] = v;
    __nv_bfloat16 h0, h1, h2, h3, l0, l1, l2, l3;
    bsplit(v.x, h0, l0); bsplit(v.y, h1, l1); bsplit(v.z, h2, l2); bsplit(v.w, h3, l3);
    ((__nv_bfloat162*)yh)[2 * idx]     = __nv_bfloat162(h0, h1);
    ((__nv_bfloat162*)yh)[2 * idx + 1] = __nv_bfloat162(h2, h3);
    ((__nv_bfloat162*)yl)[2 * idx]     = __nv_bfloat162(l0, l1);
    ((__nv_bfloat162*)yl)[2 * idx + 1] = __nv_bfloat162(l2, l3);
}

// ---------------- host helpers ----------------
#define TG_SMEM 65536

static void tgemm(const __nv_bfloat16* Ah, const __nv_bfloat16* Al,
                  const __nv_bfloat16* Bh, const __nv_bfloat16* Bl,
                  float* C, int M, int N, int K, bool acc) {
    dim3 grid(N >> 7, M >> 7);
    if (acc) {
        cudaFuncSetAttribute(tgemm_k<true>, cudaFuncAttributeMaxDynamicSharedMemorySize, TG_SMEM);
        tgemm_k<true><<<grid, 256, TG_SMEM>>>(Ah, Al, Bh, Bl, C, M, N, K);
    } else {
        cudaFuncSetAttribute(tgemm_k<false>, cudaFuncAttributeMaxDynamicSharedMemorySize, TG_SMEM);
        tgemm_k<false><<<grid, 256, TG_SMEM>>>(Ah, Al, Bh, Bl, C, M, N, K);
    }
}

static void wsplit(const float* in, __nv_bfloat16* hi, __nv_bfloat16* lo, size_t n) {
    int n4 = (int)(n >> 2);
    split_k<<<(n4 + 255) / 256, 256>>>(in, hi, lo, n4);
}

extern "C" void kernel_launch(void* const* d_in, const int* in_sizes, int n_in,
                              void* d_out, int out_size) {
    (void)in_sizes; (void)n_in; (void)out_size;
    const float* x_input     = (const float*)d_in[0];
    const float* x_ar        = (const float*)d_in[1];
    const int*   doc         = (const int*)d_in[2];
    const int*   begin       = (const int*)d_in[3];
    const float* old_norm_w  = (const float*)d_in[4];
    const float* new_norm_w  = (const float*)d_in[5];
    const float* w_old       = (const float*)d_in[6];
    const float* w_ar        = (const float*)d_in[7];
    const float* w_de        = (const float*)d_in[8];
    const float* w_ar1       = (const float*)d_in[9];
    const float* w_de1       = (const float*)d_in[10];
    const float* w_y1        = (const float*)d_in[11];
    const float* pad_emb     = (const float*)d_in[12];
    const float* w_agg       = (const float*)d_in[13];
    const float* attn_norm_w = (const float*)d_in[14];
    const float* ffn_norm_w  = (const float*)d_in[15];
    const float* w_qkv       = (const float*)d_in[16];
    const float* w_o         = (const float*)d_in[17];
    const float* w_up        = (const float*)d_in[18];
    const float* w_down      = (const float*)d_in[19];
    float* out = (float*)d_out;

    float *x, *qkv, *up, *xold, *xnew, *y;
    unsigned char* mask;
    __nv_bfloat16 *hh, *hl, *ah, *al, *gh, *gl;
    __nv_bfloat16 *xarnh, *xarnl, *xdenh, *xdenl, *y2h, *y2l, *yh, *yl, *whi, *wlo;
    cudaGetSymbolAddress((void**)&x,    g_x);
    cudaGetSymbolAddress((void**)&qkv,  g_qkv);
    cudaGetSymbolAddress((void**)&up,   g_up);
    cudaGetSymbolAddress((void**)&xold, g_xold);
    cudaGetSymbolAddress((void**)&xnew, g_xnew);
    cudaGetSymbolAddress((void**)&y,    g_y);
    cudaGetSymbolAddress((void**)&mask, g_mask);
    cudaGetSymbolAddress((void**)&hh,   g_hh);
    cudaGetSymbolAddress((void**)&hl,   g_hl);
    cudaGetSymbolAddress((void**)&ah,   g_ah);
    cudaGetSymbolAddress((void**)&al,   g_al);
    cudaGetSymbolAddress((void**)&gh,   g_gh);
    cudaGetSymbolAddress((void**)&gl,   g_gl);
    cudaGetSymbolAddress((void**)&xarnh, g_xarnh);
    cudaGetSymbolAddress((void**)&xarnl, g_xarnl);
    cudaGetSymbolAddress((void**)&xdenh, g_xdenh);
    cudaGetSymbolAddress((void**)&xdenl, g_xdenl);
    cudaGetSymbolAddress((void**)&y2h,  g_y2h);
    cudaGetSymbolAddress((void**)&y2l,  g_y2l);
    cudaGetSymbolAddress((void**)&yh,   g_yh);
    cudaGetSymbolAddress((void**)&yl,   g_yl);
    cudaGetSymbolAddress((void**)&whi,  g_whi);
    cudaGetSymbolAddress((void**)&wlo,  g_wlo);

    init_invf_k<<<1, 64>>>();
    mask_k<<<dim3(2048, 2), 256>>>(doc, mask);

    // weight splits (every call; deterministic)
    wsplit(w_old, whi + (size_t)OFF_WOLD * MB1, wlo + (size_t)OFF_WOLD * MB1, 1u * MB1);
    wsplit(w_ar,  whi + (size_t)OFF_WAR  * MB1, wlo + (size_t)OFF_WAR  * MB1, 1u * MB1);
    wsplit(w_de,  whi + (size_t)OFF_WDE  * MB1, wlo + (size_t)OFF_WDE  * MB1, 1u * MB1);
    wsplit(w_ar1, whi + (size_t)OFF_WAR1 * MB1, wlo + (size_t)OFF_WAR1 * MB1, 1u * MB1);
    wsplit(w_de1, whi + (size_t)OFF_WDE1 * MB1, wlo + (size_t)OFF_WDE1 * MB1, 1u * MB1);
    wsplit(w_y1,  whi + (size_t)OFF_WY1  * MB1, wlo + (size_t)OFF_WY1  * MB1, 1u * MB1);
    wsplit(w_agg, whi + (size_t)OFF_WAGG * MB1, wlo + (size_t)OFF_WAGG * MB1, 1u * MB1);
    wsplit(w_qkv,  whi + (size_t)OFF_WQKV  * MB1, wlo + (size_t)OFF_WQKV  * MB1, 6u * MB1);
    wsplit(w_o,    whi + (size_t)OFF_WO    * MB1, wlo + (size_t)OFF_WO    * MB1, 2u * MB1);
    wsplit(w_up,   whi + (size_t)OFF_WUP   * MB1, wlo + (size_t)OFF_WUP   * MB1, 8u * MB1);
    wsplit(w_down, whi + (size_t)OFF_WDOWN * MB1, wlo + (size_t)OFF_WDOWN * MB1, 4u * MB1);

    // input projections
    rmsnorm_k<<<3072, 256>>>(x_input, old_norm_w, hh, hl, 48, 64, 0);      // x_old_n
    tgemm(hh, hl, whi + (size_t)OFF_WOLD * MB1, wlo + (size_t)OFF_WOLD * MB1,
          xold, 3072, 1024, 1024, false);
    rmsnorm_k<<<1024, 256>>>(x_ar,    new_norm_w, xarnh, xarnl, 16, 16, 0);
    rmsnorm_k<<<1024, 256>>>(x_input, new_norm_w, xdenh, xdenl, 16, 64, 48);
    tgemm(xarnh, xarnl, whi + (size_t)OFF_WAR * MB1, wlo + (size_t)OFF_WAR * MB1,
          xnew, 1024, 1024, 1024, false);
    tgemm(xdenh, xdenl, whi + (size_t)OFF_WDE * MB1, wlo + (size_t)OFF_WDE * MB1,
          xnew, 1024, 1024, 1024, true);
    assemble_k<<<(BP_ * S_ * 256 + 255) / 256, 256>>>(x, xold, xnew);

    for (int it = 0; it < 2; it++) {
        for (int li = 0; li < 2; li++) {
            const __nv_bfloat16* wq_h = whi + (size_t)(OFF_WQKV + 3 * li) * MB1;
            const __nv_bfloat16* wq_l = wlo + (size_t)(OFF_WQKV + 3 * li) * MB1;
            const __nv_bfloat16* wo_h = whi + (size_t)(OFF_WO + li) * MB1;
            const __nv_bfloat16* wo_l = wlo + (size_t)(OFF_WO + li) * MB1;
            const __nv_bfloat16* wu_h = whi + (size_t)(OFF_WUP + 4 * li) * MB1;
            const __nv_bfloat16* wu_l = wlo + (size_t)(OFF_WUP + 4 * li) * MB1;
            const __nv_bfloat16* wd_h = whi + (size_t)(OFF_WDOWN + 2 * li) * MB1;
            const __nv_bfloat16* wd_l = wlo + (size_t)(OFF_WDOWN + 2 * li) * MB1;

            rmsnorm_k<<<4096, 256>>>(x, attn_norm_w + li * 1024, hh, hl, 1, 1, 0);
            tgemm(hh, hl, wq_h, wq_l, qkv, 4096, 3072, 1024, false);
            qk_rope_k<<<dim3(2048, 16, 2), 128>>>(qkv);
            attn_k<<<dim3(2048, 8, 2), 128>>>(qkv, mask, ah, al);
            tgemm(ah, al, wo_h, wo_l, x, 4096, 1024, 1024, true);
            rmsnorm_k<<<4096, 256>>>(x, ffn_norm_w + li * 1024, hh, hl, 1, 1, 0);
            tgemm(hh, hl, wu_h, wu_l, up, 4096, 4096, 1024, false);
            silu_gate_k<<<(BP_ * S_ * FH_ + 255) / 256, 256>>>(up, gh, gl);
            tgemm(gh, gl, wd_h, wd_l, x, 4096, 1024, 2048, true);
        }
        extract_y_k<<<(BP_ * 512 * 256 + 255) / 256, 256>>>(x, y, yh, yl);
        if (it == 0) {
            yfrms_k<<<1024, 256>>>(y, begin, pad_emb, new_norm_w, y2h, y2l);
            tgemm(xarnh, xarnl, whi + (size_t)OFF_WAR1 * MB1, wlo + (size_t)OFF_WAR1 * MB1,
                  xnew, 1024, 1024, 1024, false);
            tgemm(y2h, y2l, whi + (size_t)OFF_WY1 * MB1, wlo + (size_t)OFF_WY1 * MB1,
                  xnew, 1024, 1024, 1024, true);
            tgemm(xdenh, xdenl, whi + (size_t)OFF_WDE1 * MB1, wlo + (size_t)OFF_WDE1 * MB1,
                  xnew, 1024, 1024, 1024, true);
            assemble_k<<<(BP_ * S_ * 256 + 255) / 256, 256>>>(x, xold, xnew);
        }
    }

    tgemm(yh, yl, whi + (size_t)OFF_WAGG * MB1, wlo + (size_t)OFF_WAGG * MB1,
          out, 1024, 1024, 1024, false);
}

// round 7
// speedup vs baseline: 5.9146x; 1.0870x over previous
#include <cuda_runtime.h>
#include <cuda_bf16.h>
#include <math.h>
#include <stdint.h>

// ---------------- problem constants ----------------
#define BP_  2
#define L_   32
#define N_   16
#define O_   64
#define D_   1024
#define AD_  1024
#define HEAD_ 128
#define W_   256
#define FH_  2048
#define M_   48
#define E_   64
#define S_   2048
#define EPS_ 1e-5f
#define MB1 (1u<<20)

// ---------------- device scratch (allocation-free) ----------------
__device__ float g_x   [BP_ * S_ * AD_];
__device__ float g_qkv [BP_ * S_ * 3 * AD_];
__device__ float g_up  [BP_ * S_ * 2 * FH_];
__device__ float g_xold[BP_ * L_ * M_ * AD_];
__device__ float g_xnew[BP_ * L_ * N_ * AD_];
__device__ float g_y   [BP_ * L_ * N_ * AD_];
__device__ float g_invf[64];

// bf16 split activation buffers
__device__ __nv_bfloat16 g_hh[BP_ * S_ * AD_],  g_hl[BP_ * S_ * AD_];
__device__ __nv_bfloat16 g_ah[BP_ * S_ * AD_],  g_al[BP_ * S_ * AD_];
__device__ __nv_bfloat16 g_gh[BP_ * S_ * FH_],  g_gl[BP_ * S_ * FH_];
__device__ __nv_bfloat16 g_xarnh[MB1], g_xarnl[MB1];
__device__ __nv_bfloat16 g_xdenh[MB1], g_xdenl[MB1];
__device__ __nv_bfloat16 g_y2h[MB1],   g_y2l[MB1];
__device__ __nv_bfloat16 g_yh[MB1],    g_yl[MB1];
// bf16 split weights: 27M elems (offsets in MB1 units)
__device__ __nv_bfloat16 g_whi[27u * MB1], g_wlo[27u * MB1];

#define OFF_WOLD  0
#define OFF_WAR   1
#define OFF_WDE   2
#define OFF_WAR1  3
#define OFF_WDE1  4
#define OFF_WY1   5
#define OFF_WAGG  6
#define OFF_WQKV  7
#define OFF_WO    13
#define OFF_WUP   15
#define OFF_WDOWN 23

// ---------------- small helpers ----------------
__device__ __forceinline__ void bsplit(float f, __nv_bfloat16& h, __nv_bfloat16& l) {
    h = __float2bfloat16(f);
    l = __float2bfloat16(f - __bfloat162float(h));
}

__device__ __forceinline__ float blk_sum(float v, float* red) {
    int lane = threadIdx.x & 31, w = threadIdx.x >> 5;
#pragma unroll
    for (int o = 16; o; o >>= 1) v += __shfl_xor_sync(0xffffffffu, v, o);
    if (lane == 0) red[w] = v;
    __syncthreads();
    int nw = (blockDim.x + 31) >> 5;
    if (threadIdx.x < 32) {
        float r = (threadIdx.x < nw) ? red[threadIdx.x] : 0.f;
#pragma unroll
        for (int o = 16; o; o >>= 1) r += __shfl_xor_sync(0xffffffffu, r, o);
        if (lane == 0) red[0] = r;
    }
    __syncthreads();
    float r = red[0];
    __syncthreads();
    return r;
}

// ---------------- PTX helpers (compute_103-legal) ----------------
#define SWZ64(o) ((o) ^ (((o) >> 3) & 0x30))

static __device__ __forceinline__ uint32_t smem_u32(const void* p) {
    uint32_t a;
    asm("{ .reg .u64 t; cvta.to.shared.u64 t, %1; cvt.u32.u64 %0, t; }" : "=r"(a) : "l"(p));
    return a;
}
static __device__ __forceinline__ void cpa16(uint32_t dst, const void* src) {
    asm volatile("cp.async.cg.shared.global [%0], [%1], 16;" :: "r"(dst), "l"(src) : "memory");
}
static __device__ __forceinline__ void ldm4(uint32_t& r0, uint32_t& r1, uint32_t& r2,
                                            uint32_t& r3, uint32_t addr) {
    asm volatile("ldmatrix.sync.aligned.m8n8.x4.shared.b16 {%0,%1,%2,%3}, [%4];"
                 : "=r"(r0), "=r"(r1), "=r"(r2), "=r"(r3) : "r"(addr));
}
#define MMA16816(d, a, b) \
    asm volatile("mma.sync.aligned.m16n8k16.row.col.f32.bf16.bf16.f32 " \
        "{%0,%1,%2,%3}, {%4,%5,%6,%7}, {%8,%9}, {%0,%1,%2,%3};" \
        : "+f"((d)[0]), "+f"((d)[1]), "+f"((d)[2]), "+f"((d)[3]) \
        : "r"((a)[0]), "r"((a)[1]), "r"((a)[2]), "r"((a)[3]), "r"((b)[0]), "r"((b)[1]))

// ---------------- tensor-core split-bf16 GEMM (3-stage, 1 sync/chunk) ----------------
// C[M,N] (+)= Ah@Bh^T + Ah@Bl^T + Al@Bh^T. M,N mult of 128; K mult of 32.
// 256 threads, warp grid 2(m) x 4(n), warp tile 64x32. Stage = 4x8KB SW64 tiles.
template<bool ACC>
__global__ void __launch_bounds__(256) tgemm_k(
    const __nv_bfloat16* __restrict__ Ah, const __nv_bfloat16* __restrict__ Al,
    const __nv_bfloat16* __restrict__ Bh, const __nv_bfloat16* __restrict__ Bl,
    float* __restrict__ C, int M, int N, int K)
{
    extern __shared__ char smem[];
    uint32_t sb = smem_u32(smem);
    int tid = threadIdx.x, lane = tid & 31, wid = tid >> 5;
    int wm = wid & 1, wn = wid >> 1;
    int brow = blockIdx.y << 7, bcol = blockIdx.x << 7;

    const __nv_bfloat16* src0 = Ah + (size_t)brow * K;
    const __nv_bfloat16* src1 = Al + (size_t)brow * K;
    const __nv_bfloat16* src2 = Bh + (size_t)bcol * K;
    const __nv_bfloat16* src3 = Bl + (size_t)bcol * K;

    float d[4][4][4];
#pragma unroll
    for (int mi = 0; mi < 4; mi++)
#pragma unroll
        for (int ni = 0; ni < 4; ni++)
#pragma unroll
            for (int q = 0; q < 4; q++) d[mi][ni][q] = 0.f;

    const int nch = K >> 5;

    auto load_stage = [&](uint32_t stb, int k0) {
#pragma unroll
        for (int j = 0; j < 2; j++) {
            int u = tid + (j << 8);
            int row = u >> 2, un = u & 3;
            uint32_t doff = SWZ64((uint32_t)(row * 64 + un * 16));
            size_t goff = (size_t)row * K + k0 + un * 8;
            cpa16(stb +     0 + doff, src0 + goff);
            cpa16(stb +  8192 + doff, src1 + goff);
            cpa16(stb + 16384 + doff, src2 + goff);
            cpa16(stb + 24576 + doff, src3 + goff);
        }
        asm volatile("cp.async.commit_group;" ::: "memory");
    };

    load_stage(sb, 0);
    if (nch > 1) load_stage(sb + 32768, 32);

    int g = lane >> 3, r = lane & 7;
    for (int i = 0; i < nch; i++) {
        if (i + 1 < nch) { asm volatile("cp.async.wait_group 1;" ::: "memory"); }
        else             { asm volatile("cp.async.wait_group 0;" ::: "memory"); }
        __syncthreads();
        // buffer (i+2)%3 held stage i-1, finished by all warps at the sync above
        if (i + 2 < nch) {
            int s = (i + 2) % 3;
            load_stage(sb + (uint32_t)(s * 32768), (i + 2) << 5);
        }
        uint32_t stb = sb + (uint32_t)((i % 3) * 32768);

#pragma unroll
        for (int ks = 0; ks < 2; ks++) {
            uint32_t ah[4][4], al[4][4], bh[4][2], bl[4][2];
#pragma unroll
            for (int mi = 0; mi < 4; mi++) {
                int row = wm * 64 + mi * 16 + (g & 1) * 8 + r;
                int colb = ks * 32 + (g >> 1) * 16;
                uint32_t off = SWZ64((uint32_t)(row * 64 + colb));
                ldm4(ah[mi][0], ah[mi][1], ah[mi][2], ah[mi][3], stb + off);
                ldm4(al[mi][0], al[mi][1], al[mi][2], al[mi][3], stb + 8192 + off);
            }
#pragma unroll
            for (int n2 = 0; n2 < 2; n2++) {
                int rown = wn * 32 + n2 * 16 + (g >> 1) * 8 + r;
                int colb = ks * 32 + (g & 1) * 16;
                uint32_t off = SWZ64((uint32_t)(rown * 64 + colb));
                ldm4(bh[2*n2][0], bh[2*n2][1], bh[2*n2+1][0], bh[2*n2+1][1], stb + 16384 + off);
                ldm4(bl[2*n2][0], bl[2*n2][1], bl[2*n2+1][0], bl[2*n2+1][1], stb + 24576 + off);
            }
#pragma unroll
            for (int mi = 0; mi < 4; mi++)
#pragma unroll
                for (int ni = 0; ni < 4; ni++) MMA16816(d[mi][ni], ah[mi], bh[ni]);
#pragma unroll
            for (int mi = 0; mi < 4; mi++)
#pragma unroll
                for (int ni = 0; ni < 4; ni++) MMA16816(d[mi][ni], ah[mi], bl[ni]);
#pragma unroll
            for (int mi = 0; mi < 4; mi++)
#pragma unroll
                for (int ni = 0; ni < 4; ni++) MMA16816(d[mi][ni], al[mi], bh[ni]);
        }
    }

    // epilogue: registers -> global
#pragma unroll
    for (int mi = 0; mi < 4; mi++)
#pragma unroll
        for (int ni = 0; ni < 4; ni++) {
            int row = brow + wm * 64 + mi * 16 + (lane >> 2);
            int col = bcol + wn * 32 + ni * 8 + 2 * (lane & 3);
            float* p0 = C + (size_t)row * N + col;
            float* p1 = C + (size_t)(row + 8) * N + col;
            float2 v0 = make_float2(d[mi][ni][0], d[mi][ni][1]);
            float2 v1 = make_float2(d[mi][ni][2], d[mi][ni][3]);
            if (ACC) {
                float2 o0 = *(const float2*)p0, o1 = *(const float2*)p1;
                v0.x += o0.x; v0.y += o0.y; v1.x += o1.x; v1.y += o1.y;
            }
            *(float2*)p0 = v0;
            *(float2*)p1 = v1;
        }
}

// ---------------- fp32 -> (hi, lo) bf16 split ----------------
__global__ void split_k(const float* __restrict__ in, __nv_bfloat16* __restrict__ hi,
                        __nv_bfloat16* __restrict__ lo, int n4) {
    int i = blockIdx.x * 256 + threadIdx.x;
    if (i >= n4) return;
    float4 v = ((const float4*)in)[i];
    __nv_bfloat16 h0, h1, h2, h3, l0, l1, l2, l3;
    bsplit(v.x, h0, l0); bsplit(v.y, h1, l1); bsplit(v.z, h2, l2); bsplit(v.w, h3, l3);
    __nv_bfloat162* H = (__nv_bfloat162*)hi;
    __nv_bfloat162* Lo = (__nv_bfloat162*)lo;
    H[2 * i]      = __nv_bfloat162(h0, h1);
    H[2 * i + 1]  = __nv_bfloat162(h2, h3);
    Lo[2 * i]     = __nv_bfloat162(l0, l1);
    Lo[2 * i + 1] = __nv_bfloat162(l2, l3);
}

// ---------------- one-time inv_freq table ----------------
__global__ void init_invf_k() {
    int j = threadIdx.x;
    if (j < 64) {
        double invf_d = exp(-(double)j * (9.210340371976184 / 64.0));
        g_invf[j] = (float)invf_d;
    }
}

// ---------------- rmsnorm -> split bf16 ----------------
__global__ void rmsnorm_k(const float* __restrict__ in, const float* __restrict__ w,
                          __nv_bfloat16* __restrict__ oh, __nv_bfloat16* __restrict__ ol,
                          int gsize, int gstride, int goff) {
    __shared__ float red[32];
    int r = blockIdx.x;
    int inrow = (r / gsize) * gstride + goff + (r % gsize);
    const float* x = in + (size_t)inrow * 1024;
    float v[4]; float ss = 0.f;
#pragma unroll
    for (int i = 0; i < 4; i++) { v[i] = x[threadIdx.x + i * 256]; ss += v[i] * v[i]; }
    ss = blk_sum(ss, red);
    float sc = rsqrtf(ss * (1.f / 1024.f) + EPS_);
#pragma unroll
    for (int i = 0; i < 4; i++) {
        int idx = threadIdx.x + i * 256;
        float f = v[i] * sc * w[idx];
        __nv_bfloat16 h, l; bsplit(f, h, l);
        size_t o = (size_t)r * 1024 + idx;
        oh[o] = h; ol[o] = l;
    }
}

// ---------------- fused shifted-y + rmsnorm (refresh) -> split ----------------
__global__ void yfrms_k(const float* __restrict__ y, const int* __restrict__ begin,
                        const float* __restrict__ pad_emb, const float* __restrict__ w,
                        __nv_bfloat16* __restrict__ oh, __nv_bfloat16* __restrict__ ol) {
    __shared__ float red[32];
    int r = blockIdx.x;
    int b = r >> 9, t = r & 511;
    int n = t & 15, l = t >> 4;
    bool cond = (n == 0) && (begin[b * 32 + l] != 0);
    const float* x = cond ? pad_emb : (y + ((size_t)b * 512 + ((t + 511) & 511)) * 1024);
    float v[4]; float ss = 0.f;
#pragma unroll
    for (int i = 0; i < 4; i++) { v[i] = x[threadIdx.x + i * 256]; ss += v[i] * v[i]; }
    ss = blk_sum(ss, red);
    float sc = rsqrtf(ss * (1.f / 1024.f) + EPS_);
#pragma unroll
    for (int i = 0; i < 4; i++) {
        int idx = threadIdx.x + i * 256;
        float f = v[i] * sc * w[idx];
        __nv_bfloat16 h, lo; bsplit(f, h, lo);
        size_t o = (size_t)r * 1024 + idx;
        oh[o] = h; ol[o] = lo;
    }
}

// ---------------- l2norm + rotary on q,k in-place ----------------
__global__ void qk_rope_k(float* __restrict__ qkv) {
    __shared__ float red[32];
    __shared__ float sh[128];
    int s = blockIdx.x, hk = blockIdx.y, b = blockIdx.z;
    int h = hk >> 1;
    int off = (hk & 1) ? 1024 : 0;
    float* p = qkv + ((size_t)(b * 2048 + s)) * 3072 + off + h * 128;
    int tid = threadIdx.x;
    float v = p[tid];
    float ss = blk_sum(v * v, red);
    float scl = 1.f / fmaxf(sqrtf(ss), EPS_);
    sh[tid] = v * scl;
    __syncthreads();
    int j = tid & 63;
    float ang = (float)s * g_invf[j];
    float c = cosf(ang), sn = sinf(ang);
    float x1 = sh[j], x2 = sh[j + 64];
    p[tid] = (tid < 64) ? (x1 * c + x2 * sn) : (-x1 * sn + x2 * c);
}

// ---------------- attention v2: CTA per (b, role*8+h, qb) ----------------
// role 0: 48 old queries x 48 own old keys (mask algebra: unconditional).
// role 1: 16 new queries x (prior-new + own block) candidates, exact inline mask.
__global__ void __launch_bounds__(128) attn2_k(const float* __restrict__ qkv,
                                               const int* __restrict__ doc,
                                               __nv_bfloat16* __restrict__ oh,
                                               __nv_bfloat16* __restrict__ ol) {
    __shared__ __align__(16) float sbuf[8752];
    int qb = blockIdx.x;
    int role = blockIdx.y >> 3;
    int h = blockIdx.y & 7;
    int b = blockIdx.z;
    int t = threadIdx.x;
    int lane = t & 31, w = t >> 5;
    const float* base = qkv + (size_t)b * 2048 * 3072;
    const float* Qb = base + (size_t)h * 128;
    const float* Kb = base + 1024 + (size_t)h * 128;
    const float* Vb = base + 2048 + (size_t)h * 128;
    const float scale = 0.088388347648318447f;  // 1/sqrt(128)

    if (role == 0) {
        float (*qs)[132] = (float(*)[132])sbuf;             // 48 x 132
        float (*ps)[49]  = (float(*)[49])(sbuf + 6336);     // 48 x 49
        float* inv = sbuf + 6336 + 2352;                    // 48
        for (int u = t; u < 48 * 32; u += 128) {
            int rr = u >> 5, c = u & 31;
            *(float4*)&qs[rr][c * 4] =
                *(const float4*)&Qb[(size_t)(qb * 64 + rr) * 3072 + c * 4];
        }
        __syncthreads();
        // scores 48x48: thread (tq = t&15 -> 3 q, tk = t>>4 -> 6 k)
        int tq = t & 15, tk = t >> 4;
        float acc[3][6];
#pragma unroll
        for (int j = 0; j < 3; j++)
#pragma unroll
            for (int i = 0; i < 6; i++) acc[j][i] = 0.f;
#pragma unroll
        for (int dc = 0; dc < 8; dc++) {
            float4 qv[3][4];
#pragma unroll
            for (int j = 0; j < 3; j++)
#pragma unroll
                for (int x = 0; x < 4; x++)
                    qv[j][x] = *(float4*)&qs[tq + 16 * j][dc * 16 + x * 4];
#pragma unroll
            for (int i = 0; i < 6; i++) {
                int k = tk + 8 * i;
                const float4* Kr = (const float4*)&Kb[(size_t)(qb * 64 + k) * 3072 + dc * 16];
#pragma unroll
                for (int x = 0; x < 4; x++) {
                    float4 kv = Kr[x];
#pragma unroll
                    for (int j = 0; j < 3; j++)
                        acc[j][i] += qv[j][x].x * kv.x + qv[j][x].y * kv.y
                                   + qv[j][x].z * kv.z + qv[j][x].w * kv.w;
                }
            }
        }
#pragma unroll
        for (int j = 0; j < 3; j++)
#pragma unroll
            for (int i = 0; i < 6; i++)
                ps[tq + 16 * j][tk + 8 * i] = acc[j][i] * scale;
        __syncthreads();
        // softmax: warp w -> q rows w*12 .. w*12+11 (48 keys, no mask)
        for (int j = 0; j < 12; j++) {
            int q = w * 12 + j;
            float v0 = ps[q][lane];
            float v1 = (lane < 16) ? ps[q][lane + 32] : -INFINITY;
            float m = fmaxf(v0, v1);
#pragma unroll
            for (int o = 16; o; o >>= 1) m = fmaxf(m, __shfl_xor_sync(0xffffffffu, m, o));
            float p0 = expf(v0 - m);
            float p1 = (lane < 16) ? expf(v1 - m) : 0.f;
            float s = p0 + p1;
#pragma unroll
            for (int o = 16; o; o >>= 1) s += __shfl_xor_sync(0xffffffffu, s, o);
            ps[q][lane] = p0;
            if (lane < 16) ps[q][lane + 32] = p1;
            if (lane == 0) inv[q] = 1.f / s;
        }
        __syncthreads();
        // PV: thread (tq2 = t&15 -> 3 q, td = t>>4 -> 16 d)
        int tq2 = t & 15, td = t >> 4;
        float a2[3][16];
#pragma unroll
        for (int j = 0; j < 3; j++)
#pragma unroll
            for (int x = 0; x < 16; x++) a2[j][x] = 0.f;
        for (int k = 0; k < 48; k++) {
            const float4* Vr = (const float4*)&Vb[(size_t)(qb * 64 + k) * 3072 + td * 16];
            float4 v[4];
#pragma unroll
            for (int x = 0; x < 4; x++) v[x] = Vr[x];
#pragma unroll
            for (int j = 0; j < 3; j++) {
                float p = ps[tq2 + 16 * j][k];
#pragma unroll
                for (int x = 0; x < 4; x++) {
                    a2[j][x * 4 + 0] += p * v[x].x; a2[j][x * 4 + 1] += p * v[x].y;
                    a2[j][x * 4 + 2] += p * v[x].z; a2[j][x * 4 + 3] += p * v[x].w;
                }
            }
        }
#pragma unroll
        for (int j = 0; j < 3; j++) {
            int q = tq2 + 16 * j;
            float iv = inv[q];
            size_t o = ((size_t)(b * 2048 + qb * 64 + q)) * 1024 + h * 128 + td * 16;
#pragma unroll
            for (int x = 0; x < 16; x++) {
                __nv_bfloat16 fh, fl; bsplit(a2[j][x] * iv, fh, fl);
                oh[o + x] = fh; ol[o + x] = fl;
            }
        }
    } else {
        float (*qs)[132] = (float(*)[132])sbuf;             // 16 x 132
        float (*ps)[324] = (float(*)[324])(sbuf + 2112);    // 16 x 324
        int*   kls  = (int*)(sbuf + 2112 + 5184);           // 320
        int*   docs = kls + 320;                            // 32
        float* inv  = (float*)(docs + 32);                  // 16
        int npb = min(16, qb), np = npb * 16, NK = np + 64;
        if (t < 32) docs[t] = doc[b * 32 + t];
        for (int i = t; i < NK; i += 128) {
            int k;
            if (i < np) { int kb = qb - npb + (i >> 4); k = kb * 64 + 48 + (i & 15); }
            else          k = qb * 64 + (i - np);
            kls[i] = k;
        }
        for (int u = t; u < 16 * 32; u += 128) {
            int rr = u >> 5, c = u & 31;
            *(float4*)&qs[rr][c * 4] =
                *(const float4*)&Qb[(size_t)(qb * 64 + 48 + rr) * 3072 + c * 4];
        }
        __syncthreads();
        int tq = t & 15, tk = t >> 4;
        // scores, d-chunked so q stays in registers
#pragma unroll
        for (int dc = 0; dc < 4; dc++) {
            float4 qv[8];
#pragma unroll
            for (int x = 0; x < 8; x++) qv[x] = *(float4*)&qs[tq][dc * 32 + x * 4];
            for (int ki = tk; ki < NK; ki += 8) {
                const float4* Kr = (const float4*)&Kb[(size_t)kls[ki] * 3072 + dc * 32];
                float a = 0.f;
#pragma unroll
                for (int x = 0; x < 8; x++) {
                    float4 kv = Kr[x];
                    a += qv[x].x * kv.x + qv[x].y * kv.y + qv[x].z * kv.z + qv[x].w * kv.w;
                }
                if (dc == 0) ps[tq][ki] = a; else ps[tq][ki] += a;
            }
        }
        // exact mask (reference conditions) + scale; same thread owns (tq, ki)
        {
            int docq = docs[qb];
            int docp = docs[qb > 0 ? qb - 1 : 0];
            int q = qb * 64 + 48 + tq;
            int posq = (48 + tq) + qb * 16;
            for (int ki = tk; ki < NK; ki += 8) {
                int k = kls[ki];
                int kb = k >> 6, kr = k & 63;
                bool newk = kr >= 48;
                int posk = kr + kb * 16;
                bool nn = newk && (q >= k) && (posq < posk + 256) && (docq == docs[kb]);
                bool ao = (!newk) && (kb == qb) && (docq == docp);
                ps[tq][ki] = (nn || ao) ? ps[tq][ki] * scale : -INFINITY;
            }
        }
        __syncthreads();
        // softmax: warp w -> q = w*4 + j
        for (int j = 0; j < 4; j++) {
            int q = w * 4 + j;
            float m = -INFINITY;
            for (int i = lane; i < NK; i += 32) m = fmaxf(m, ps[q][i]);
#pragma unroll
            for (int o = 16; o; o >>= 1) m = fmaxf(m, __shfl_xor_sync(0xffffffffu, m, o));
            float s = 0.f;
            for (int i = lane; i < NK; i += 32) {
                float v = ps[q][i];
                float p = (v > -INFINITY) ? expf(v - m) : 0.f;
                ps[q][i] = p;
                s += p;
            }
#pragma unroll
            for (int o = 16; o; o >>= 1) s += __shfl_xor_sync(0xffffffffu, s, o);
            if (lane == 0) inv[q] = 1.f / s;
        }
        __syncthreads();
        // PV: thread (tq3 = t>>3 -> q, td = t&7 -> 16 d)
        int tq3 = t >> 3, td = t & 7;
        float a2[16];
#pragma unroll
        for (int x = 0; x < 16; x++) a2[x] = 0.f;
        for (int ki = 0; ki < NK; ki++) {
            float p = ps[tq3][ki];
            if (p != 0.f) {
                const float4* Vr = (const float4*)&Vb[(size_t)kls[ki] * 3072 + td * 16];
#pragma unroll
                for (int x = 0; x < 4; x++) {
                    float4 v = Vr[x];
                    a2[x * 4 + 0] += p * v.x; a2[x * 4 + 1] += p * v.y;
                    a2[x * 4 + 2] += p * v.z; a2[x * 4 + 3] += p * v.w;
                }
            }
        }
        float iv = inv[tq3];
        size_t o = ((size_t)(b * 2048 + qb * 64 + 48 + tq3)) * 1024 + h * 128 + td * 16;
#pragma unroll
        for (int x = 0; x < 16; x++) {
            __nv_bfloat16 fh, fl; bsplit(a2[x] * iv, fh, fl);
            oh[o + x] = fh; ol[o + x] = fl;
        }
    }
}

// ---------------- silu-gate -> split bf16 ----------------
__global__ void silu_gate_k(const float* __restrict__ up,
                            __nv_bfloat16* __restrict__ gh, __nv_bfloat16* __restrict__ gl) {
    int idx = blockIdx.x * blockDim.x + threadIdx.x;
    if (idx >= BP_ * S_ * FH_) return;
    int r = idx >> 11, c = idx & 2047;
    float a  = up[(size_t)r * 4096 + c];
    float bb = up[(size_t)r * 4096 + 2048 + c];
    float f = (a / (1.f + expf(-a))) * bb;
    __nv_bfloat16 h, l; bsplit(f, h, l);
    gh[idx] = h; gl[idx] = l;
}

// ---------------- assemble x from x_old / x_new ----------------
__global__ void assemble_k(float* __restrict__ x, const float* __restrict__ xold,
                           const float* __restrict__ xnew) {
    int idx = blockIdx.x * blockDim.x + threadIdx.x;
    if (idx >= BP_ * S_ * 256) return;
    int d4 = idx & 255;
    int gr = idx >> 8;
    int b = gr >> 11, s = gr & 2047;
    int l = s >> 6, rr = s & 63;
    float4 v;
    if (rr < 48)
        v = ((const float4*)xold)[((size_t)((b * 32 + l) * 48 + rr)) * 256 + d4];
    else
        v = ((const float4*)xnew)[((size_t)((b * 32 + l) * 16 + (rr - 48))) * 256 + d4];
    ((float4*)x)[idx] = v;
}

// ---------------- extract y = x[:,:,M:,:] (fp32 + split) ----------------
__global__ void extract_y_k(const float* __restrict__ x, float* __restrict__ y,
                            __nv_bfloat16* __restrict__ yh, __nv_bfloat16* __restrict__ yl) {
    int idx = blockIdx.x * blockDim.x + threadIdx.x;
    if (idx >= BP_ * 512 * 256) return;
    int d4 = idx & 255;
    int r = idx >> 8;
    int b = r >> 9, t = r & 511;
    int l = t >> 4, n = t & 15;
    int xr = b * 2048 + l * 64 + 48 + n;
    float4 v = ((const float4*)x)[(size_t)xr * 256 + d4];
    ((float4*)y)[idx] = v;
    __nv_bfloat16 h0, h1, h2, h3, l0, l1, l2, l3;
    bsplit(v.x, h0, l0); bsplit(v.y, h1, l1); bsplit(v.z, h2, l2); bsplit(v.w, h3, l3);
    ((__nv_bfloat162*)yh)[2 * idx]     = __nv_bfloat162(h0, h1);
    ((__nv_bfloat162*)yh)[2 * idx + 1] = __nv_bfloat162(h2, h3);
    ((__nv_bfloat162*)yl)[2 * idx]     = __nv_bfloat162(l0, l1);
    ((__nv_bfloat162*)yl)[2 * idx + 1] = __nv_bfloat162(l2, l3);
}

// ---------------- host helpers ----------------
#define TG_SMEM (3 * 32768)

static void tgemm(const __nv_bfloat16* Ah, const __nv_bfloat16* Al,
                  const __nv_bfloat16* Bh, const __nv_bfloat16* Bl,
                  float* C, int M, int N, int K, bool acc) {
    dim3 grid(N >> 7, M >> 7);
    if (acc) {
        cudaFuncSetAttribute(tgemm_k<true>, cudaFuncAttributeMaxDynamicSharedMemorySize, TG_SMEM);
        tgemm_k<true><<<grid, 256, TG_SMEM>>>(Ah, Al, Bh, Bl, C, M, N, K);
    } else {
        cudaFuncSetAttribute(tgemm_k<false>, cudaFuncAttributeMaxDynamicSharedMemorySize, TG_SMEM);
        tgemm_k<false><<<grid, 256, TG_SMEM>>>(Ah, Al, Bh, Bl, C, M, N, K);
    }
}

static void wsplit(const float* in, __nv_bfloat16* hi, __nv_bfloat16* lo, size_t n) {
    int n4 = (int)(n >> 2);
    split_k<<<(n4 + 255) / 256, 256>>>(in, hi, lo, n4);
}

extern "C" void kernel_launch(void* const* d_in, const int* in_sizes, int n_in,
                              void* d_out, int out_size) {
    (void)in_sizes; (void)n_in; (void)out_size;
    const float* x_input     = (const float*)d_in[0];
    const float* x_ar        = (const float*)d_in[1];
    const int*   doc         = (const int*)d_in[2];
    const int*   begin       = (const int*)d_in[3];
    const float* old_norm_w  = (const float*)d_in[4];
    const float* new_norm_w  = (const float*)d_in[5];
    const float* w_old       = (const float*)d_in[6];
    const float* w_ar        = (const float*)d_in[7];
    const float* w_de        = (const float*)d_in[8];
    const float* w_ar1       = (const float*)d_in[9];
    const float* w_de1       = (const float*)d_in[10];
    const float* w_y1        = (const float*)d_in[11];
    const float* pad_emb     = (const float*)d_in[12];
    const float* w_agg       = (const float*)d_in[13];
    const float* attn_norm_w = (const float*)d_in[14];
    const float* ffn_norm_w  = (const float*)d_in[15];
    const float* w_qkv       = (const float*)d_in[16];
    const float* w_o         = (const float*)d_in[17];
    const float* w_up        = (const float*)d_in[18];
    const float* w_down      = (const float*)d_in[19];
    float* out = (float*)d_out;

    float *x, *qkv, *up, *xold, *xnew, *y;
    __nv_bfloat16 *hh, *hl, *ah, *al, *gh, *gl;
    __nv_bfloat16 *xarnh, *xarnl, *xdenh, *xdenl, *y2h, *y2l, *yh, *yl, *whi, *wlo;
    cudaGetSymbolAddress((void**)&x,    g_x);
    cudaGetSymbolAddress((void**)&qkv,  g_qkv);
    cudaGetSymbolAddress((void**)&up,   g_up);
    cudaGetSymbolAddress((void**)&xold, g_xold);
    cudaGetSymbolAddress((void**)&xnew, g_xnew);
    cudaGetSymbolAddress((void**)&y,    g_y);
    cudaGetSymbolAddress((void**)&hh,   g_hh);
    cudaGetSymbolAddress((void**)&hl,   g_hl);
    cudaGetSymbolAddress((void**)&ah,   g_ah);
    cudaGetSymbolAddress((void**)&al,   g_al);
    cudaGetSymbolAddress((void**)&gh,   g_gh);
    cudaGetSymbolAddress((void**)&gl,   g_gl);
    cudaGetSymbolAddress((void**)&xarnh, g_xarnh);
    cudaGetSymbolAddress((void**)&xarnl, g_xarnl);
    cudaGetSymbolAddress((void**)&xdenh, g_xdenh);
    cudaGetSymbolAddress((void**)&xdenl, g_xdenl);
    cudaGetSymbolAddress((void**)&y2h,  g_y2h);
    cudaGetSymbolAddress((void**)&y2l,  g_y2l);
    cudaGetSymbolAddress((void**)&yh,   g_yh);
    cudaGetSymbolAddress((void**)&yl,   g_yl);
    cudaGetSymbolAddress((void**)&whi,  g_whi);
    cudaGetSymbolAddress((void**)&wlo,  g_wlo);

    init_invf_k<<<1, 64>>>();

    // weight splits (every call; deterministic)
    wsplit(w_old, whi + (size_t)OFF_WOLD * MB1, wlo + (size_t)OFF_WOLD * MB1, 1u * MB1);
    wsplit(w_ar,  whi + (size_t)OFF_WAR  * MB1, wlo + (size_t)OFF_WAR  * MB1, 1u * MB1);
    wsplit(w_de,  whi + (size_t)OFF_WDE  * MB1, wlo + (size_t)OFF_WDE  * MB1, 1u * MB1);
    wsplit(w_ar1, whi + (size_t)OFF_WAR1 * MB1, wlo + (size_t)OFF_WAR1 * MB1, 1u * MB1);
    wsplit(w_de1, whi + (size_t)OFF_WDE1 * MB1, wlo + (size_t)OFF_WDE1 * MB1, 1u * MB1);
    wsplit(w_y1,  whi + (size_t)OFF_WY1  * MB1, wlo + (size_t)OFF_WY1  * MB1, 1u * MB1);
    wsplit(w_agg, whi + (size_t)OFF_WAGG * MB1, wlo + (size_t)OFF_WAGG * MB1, 1u * MB1);
    wsplit(w_qkv,  whi + (size_t)OFF_WQKV  * MB1, wlo + (size_t)OFF_WQKV  * MB1, 6u * MB1);
    wsplit(w_o,    whi + (size_t)OFF_WO    * MB1, wlo + (size_t)OFF_WO    * MB1, 2u * MB1);
    wsplit(w_up,   whi + (size_t)OFF_WUP   * MB1, wlo + (size_t)OFF_WUP   * MB1, 8u * MB1);
    wsplit(w_down, whi + (size_t)OFF_WDOWN * MB1, wlo + (size_t)OFF_WDOWN * MB1, 4u * MB1);

    // input projections
    rmsnorm_k<<<3072, 256>>>(x_input, old_norm_w, hh, hl, 48, 64, 0);
    tgemm(hh, hl, whi + (size_t)OFF_WOLD * MB1, wlo + (size_t)OFF_WOLD * MB1,
          xold, 3072, 1024, 1024, false);
    rmsnorm_k<<<1024, 256>>>(x_ar,    new_norm_w, xarnh, xarnl, 16, 16, 0);
    rmsnorm_k<<<1024, 256>>>(x_input, new_norm_w, xdenh, xdenl, 16, 64, 48);
    tgemm(xarnh, xarnl, whi + (size_t)OFF_WAR * MB1, wlo + (size_t)OFF_WAR * MB1,
          xnew, 1024, 1024, 1024, false);
    tgemm(xdenh, xdenl, whi + (size_t)OFF_WDE * MB1, wlo + (size_t)OFF_WDE * MB1,
          xnew, 1024, 1024, 1024, true);
    assemble_k<<<(BP_ * S_ * 256 + 255) / 256, 256>>>(x, xold, xnew);

    for (int it = 0; it < 2; it++) {
        for (int li = 0; li < 2; li++) {
            const __nv_bfloat16* wq_h = whi + (size_t)(OFF_WQKV + 3 * li) * MB1;
            const __nv_bfloat16* wq_l = wlo + (size_t)(OFF_WQKV + 3 * li) * MB1;
            const __nv_bfloat16* wo_h = whi + (size_t)(OFF_WO + li) * MB1;
            const __nv_bfloat16* wo_l = wlo + (size_t)(OFF_WO + li) * MB1;
            const __nv_bfloat16* wu_h = whi + (size_t)(OFF_WUP + 4 * li) * MB1;
            const __nv_bfloat16* wu_l = wlo + (size_t)(OFF_WUP + 4 * li) * MB1;
            const __nv_bfloat16* wd_h = whi + (size_t)(OFF_WDOWN + 2 * li) * MB1;
            const __nv_bfloat16* wd_l = wlo + (size_t)(OFF_WDOWN + 2 * li) * MB1;

            rmsnorm_k<<<4096, 256>>>(x, attn_norm_w + li * 1024, hh, hl, 1, 1, 0);
            tgemm(hh, hl, wq_h, wq_l, qkv, 4096, 3072, 1024, false);
            qk_rope_k<<<dim3(2048, 16, 2), 128>>>(qkv);
            attn2_k<<<dim3(32, 16, 2), 128>>>(qkv, doc, ah, al);
            tgemm(ah, al, wo_h, wo_l, x, 4096, 1024, 1024, true);
            rmsnorm_k<<<4096, 256>>>(x, ffn_norm_w + li * 1024, hh, hl, 1, 1, 0);
            tgemm(hh, hl, wu_h, wu_l, up, 4096, 4096, 1024, false);
            silu_gate_k<<<(BP_ * S_ * FH_ + 255) / 256, 256>>>(up, gh, gl);
            tgemm(gh, gl, wd_h, wd_l, x, 4096, 1024, 2048, true);
        }
        extract_y_k<<<(BP_ * 512 * 256 + 255) / 256, 256>>>(x, y, yh, yl);
        if (it == 0) {
            yfrms_k<<<1024, 256>>>(y, begin, pad_emb, new_norm_w, y2h, y2l);
            tgemm(xarnh, xarnl, whi + (size_t)OFF_WAR1 * MB1, wlo + (size_t)OFF_WAR1 * MB1,
                  xnew, 1024, 1024, 1024, false);
            tgemm(y2h, y2l, whi + (size_t)OFF_WY1 * MB1, wlo + (size_t)OFF_WY1 * MB1,
                  xnew, 1024, 1024, 1024, true);
            tgemm(xdenh, xdenl, whi + (size_t)OFF_WDE1 * MB1, wlo + (size_t)OFF_WDE1 * MB1,
                  xnew, 1024, 1024, 1024, true);
            assemble_k<<<(BP_ * S_ * 256 + 255) / 256, 256>>>(x, xold, xnew);
        }
    }

    tgemm(yh, yl, whi + (size_t)OFF_WAGG * MB1, wlo + (size_t)OFF_WAGG * MB1,
          out, 1024, 1024, 1024, false);
}

// round 8
// speedup vs baseline: 6.2380x; 1.0547x over previous
#include <cuda_runtime.h>
#include <cuda_bf16.h>
#include <math.h>
#include <stdint.h>

// ---------------- problem constants ----------------
#define BP_  2
#define L_   32
#define N_   16
#define O_   64
#define D_   1024
#define AD_  1024
#define HEAD_ 128
#define W_   256
#define FH_  2048
#define M_   48
#define E_   64
#define S_   2048
#define EPS_ 1e-5f
#define MB1 (1u<<20)

// ---------------- device scratch (allocation-free) ----------------
__device__ float g_x   [BP_ * S_ * AD_];
__device__ float g_qkv [BP_ * S_ * 3 * AD_];
__device__ float g_xold[BP_ * L_ * M_ * AD_];
__device__ float g_xnew[BP_ * L_ * N_ * AD_];
__device__ float g_y   [BP_ * L_ * N_ * AD_];
__device__ float g_invf[64];

// bf16 split activation buffers
__device__ __nv_bfloat16 g_hh[BP_ * S_ * AD_],  g_hl[BP_ * S_ * AD_];
__device__ __nv_bfloat16 g_ah[BP_ * S_ * AD_],  g_al[BP_ * S_ * AD_];
__device__ __nv_bfloat16 g_uph[BP_ * S_ * 2 * FH_], g_upl[BP_ * S_ * 2 * FH_];
__device__ __nv_bfloat16 g_gh[BP_ * S_ * FH_],  g_gl[BP_ * S_ * FH_];
__device__ __nv_bfloat16 g_xarnh[MB1], g_xarnl[MB1];
__device__ __nv_bfloat16 g_xdenh[MB1], g_xdenl[MB1];
__device__ __nv_bfloat16 g_y2h[MB1],   g_y2l[MB1];
__device__ __nv_bfloat16 g_yh[MB1],    g_yl[MB1];
// bf16 split weights: 27 MB1 units
__device__ __nv_bfloat16 g_whi[27u * MB1], g_wlo[27u * MB1];

#define OFF_WOLD  0
#define OFF_WAR   1
#define OFF_WDE   2
#define OFF_WAR1  3
#define OFF_WDE1  4
#define OFF_WY1   5
#define OFF_WAGG  6
#define OFF_WQKV  7
#define OFF_WO    13
#define OFF_WUP   15
#define OFF_WDOWN 23

// ---------------- small helpers ----------------
__device__ __forceinline__ void bsplit(float f, __nv_bfloat16& h, __nv_bfloat16& l) {
    h = __float2bfloat16(f);
    l = __float2bfloat16(f - __bfloat162float(h));
}

__device__ __forceinline__ float blk_sum(float v, float* red) {
    int lane = threadIdx.x & 31, w = threadIdx.x >> 5;
#pragma unroll
    for (int o = 16; o; o >>= 1) v += __shfl_xor_sync(0xffffffffu, v, o);
    if (lane == 0) red[w] = v;
    __syncthreads();
    int nw = (blockDim.x + 31) >> 5;
    if (threadIdx.x < 32) {
        float r = (threadIdx.x < nw) ? red[threadIdx.x] : 0.f;
#pragma unroll
        for (int o = 16; o; o >>= 1) r += __shfl_xor_sync(0xffffffffu, r, o);
        if (lane == 0) red[0] = r;
    }
    __syncthreads();
    float r = red[0];
    __syncthreads();
    return r;
}

// ---------------- PTX helpers (compute_103-legal) ----------------
#define SWZ64(o) ((o) ^ (((o) >> 3) & 0x30))

static __device__ __forceinline__ uint32_t smem_u32(const void* p) {
    uint32_t a;
    asm("{ .reg .u64 t; cvta.to.shared.u64 t, %1; cvt.u32.u64 %0, t; }" : "=r"(a) : "l"(p));
    return a;
}
static __device__ __forceinline__ void cpa16(uint32_t dst, const void* src) {
    asm volatile("cp.async.cg.shared.global [%0], [%1], 16;" :: "r"(dst), "l"(src) : "memory");
}
static __device__ __forceinline__ void ldm4(uint32_t& r0, uint32_t& r1, uint32_t& r2,
                                            uint32_t& r3, uint32_t addr) {
    asm volatile("ldmatrix.sync.aligned.m8n8.x4.shared.b16 {%0,%1,%2,%3}, [%4];"
                 : "=r"(r0), "=r"(r1), "=r"(r2), "=r"(r3) : "r"(addr));
}
#define MMA16816(d, a, b) \
    asm volatile("mma.sync.aligned.m16n8k16.row.col.f32.bf16.bf16.f32 " \
        "{%0,%1,%2,%3}, {%4,%5,%6,%7}, {%8,%9}, {%0,%1,%2,%3};" \
        : "+f"((d)[0]), "+f"((d)[1]), "+f"((d)[2]), "+f"((d)[3]) \
        : "r"((a)[0]), "r"((a)[1]), "r"((a)[2]), "r"((a)[3]), "r"((b)[0]), "r"((b)[1]))

// ---------------- tensor-core split-bf16 GEMM (3-stage, 2 CTA/SM) ----------------
// OMODE: 0 = store fp32, 1 = accumulate fp32, 2 = store split bf16 (Ch, Cl).
template<int OMODE>
__global__ void __launch_bounds__(256, 2) tgemm_k(
    const __nv_bfloat16* __restrict__ Ah, const __nv_bfloat16* __restrict__ Al,
    const __nv_bfloat16* __restrict__ Bh, const __nv_bfloat16* __restrict__ Bl,
    float* __restrict__ C, __nv_bfloat16* __restrict__ Ch, __nv_bfloat16* __restrict__ Cl,
    int M, int N, int K)
{
    extern __shared__ char smem[];
    uint32_t sb = smem_u32(smem);
    int tid = threadIdx.x, lane = tid & 31, wid = tid >> 5;
    int wm = wid & 1, wn = wid >> 1;
    int brow = blockIdx.y << 7, bcol = blockIdx.x << 7;

    const __nv_bfloat16* src0 = Ah + (size_t)brow * K;
    const __nv_bfloat16* src1 = Al + (size_t)brow * K;
    const __nv_bfloat16* src2 = Bh + (size_t)bcol * K;
    const __nv_bfloat16* src3 = Bl + (size_t)bcol * K;

    float d[4][4][4];
#pragma unroll
    for (int mi = 0; mi < 4; mi++)
#pragma unroll
        for (int ni = 0; ni < 4; ni++)
#pragma unroll
            for (int q = 0; q < 4; q++) d[mi][ni][q] = 0.f;

    const int nch = K >> 5;

    auto load_stage = [&](uint32_t stb, int k0) {
#pragma unroll
        for (int j = 0; j < 2; j++) {
            int u = tid + (j << 8);
            int row = u >> 2, un = u & 3;
            uint32_t doff = SWZ64((uint32_t)(row * 64 + un * 16));
            size_t goff = (size_t)row * K + k0 + un * 8;
            cpa16(stb +     0 + doff, src0 + goff);
            cpa16(stb +  8192 + doff, src1 + goff);
            cpa16(stb + 16384 + doff, src2 + goff);
            cpa16(stb + 24576 + doff, src3 + goff);
        }
        asm volatile("cp.async.commit_group;" ::: "memory");
    };

    load_stage(sb, 0);
    if (nch > 1) load_stage(sb + 32768, 32);

    int g = lane >> 3, r = lane & 7;
    for (int i = 0; i < nch; i++) {
        if (i + 1 < nch) { asm volatile("cp.async.wait_group 1;" ::: "memory"); }
        else             { asm volatile("cp.async.wait_group 0;" ::: "memory"); }
        __syncthreads();
        if (i + 2 < nch) {
            int s = (i + 2) % 3;
            load_stage(sb + (uint32_t)(s * 32768), (i + 2) << 5);
        }
        uint32_t stb = sb + (uint32_t)((i % 3) * 32768);

#pragma unroll
        for (int ks = 0; ks < 2; ks++) {
            uint32_t ah[4][4], al[4][4], bh[4][2], bl[4][2];
#pragma unroll
            for (int mi = 0; mi < 4; mi++) {
                int row = wm * 64 + mi * 16 + (g & 1) * 8 + r;
                int colb = ks * 32 + (g >> 1) * 16;
                uint32_t off = SWZ64((uint32_t)(row * 64 + colb));
                ldm4(ah[mi][0], ah[mi][1], ah[mi][2], ah[mi][3], stb + off);
                ldm4(al[mi][0], al[mi][1], al[mi][2], al[mi][3], stb + 8192 + off);
            }
#pragma unroll
            for (int n2 = 0; n2 < 2; n2++) {
                int rown = wn * 32 + n2 * 16 + (g >> 1) * 8 + r;
                int colb = ks * 32 + (g & 1) * 16;
                uint32_t off = SWZ64((uint32_t)(rown * 64 + colb));
                ldm4(bh[2*n2][0], bh[2*n2][1], bh[2*n2+1][0], bh[2*n2+1][1], stb + 16384 + off);
                ldm4(bl[2*n2][0], bl[2*n2][1], bl[2*n2+1][0], bl[2*n2+1][1], stb + 24576 + off);
            }
#pragma unroll
            for (int mi = 0; mi < 4; mi++)
#pragma unroll
                for (int ni = 0; ni < 4; ni++) MMA16816(d[mi][ni], ah[mi], bh[ni]);
#pragma unroll
            for (int mi = 0; mi < 4; mi++)
#pragma unroll
                for (int ni = 0; ni < 4; ni++) MMA16816(d[mi][ni], ah[mi], bl[ni]);
#pragma unroll
            for (int mi = 0; mi < 4; mi++)
#pragma unroll
                for (int ni = 0; ni < 4; ni++) MMA16816(d[mi][ni], al[mi], bh[ni]);
        }
    }

    // epilogue
#pragma unroll
    for (int mi = 0; mi < 4; mi++)
#pragma unroll
        for (int ni = 0; ni < 4; ni++) {
            int row = brow + wm * 64 + mi * 16 + (lane >> 2);
            int col = bcol + wn * 32 + ni * 8 + 2 * (lane & 3);
            if (OMODE == 2) {
                __nv_bfloat16 h0, h1, l0, l1;
                bsplit(d[mi][ni][0], h0, l0); bsplit(d[mi][ni][1], h1, l1);
                *(__nv_bfloat162*)(Ch + (size_t)row * N + col) = __nv_bfloat162(h0, h1);
                *(__nv_bfloat162*)(Cl + (size_t)row * N + col) = __nv_bfloat162(l0, l1);
                bsplit(d[mi][ni][2], h0, l0); bsplit(d[mi][ni][3], h1, l1);
                *(__nv_bfloat162*)(Ch + (size_t)(row + 8) * N + col) = __nv_bfloat162(h0, h1);
                *(__nv_bfloat162*)(Cl + (size_t)(row + 8) * N + col) = __nv_bfloat162(l0, l1);
            } else {
                float* p0 = C + (size_t)row * N + col;
                float* p1 = C + (size_t)(row + 8) * N + col;
                float2 v0 = make_float2(d[mi][ni][0], d[mi][ni][1]);
                float2 v1 = make_float2(d[mi][ni][2], d[mi][ni][3]);
                if (OMODE == 1) {
                    float2 o0 = *(const float2*)p0, o1 = *(const float2*)p1;
                    v0.x += o0.x; v0.y += o0.y; v1.x += o1.x; v1.y += o1.y;
                }
                *(float2*)p0 = v0;
                *(float2*)p1 = v1;
            }
        }
}

// ---------------- fused weight split: all 11 tensors, one launch ----------------
struct WSrc { const float* p[11]; };
__global__ void wsplit_all_k(WSrc ws, __nv_bfloat16* __restrict__ hi,
                             __nv_bfloat16* __restrict__ lo) {
    const unsigned char segOf[27] = {0,1,2,3,4,5,6, 7,7,7,7,7,7, 8,8, 9,9,9,9,9,9,9,9, 10,10,10,10};
    const unsigned char locOf[27] = {0,0,0,0,0,0,0, 0,1,2,3,4,5, 0,1, 0,1,2,3,4,5,6,7, 0,1,2,3};
    int unit = blockIdx.y;
    const float4* src = (const float4*)ws.p[segOf[unit]] + (size_t)locOf[unit] * (MB1 >> 2);
    __nv_bfloat162* H  = (__nv_bfloat162*)(hi + (size_t)unit * MB1);
    __nv_bfloat162* Lo = (__nv_bfloat162*)(lo + (size_t)unit * MB1);
    for (int i = blockIdx.x * blockDim.x + threadIdx.x; i < (int)(MB1 >> 2);
         i += gridDim.x * blockDim.x) {
        float4 v = src[i];
        __nv_bfloat16 h0, h1, h2, h3, l0, l1, l2, l3;
        bsplit(v.x, h0, l0); bsplit(v.y, h1, l1);
        bsplit(v.z, h2, l2); bsplit(v.w, h3, l3);
        H[2 * i]      = __nv_bfloat162(h0, h1);
        H[2 * i + 1]  = __nv_bfloat162(h2, h3);
        Lo[2 * i]     = __nv_bfloat162(l0, l1);
        Lo[2 * i + 1] = __nv_bfloat162(l2, l3);
    }
}

// ---------------- one-time inv_freq table ----------------
__global__ void init_invf_k() {
    int j = threadIdx.x;
    if (j < 64) {
        double invf_d = exp(-(double)j * (9.210340371976184 / 64.0));
        g_invf[j] = (float)invf_d;
    }
}

// ---------------- rmsnorm -> split bf16 ----------------
__global__ void rmsnorm_k(const float* __restrict__ in, const float* __restrict__ w,
                          __nv_bfloat16* __restrict__ oh, __nv_bfloat16* __restrict__ ol,
                          int gsize, int gstride, int goff) {
    __shared__ float red[32];
    int r = blockIdx.x;
    int inrow = (r / gsize) * gstride + goff + (r % gsize);
    const float* x = in + (size_t)inrow * 1024;
    float v[4]; float ss = 0.f;
#pragma unroll
    for (int i = 0; i < 4; i++) { v[i] = x[threadIdx.x + i * 256]; ss += v[i] * v[i]; }
    ss = blk_sum(ss, red);
    float sc = rsqrtf(ss * (1.f / 1024.f) + EPS_);
#pragma unroll
    for (int i = 0; i < 4; i++) {
        int idx = threadIdx.x + i * 256;
        float f = v[i] * sc * w[idx];
        __nv_bfloat16 h, l; bsplit(f, h, l);
        size_t o = (size_t)r * 1024 + idx;
        oh[o] = h; ol[o] = l;
    }
}

// ---------------- fused shifted-y + rmsnorm (refresh) -> split ----------------
__global__ void yfrms_k(const float* __restrict__ y, const int* __restrict__ begin,
                        const float* __restrict__ pad_emb, const float* __restrict__ w,
                        __nv_bfloat16* __restrict__ oh, __nv_bfloat16* __restrict__ ol) {
    __shared__ float red[32];
    int r = blockIdx.x;
    int b = r >> 9, t = r & 511;
    int n = t & 15, l = t >> 4;
    bool cond = (n == 0) && (begin[b * 32 + l] != 0);
    const float* x = cond ? pad_emb : (y + ((size_t)b * 512 + ((t + 511) & 511)) * 1024);
    float v[4]; float ss = 0.f;
#pragma unroll
    for (int i = 0; i < 4; i++) { v[i] = x[threadIdx.x + i * 256]; ss += v[i] * v[i]; }
    ss = blk_sum(ss, red);
    float sc = rsqrtf(ss * (1.f / 1024.f) + EPS_);
#pragma unroll
    for (int i = 0; i < 4; i++) {
        int idx = threadIdx.x + i * 256;
        float f = v[i] * sc * w[idx];
        __nv_bfloat16 h, lo; bsplit(f, h, lo);
        size_t o = (size_t)r * 1024 + idx;
        oh[o] = h; ol[o] = lo;
    }
}

// ---------------- l2norm + rotary on q,k in-place ----------------
__global__ void qk_rope_k(float* __restrict__ qkv) {
    __shared__ float red[32];
    __shared__ float sh[128];
    int s = blockIdx.x, hk = blockIdx.y, b = blockIdx.z;
    int h = hk >> 1;
    int off = (hk & 1) ? 1024 : 0;
    float* p = qkv + ((size_t)(b * 2048 + s)) * 3072 + off + h * 128;
    int tid = threadIdx.x;
    float v = p[tid];
    float ss = blk_sum(v * v, red);
    float scl = 1.f / fmaxf(sqrtf(ss), EPS_);
    sh[tid] = v * scl;
    __syncthreads();
    int j = tid & 63;
    float ang = (float)s * g_invf[j];
    float c = cosf(ang), sn = sinf(ang);
    float x1 = sh[j], x2 = sh[j + 64];
    p[tid] = (tid < 64) ? (x1 * c + x2 * sn) : (-x1 * sn + x2 * c);
}

// ---------------- attention v2: CTA per (b, role*8+h, qb) ----------------
__global__ void __launch_bounds__(128) attn2_k(const float* __restrict__ qkv,
                                               const int* __restrict__ doc,
                                               __nv_bfloat16* __restrict__ oh,
                                               __nv_bfloat16* __restrict__ ol) {
    __shared__ __align__(16) float sbuf[8752];
    int qb = blockIdx.x;
    int role = blockIdx.y >> 3;
    int h = blockIdx.y & 7;
    int b = blockIdx.z;
    int t = threadIdx.x;
    int lane = t & 31, w = t >> 5;
    const float* base = qkv + (size_t)b * 2048 * 3072;
    const float* Qb = base + (size_t)h * 128;
    const float* Kb = base + 1024 + (size_t)h * 128;
    const float* Vb = base + 2048 + (size_t)h * 128;
    const float scale = 0.088388347648318447f;

    if (role == 0) {
        float (*qs)[132] = (float(*)[132])sbuf;
        float (*ps)[49]  = (float(*)[49])(sbuf + 6336);
        float* inv = sbuf + 6336 + 2352;
        for (int u = t; u < 48 * 32; u += 128) {
            int rr = u >> 5, c = u & 31;
            *(float4*)&qs[rr][c * 4] =
                *(const float4*)&Qb[(size_t)(qb * 64 + rr) * 3072 + c * 4];
        }
        __syncthreads();
        int tq = t & 15, tk = t >> 4;
        float acc[3][6];
#pragma unroll
        for (int j = 0; j < 3; j++)
#pragma unroll
            for (int i = 0; i < 6; i++) acc[j][i] = 0.f;
#pragma unroll
        for (int dc = 0; dc < 8; dc++) {
            float4 qv[3][4];
#pragma unroll
            for (int j = 0; j < 3; j++)
#pragma unroll
                for (int x = 0; x < 4; x++)
                    qv[j][x] = *(float4*)&qs[tq + 16 * j][dc * 16 + x * 4];
#pragma unroll
            for (int i = 0; i < 6; i++) {
                int k = tk + 8 * i;
                const float4* Kr = (const float4*)&Kb[(size_t)(qb * 64 + k) * 3072 + dc * 16];
#pragma unroll
                for (int x = 0; x < 4; x++) {
                    float4 kv = Kr[x];
#pragma unroll
                    for (int j = 0; j < 3; j++)
                        acc[j][i] += qv[j][x].x * kv.x + qv[j][x].y * kv.y
                                   + qv[j][x].z * kv.z + qv[j][x].w * kv.w;
                }
            }
        }
#pragma unroll
        for (int j = 0; j < 3; j++)
#pragma unroll
            for (int i = 0; i < 6; i++)
                ps[tq + 16 * j][tk + 8 * i] = acc[j][i] * scale;
        __syncthreads();
        for (int j = 0; j < 12; j++) {
            int q = w * 12 + j;
            float v0 = ps[q][lane];
            float v1 = (lane < 16) ? ps[q][lane + 32] : -INFINITY;
            float m = fmaxf(v0, v1);
#pragma unroll
            for (int o = 16; o; o >>= 1) m = fmaxf(m, __shfl_xor_sync(0xffffffffu, m, o));
            float p0 = expf(v0 - m);
            float p1 = (lane < 16) ? expf(v1 - m) : 0.f;
            float s = p0 + p1;
#pragma unroll
            for (int o = 16; o; o >>= 1) s += __shfl_xor_sync(0xffffffffu, s, o);
            ps[q][lane] = p0;
            if (lane < 16) ps[q][lane + 32] = p1;
            if (lane == 0) inv[q] = 1.f / s;
        }
        __syncthreads();
        int tq2 = t & 15, td = t >> 4;
        float a2[3][16];
#pragma unroll
        for (int j = 0; j < 3; j++)
#pragma unroll
            for (int x = 0; x < 16; x++) a2[j][x] = 0.f;
        for (int k = 0; k < 48; k++) {
            const float4* Vr = (const float4*)&Vb[(size_t)(qb * 64 + k) * 3072 + td * 16];
            float4 v[4];
#pragma unroll
            for (int x = 0; x < 4; x++) v[x] = Vr[x];
#pragma unroll
            for (int j = 0; j < 3; j++) {
                float p = ps[tq2 + 16 * j][k];
#pragma unroll
                for (int x = 0; x < 4; x++) {
                    a2[j][x * 4 + 0] += p * v[x].x; a2[j][x * 4 + 1] += p * v[x].y;
                    a2[j][x * 4 + 2] += p * v[x].z; a2[j][x * 4 + 3] += p * v[x].w;
                }
            }
        }
#pragma unroll
        for (int j = 0; j < 3; j++) {
            int q = tq2 + 16 * j;
            float iv = inv[q];
            size_t o = ((size_t)(b * 2048 + qb * 64 + q)) * 1024 + h * 128 + td * 16;
#pragma unroll
            for (int x = 0; x < 16; x++) {
                __nv_bfloat16 fh, fl; bsplit(a2[j][x] * iv, fh, fl);
                oh[o + x] = fh; ol[o + x] = fl;
            }
        }
    } else {
        float (*qs)[132] = (float(*)[132])sbuf;
        float (*ps)[324] = (float(*)[324])(sbuf + 2112);
        int*   kls  = (int*)(sbuf + 2112 + 5184);
        int*   docs = kls + 320;
        float* inv  = (float*)(docs + 32);
        int npb = min(16, qb), np = npb * 16, NK = np + 64;
        if (t < 32) docs[t] = doc[b * 32 + t];
        for (int i = t; i < NK; i += 128) {
            int k;
            if (i < np) { int kb = qb - npb + (i >> 4); k = kb * 64 + 48 + (i & 15); }
            else          k = qb * 64 + (i - np);
            kls[i] = k;
        }
        for (int u = t; u < 16 * 32; u += 128) {
            int rr = u >> 5, c = u & 31;
            *(float4*)&qs[rr][c * 4] =
                *(const float4*)&Qb[(size_t)(qb * 64 + 48 + rr) * 3072 + c * 4];
        }
        __syncthreads();
        int tq = t & 15, tk = t >> 4;
#pragma unroll
        for (int dc = 0; dc < 4; dc++) {
            float4 qv[8];
#pragma unroll
            for (int x = 0; x < 8; x++) qv[x] = *(float4*)&qs[tq][dc * 32 + x * 4];
            for (int ki = tk; ki < NK; ki += 8) {
                const float4* Kr = (const float4*)&Kb[(size_t)kls[ki] * 3072 + dc * 32];
                float a = 0.f;
#pragma unroll
                for (int x = 0; x < 8; x++) {
                    float4 kv = Kr[x];
                    a += qv[x].x * kv.x + qv[x].y * kv.y + qv[x].z * kv.z + qv[x].w * kv.w;
                }
                if (dc == 0) ps[tq][ki] = a; else ps[tq][ki] += a;
            }
        }
        {
            int docq = docs[qb];
            int docp = docs[qb > 0 ? qb - 1 : 0];
            int q = qb * 64 + 48 + tq;
            int posq = (48 + tq) + qb * 16;
            for (int ki = tk; ki < NK; ki += 8) {
                int k = kls[ki];
                int kb = k >> 6, kr = k & 63;
                bool newk = kr >= 48;
                int posk = kr + kb * 16;
                bool nn = newk && (q >= k) && (posq < posk + 256) && (docq == docs[kb]);
                bool ao = (!newk) && (kb == qb) && (docq == docp);
                ps[tq][ki] = (nn || ao) ? ps[tq][ki] * scale : -INFINITY;
            }
        }
        __syncthreads();
        for (int j = 0; j < 4; j++) {
            int q = w * 4 + j;
            float m = -INFINITY;
            for (int i = lane; i < NK; i += 32) m = fmaxf(m, ps[q][i]);
#pragma unroll
            for (int o = 16; o; o >>= 1) m = fmaxf(m, __shfl_xor_sync(0xffffffffu, m, o));
            float s = 0.f;
            for (int i = lane; i < NK; i += 32) {
                float v = ps[q][i];
                float p = (v > -INFINITY) ? expf(v - m) : 0.f;
                ps[q][i] = p;
                s += p;
            }
#pragma unroll
            for (int o = 16; o; o >>= 1) s += __shfl_xor_sync(0xffffffffu, s, o);
            if (lane == 0) inv[q] = 1.f / s;
        }
        __syncthreads();
        int tq3 = t >> 3, td = t & 7;
        float a2[16];
#pragma unroll
        for (int x = 0; x < 16; x++) a2[x] = 0.f;
        for (int ki = 0; ki < NK; ki++) {
            float p = ps[tq3][ki];
            if (p != 0.f) {
                const float4* Vr = (const float4*)&Vb[(size_t)kls[ki] * 3072 + td * 16];
#pragma unroll
                for (int x = 0; x < 4; x++) {
                    float4 v = Vr[x];
                    a2[x * 4 + 0] += p * v.x; a2[x * 4 + 1] += p * v.y;
                    a2[x * 4 + 2] += p * v.z; a2[x * 4 + 3] += p * v.w;
                }
            }
        }
        float iv = inv[tq3];
        size_t o = ((size_t)(b * 2048 + qb * 64 + 48 + tq3)) * 1024 + h * 128 + td * 16;
#pragma unroll
        for (int x = 0; x < 16; x++) {
            __nv_bfloat16 fh, fl; bsplit(a2[x] * iv, fh, fl);
            oh[o + x] = fh; ol[o + x] = fl;
        }
    }
}

// ---------------- silu-gate from split-bf16 up -> split bf16 gate ----------------
__global__ void silu_gate_k(const __nv_bfloat16* __restrict__ uph,
                            const __nv_bfloat16* __restrict__ upl,
                            __nv_bfloat16* __restrict__ gh, __nv_bfloat16* __restrict__ gl) {
    int i = blockIdx.x * 256 + threadIdx.x;         // over BP_*S_*FH_/4
    if (i >= (BP_ * S_ * FH_) / 4) return;
    int r = i >> 9, c4 = i & 511;
    size_t oa = (size_t)r * 4096 + c4 * 4;
    __nv_bfloat162 ah0 = *(const __nv_bfloat162*)(uph + oa);
    __nv_bfloat162 ah1 = *(const __nv_bfloat162*)(uph + oa + 2);
    __nv_bfloat162 al0 = *(const __nv_bfloat162*)(upl + oa);
    __nv_bfloat162 al1 = *(const __nv_bfloat162*)(upl + oa + 2);
    __nv_bfloat162 bh0 = *(const __nv_bfloat162*)(uph + oa + 2048);
    __nv_bfloat162 bh1 = *(const __nv_bfloat162*)(uph + oa + 2050);
    __nv_bfloat162 bl0 = *(const __nv_bfloat162*)(upl + oa + 2048);
    __nv_bfloat162 bl1 = *(const __nv_bfloat162*)(upl + oa + 2050);
    float a[4], bb[4];
    a[0] = __bfloat162float(ah0.x) + __bfloat162float(al0.x);
    a[1] = __bfloat162float(ah0.y) + __bfloat162float(al0.y);
    a[2] = __bfloat162float(ah1.x) + __bfloat162float(al1.x);
    a[3] = __bfloat162float(ah1.y) + __bfloat162float(al1.y);
    bb[0] = __bfloat162float(bh0.x) + __bfloat162float(bl0.x);
    bb[1] = __bfloat162float(bh0.y) + __bfloat162float(bl0.y);
    bb[2] = __bfloat162float(bh1.x) + __bfloat162float(bl1.x);
    bb[3] = __bfloat162float(bh1.y) + __bfloat162float(bl1.y);
    __nv_bfloat16 h[4], l[4];
#pragma unroll
    for (int j = 0; j < 4; j++) {
        float f = (a[j] / (1.f + expf(-a[j]))) * bb[j];
        bsplit(f, h[j], l[j]);
    }
    size_t og = (size_t)r * 2048 + c4 * 4;
    *(__nv_bfloat162*)(gh + og)     = __nv_bfloat162(h[0], h[1]);
    *(__nv_bfloat162*)(gh + og + 2) = __nv_bfloat162(h[2], h[3]);
    *(__nv_bfloat162*)(gl + og)     = __nv_bfloat162(l[0], l[1]);
    *(__nv_bfloat162*)(gl + og + 2) = __nv_bfloat162(l[2], l[3]);
}

// ---------------- assemble x from x_old / x_new ----------------
__global__ void assemble_k(float* __restrict__ x, const float* __restrict__ xold,
                           const float* __restrict__ xnew) {
    int idx = blockIdx.x * blockDim.x + threadIdx.x;
    if (idx >= BP_ * S_ * 256) return;
    int d4 = idx & 255;
    int gr = idx >> 8;
    int b = gr >> 11, s = gr & 2047;
    int l = s >> 6, rr = s & 63;
    float4 v;
    if (rr < 48)
        v = ((const float4*)xold)[((size_t)((b * 32 + l) * 48 + rr)) * 256 + d4];
    else
        v = ((const float4*)xnew)[((size_t)((b * 32 + l) * 16 + (rr - 48))) * 256 + d4];
    ((float4*)x)[idx] = v;
}

// ---------------- extract y = x[:,:,M:,:] (fp32 + split) ----------------
__global__ void extract_y_k(const float* __restrict__ x, float* __restrict__ y,
                            __nv_bfloat16* __restrict__ yh, __nv_bfloat16* __restrict__ yl) {
    int idx = blockIdx.x * blockDim.x + threadIdx.x;
    if (idx >= BP_ * 512 * 256) return;
    int d4 = idx & 255;
    int r = idx >> 8;
    int b = r >> 9, t = r & 511;
    int l = t >> 4, n = t & 15;
    int xr = b * 2048 + l * 64 + 48 + n;
    float4 v = ((const float4*)x)[(size_t)xr * 256 + d4];
    ((float4*)y)[idx] = v;
    __nv_bfloat16 h0, h1, h2, h3, l0, l1, l2, l3;
    bsplit(v.x, h0, l0); bsplit(v.y, h1, l1); bsplit(v.z, h2, l2); bsplit(v.w, h3, l3);
    ((__nv_bfloat162*)yh)[2 * idx]     = __nv_bfloat162(h0, h1);
    ((__nv_bfloat162*)yh)[2 * idx + 1] = __nv_bfloat162(h2, h3);
    ((__nv_bfloat162*)yl)[2 * idx]     = __nv_bfloat162(l0, l1);
    ((__nv_bfloat162*)yl)[2 * idx + 1] = __nv_bfloat162(l2, l3);
}

// ---------------- host helpers ----------------
#define TG_SMEM (3 * 32768)

static void tgemm(const __nv_bfloat16* Ah, const __nv_bfloat16* Al,
                  const __nv_bfloat16* Bh, const __nv_bfloat16* Bl,
                  float* C, __nv_bfloat16* Ch, __nv_bfloat16* Cl,
                  int M, int N, int K, int mode) {
    dim3 grid(N >> 7, M >> 7);
    if (mode == 0) {
        cudaFuncSetAttribute(tgemm_k<0>, cudaFuncAttributeMaxDynamicSharedMemorySize, TG_SMEM);
        tgemm_k<0><<<grid, 256, TG_SMEM>>>(Ah, Al, Bh, Bl, C, Ch, Cl, M, N, K);
    } else if (mode == 1) {
        cudaFuncSetAttribute(tgemm_k<1>, cudaFuncAttributeMaxDynamicSharedMemorySize, TG_SMEM);
        tgemm_k<1><<<grid, 256, TG_SMEM>>>(Ah, Al, Bh, Bl, C, Ch, Cl, M, N, K);
    } else {
        cudaFuncSetAttribute(tgemm_k<2>, cudaFuncAttributeMaxDynamicSharedMemorySize, TG_SMEM);
        tgemm_k<2><<<grid, 256, TG_SMEM>>>(Ah, Al, Bh, Bl, C, Ch, Cl, M, N, K);
    }
}

extern "C" void kernel_launch(void* const* d_in, const int* in_sizes, int n_in,
                              void* d_out, int out_size) {
    (void)in_sizes; (void)n_in; (void)out_size;
    const float* x_input     = (const float*)d_in[0];
    const float* x_ar        = (const float*)d_in[1];
    const int*   doc         = (const int*)d_in[2];
    const int*   begin       = (const int*)d_in[3];
    const float* old_norm_w  = (const float*)d_in[4];
    const float* new_norm_w  = (const float*)d_in[5];
    const float* pad_emb     = (const float*)d_in[12];
    const float* attn_norm_w = (const float*)d_in[14];
    const float* ffn_norm_w  = (const float*)d_in[15];
    float* out = (float*)d_out;

    float *x, *qkv, *xold, *xnew, *y;
    __nv_bfloat16 *hh, *hl, *ah, *al, *uph, *upl, *gh, *gl;
    __nv_bfloat16 *xarnh, *xarnl, *xdenh, *xdenl, *y2h, *y2l, *yh, *yl, *whi, *wlo;
    cudaGetSymbolAddress((void**)&x,    g_x);
    cudaGetSymbolAddress((void**)&qkv,  g_qkv);
    cudaGetSymbolAddress((void**)&xold, g_xold);
    cudaGetSymbolAddress((void**)&xnew, g_xnew);
    cudaGetSymbolAddress((void**)&y,    g_y);
    cudaGetSymbolAddress((void**)&hh,   g_hh);
    cudaGetSymbolAddress((void**)&hl,   g_hl);
    cudaGetSymbolAddress((void**)&ah,   g_ah);
    cudaGetSymbolAddress((void**)&al,   g_al);
    cudaGetSymbolAddress((void**)&uph,  g_uph);
    cudaGetSymbolAddress((void**)&upl,  g_upl);
    cudaGetSymbolAddress((void**)&gh,   g_gh);
    cudaGetSymbolAddress((void**)&gl,   g_gl);
    cudaGetSymbolAddress((void**)&xarnh, g_xarnh);
    cudaGetSymbolAddress((void**)&xarnl, g_xarnl);
    cudaGetSymbolAddress((void**)&xdenh, g_xdenh);
    cudaGetSymbolAddress((void**)&xdenl, g_xdenl);
    cudaGetSymbolAddress((void**)&y2h,  g_y2h);
    cudaGetSymbolAddress((void**)&y2l,  g_y2l);
    cudaGetSymbolAddress((void**)&yh,   g_yh);
    cudaGetSymbolAddress((void**)&yl,   g_yl);
    cudaGetSymbolAddress((void**)&whi,  g_whi);
    cudaGetSymbolAddress((void**)&wlo,  g_wlo);

    init_invf_k<<<1, 64>>>();

    // fused weight split: one launch for all 11 tensors (27 MB1 units)
    WSrc ws;
    ws.p[0]  = (const float*)d_in[6];   // w_old
    ws.p[1]  = (const float*)d_in[7];   // w_ar
    ws.p[2]  = (const float*)d_in[8];   // w_de
    ws.p[3]  = (const float*)d_in[9];   // w_ar1
    ws.p[4]  = (const float*)d_in[10];  // w_de1
    ws.p[5]  = (const float*)d_in[11];  // w_y1
    ws.p[6]  = (const float*)d_in[13];  // w_agg
    ws.p[7]  = (const float*)d_in[16];  // w_qkv
    ws.p[8]  = (const float*)d_in[17];  // w_o
    ws.p[9]  = (const float*)d_in[18];  // w_up
    ws.p[10] = (const float*)d_in[19];  // w_down
    wsplit_all_k<<<dim3(64, 27), 256>>>(ws, whi, wlo);

    // input projections
    rmsnorm_k<<<3072, 256>>>(x_input, old_norm_w, hh, hl, 48, 64, 0);
    tgemm(hh, hl, whi + (size_t)OFF_WOLD * MB1, wlo + (size_t)OFF_WOLD * MB1,
          xold, 0, 0, 3072, 1024, 1024, 0);
    rmsnorm_k<<<1024, 256>>>(x_ar,    new_norm_w, xarnh, xarnl, 16, 16, 0);
    rmsnorm_k<<<1024, 256>>>(x_input, new_norm_w, xdenh, xdenl, 16, 64, 48);
    tgemm(xarnh, xarnl, whi + (size_t)OFF_WAR * MB1, wlo + (size_t)OFF_WAR * MB1,
          xnew, 0, 0, 1024, 1024, 1024, 0);
    tgemm(xdenh, xdenl, whi + (size_t)OFF_WDE * MB1, wlo + (size_t)OFF_WDE * MB1,
          xnew, 0, 0, 1024, 1024, 1024, 1);
    assemble_k<<<(BP_ * S_ * 256 + 255) / 256, 256>>>(x, xold, xnew);

    for (int it = 0; it < 2; it++) {
        for (int li = 0; li < 2; li++) {
            const __nv_bfloat16* wq_h = whi + (size_t)(OFF_WQKV + 3 * li) * MB1;
            const __nv_bfloat16* wq_l = wlo + (size_t)(OFF_WQKV + 3 * li) * MB1;
            const __nv_bfloat16* wo_h = whi + (size_t)(OFF_WO + li) * MB1;
            const __nv_bfloat16* wo_l = wlo + (size_t)(OFF_WO + li) * MB1;
            const __nv_bfloat16* wu_h = whi + (size_t)(OFF_WUP + 4 * li) * MB1;
            const __nv_bfloat16* wu_l = wlo + (size_t)(OFF_WUP + 4 * li) * MB1;
            const __nv_bfloat16* wd_h = whi + (size_t)(OFF_WDOWN + 2 * li) * MB1;
            const __nv_bfloat16* wd_l = wlo + (size_t)(OFF_WDOWN + 2 * li) * MB1;

            rmsnorm_k<<<4096, 256>>>(x, attn_norm_w + li * 1024, hh, hl, 1, 1, 0);
            tgemm(hh, hl, wq_h, wq_l, qkv, 0, 0, 4096, 3072, 1024, 0);
            qk_rope_k<<<dim3(2048, 16, 2), 128>>>(qkv);
            attn2_k<<<dim3(32, 16, 2), 128>>>(qkv, doc, ah, al);
            tgemm(ah, al, wo_h, wo_l, x, 0, 0, 4096, 1024, 1024, 1);
            rmsnorm_k<<<4096, 256>>>(x, ffn_norm_w + li * 1024, hh, hl, 1, 1, 0);
            tgemm(hh, hl, wu_h, wu_l, 0, uph, upl, 4096, 4096, 1024, 2);
            silu_gate_k<<<(BP_ * S_ * FH_ / 4 + 255) / 256, 256>>>(uph, upl, gh, gl);
            tgemm(gh, gl, wd_h, wd_l, x, 0, 0, 4096, 1024, 2048, 1);
        }
        extract_y_k<<<(BP_ * 512 * 256 + 255) / 256, 256>>>(x, y, yh, yl);
        if (it == 0) {
            yfrms_k<<<1024, 256>>>(y, begin, pad_emb, new_norm_w, y2h, y2l);
            tgemm(xarnh, xarnl, whi + (size_t)OFF_WAR1 * MB1, wlo + (size_t)OFF_WAR1 * MB1,
                  xnew, 0, 0, 1024, 1024, 1024, 0);
            tgemm(y2h, y2l, whi + (size_t)OFF_WY1 * MB1, wlo + (size_t)OFF_WY1 * MB1,
                  xnew, 0, 0, 1024, 1024, 1024, 1);
            tgemm(xdenh, xdenl, whi + (size_t)OFF_WDE1 * MB1, wlo + (size_t)OFF_WDE1 * MB1,
                  xnew, 0, 0, 1024, 1024, 1024, 1);
            assemble_k<<<(BP_ * S_ * 256 + 255) / 256, 256>>>(x, xold, xnew);
        }
    }

    tgemm(yh, yl, whi + (size_t)OFF_WAGG * MB1, wlo + (size_t)OFF_WAGG * MB1,
          out, 0, 0, 1024, 1024, 1024, 0);
}

// round 9
// speedup vs baseline: 6.4076x; 1.0272x over previous
#include <cuda_runtime.h>
#include <cuda_bf16.h>
#include <math.h>
#include <stdint.h>

// ---------------- problem constants ----------------
#define BP_  2
#define L_   32
#define N_   16
#define O_   64
#define D_   1024
#define AD_  1024
#define HEAD_ 128
#define W_   256
#define FH_  2048
#define M_   48
#define E_   64
#define S_   2048
#define EPS_ 1e-5f
#define MB1 (1u<<20)

// ---------------- device scratch (allocation-free) ----------------
__device__ float g_x   [BP_ * S_ * AD_];
__device__ float g_qkv [BP_ * S_ * 3 * AD_];
__device__ float g_xold[BP_ * L_ * M_ * AD_];
__device__ float g_xnew[BP_ * L_ * N_ * AD_];
__device__ float g_y   [BP_ * L_ * N_ * AD_];
__device__ float g_invf[64];

// bf16 split activation buffers
__device__ __nv_bfloat16 g_hh[BP_ * S_ * AD_],  g_hl[BP_ * S_ * AD_];
__device__ __nv_bfloat16 g_ah[BP_ * S_ * AD_],  g_al[BP_ * S_ * AD_];
__device__ __nv_bfloat16 g_uph[BP_ * S_ * 2 * FH_], g_upl[BP_ * S_ * 2 * FH_];
__device__ __nv_bfloat16 g_gh[BP_ * S_ * FH_],  g_gl[BP_ * S_ * FH_];
__device__ __nv_bfloat16 g_xarnh[MB1], g_xarnl[MB1];
__device__ __nv_bfloat16 g_xdenh[MB1], g_xdenl[MB1];
__device__ __nv_bfloat16 g_y2h[MB1],   g_y2l[MB1];
__device__ __nv_bfloat16 g_yh[MB1],    g_yl[MB1];
// bf16 split weights: 27 MB1 units
__device__ __nv_bfloat16 g_whi[27u * MB1], g_wlo[27u * MB1];

#define OFF_WOLD  0
#define OFF_WAR   1
#define OFF_WDE   2
#define OFF_WAR1  3
#define OFF_WDE1  4
#define OFF_WY1   5
#define OFF_WAGG  6
#define OFF_WQKV  7
#define OFF_WO    13
#define OFF_WUP   15
#define OFF_WDOWN 23

// ---------------- small helpers ----------------
__device__ __forceinline__ void bsplit(float f, __nv_bfloat16& h, __nv_bfloat16& l) {
    h = __float2bfloat16(f);
    l = __float2bfloat16(f - __bfloat162float(h));
}

__device__ __forceinline__ float blk_sum(float v, float* red) {
    int lane = threadIdx.x & 31, w = threadIdx.x >> 5;
#pragma unroll
    for (int o = 16; o; o >>= 1) v += __shfl_xor_sync(0xffffffffu, v, o);
    if (lane == 0) red[w] = v;
    __syncthreads();
    int nw = (blockDim.x + 31) >> 5;
    if (threadIdx.x < 32) {
        float r = (threadIdx.x < nw) ? red[threadIdx.x] : 0.f;
#pragma unroll
        for (int o = 16; o; o >>= 1) r += __shfl_xor_sync(0xffffffffu, r, o);
        if (lane == 0) red[0] = r;
    }
    __syncthreads();
    float r = red[0];
    __syncthreads();
    return r;
}

// ---------------- PTX helpers (compute_103-legal) ----------------
#define SWZ64(o) ((o) ^ (((o) >> 3) & 0x30))

static __device__ __forceinline__ uint32_t smem_u32(const void* p) {
    uint32_t a;
    asm("{ .reg .u64 t; cvta.to.shared.u64 t, %1; cvt.u32.u64 %0, t; }" : "=r"(a) : "l"(p));
    return a;
}
static __device__ __forceinline__ void cpa16(uint32_t dst, const void* src) {
    asm volatile("cp.async.cg.shared.global [%0], [%1], 16;" :: "r"(dst), "l"(src) : "memory");
}
static __device__ __forceinline__ void ldm4(uint32_t& r0, uint32_t& r1, uint32_t& r2,
                                            uint32_t& r3, uint32_t addr) {
    asm volatile("ldmatrix.sync.aligned.m8n8.x4.shared.b16 {%0,%1,%2,%3}, [%4];"
                 : "=r"(r0), "=r"(r1), "=r"(r2), "=r"(r3) : "r"(addr));
}
#define MMA16816(d, a, b) \
    asm volatile("mma.sync.aligned.m16n8k16.row.col.f32.bf16.bf16.f32 " \
        "{%0,%1,%2,%3}, {%4,%5,%6,%7}, {%8,%9}, {%0,%1,%2,%3};" \
        : "+f"((d)[0]), "+f"((d)[1]), "+f"((d)[2]), "+f"((d)[3]) \
        : "r"((a)[0]), "r"((a)[1]), "r"((a)[2]), "r"((a)[3]), "r"((b)[0]), "r"((b)[1]))

// ---------------- tensor-core split-bf16 GEMM ----------------
// 128x128 CTA tile, 128 threads, 2x2 warp grid, 64x64 warp tile.
// 3-stage cp.async pipeline, 2 CTA/SM. 3 mma passes (hh, hl, lh).
// OMODE: 0 = store fp32, 1 = accumulate fp32, 2 = store split bf16.
template<int OMODE>
__global__ void __launch_bounds__(128, 2) tgemm_k(
    const __nv_bfloat16* __restrict__ Ah, const __nv_bfloat16* __restrict__ Al,
    const __nv_bfloat16* __restrict__ Bh, const __nv_bfloat16* __restrict__ Bl,
    float* __restrict__ C, __nv_bfloat16* __restrict__ Ch, __nv_bfloat16* __restrict__ Cl,
    int M, int N, int K)
{
    extern __shared__ char smem[];
    uint32_t sb = smem_u32(smem);
    int tid = threadIdx.x, lane = tid & 31, wid = tid >> 5;
    int wm = wid & 1, wn = wid >> 1;      // 2 x 2 warp grid
    int brow = blockIdx.y << 7, bcol = blockIdx.x << 7;

    const __nv_bfloat16* src0 = Ah + (size_t)brow * K;
    const __nv_bfloat16* src1 = Al + (size_t)brow * K;
    const __nv_bfloat16* src2 = Bh + (size_t)bcol * K;
    const __nv_bfloat16* src3 = Bl + (size_t)bcol * K;

    float d[4][8][4];
#pragma unroll
    for (int mi = 0; mi < 4; mi++)
#pragma unroll
        for (int ni = 0; ni < 8; ni++)
#pragma unroll
            for (int q = 0; q < 4; q++) d[mi][ni][q] = 0.f;

    const int nch = K >> 5;

    auto load_stage = [&](uint32_t stb, int k0) {
#pragma unroll
        for (int j = 0; j < 4; j++) {
            int u = tid + (j << 7);
            int row = u >> 2, un = u & 3;
            uint32_t doff = SWZ64((uint32_t)(row * 64 + un * 16));
            size_t goff = (size_t)row * K + k0 + un * 8;
            cpa16(stb +     0 + doff, src0 + goff);
            cpa16(stb +  8192 + doff, src1 + goff);
            cpa16(stb + 16384 + doff, src2 + goff);
            cpa16(stb + 24576 + doff, src3 + goff);
        }
        asm volatile("cp.async.commit_group;" ::: "memory");
    };

    load_stage(sb, 0);
    if (nch > 1) load_stage(sb + 32768, 32);

    int g = lane >> 3, r = lane & 7;
    for (int i = 0; i < nch; i++) {
        if (i + 1 < nch) { asm volatile("cp.async.wait_group 1;" ::: "memory"); }
        else             { asm volatile("cp.async.wait_group 0;" ::: "memory"); }
        __syncthreads();
        if (i + 2 < nch) {
            int s = (i + 2) % 3;
            load_stage(sb + (uint32_t)(s * 32768), (i + 2) << 5);
        }
        uint32_t stb = sb + (uint32_t)((i % 3) * 32768);

#pragma unroll
        for (int ks = 0; ks < 2; ks++) {
            uint32_t ah[4][4], al[4][4], bh[8][2], bl[8][2];
#pragma unroll
            for (int mi = 0; mi < 4; mi++) {
                int row = wm * 64 + mi * 16 + (g & 1) * 8 + r;
                int colb = ks * 32 + (g >> 1) * 16;
                uint32_t off = SWZ64((uint32_t)(row * 64 + colb));
                ldm4(ah[mi][0], ah[mi][1], ah[mi][2], ah[mi][3], stb + off);
                ldm4(al[mi][0], al[mi][1], al[mi][2], al[mi][3], stb + 8192 + off);
            }
#pragma unroll
            for (int n2 = 0; n2 < 4; n2++) {
                int rown = wn * 64 + n2 * 16 + (g >> 1) * 8 + r;
                int colb = ks * 32 + (g & 1) * 16;
                uint32_t off = SWZ64((uint32_t)(rown * 64 + colb));
                ldm4(bh[2*n2][0], bh[2*n2][1], bh[2*n2+1][0], bh[2*n2+1][1], stb + 16384 + off);
                ldm4(bl[2*n2][0], bl[2*n2][1], bl[2*n2+1][0], bl[2*n2+1][1], stb + 24576 + off);
            }
#pragma unroll
            for (int mi = 0; mi < 4; mi++)
#pragma unroll
                for (int ni = 0; ni < 8; ni++) MMA16816(d[mi][ni], ah[mi], bh[ni]);
#pragma unroll
            for (int mi = 0; mi < 4; mi++)
#pragma unroll
                for (int ni = 0; ni < 8; ni++) MMA16816(d[mi][ni], ah[mi], bl[ni]);
#pragma unroll
            for (int mi = 0; mi < 4; mi++)
#pragma unroll
                for (int ni = 0; ni < 8; ni++) MMA16816(d[mi][ni], al[mi], bh[ni]);
        }
    }

    // epilogue
#pragma unroll
    for (int mi = 0; mi < 4; mi++)
#pragma unroll
        for (int ni = 0; ni < 8; ni++) {
            int row = brow + wm * 64 + mi * 16 + (lane >> 2);
            int col = bcol + wn * 64 + ni * 8 + 2 * (lane & 3);
            if (OMODE == 2) {
                __nv_bfloat16 h0, h1, l0, l1;
                bsplit(d[mi][ni][0], h0, l0); bsplit(d[mi][ni][1], h1, l1);
                *(__nv_bfloat162*)(Ch + (size_t)row * N + col) = __nv_bfloat162(h0, h1);
                *(__nv_bfloat162*)(Cl + (size_t)row * N + col) = __nv_bfloat162(l0, l1);
                bsplit(d[mi][ni][2], h0, l0); bsplit(d[mi][ni][3], h1, l1);
                *(__nv_bfloat162*)(Ch + (size_t)(row + 8) * N + col) = __nv_bfloat162(h0, h1);
                *(__nv_bfloat162*)(Cl + (size_t)(row + 8) * N + col) = __nv_bfloat162(l0, l1);
            } else {
                float* p0 = C + (size_t)row * N + col;
                float* p1 = C + (size_t)(row + 8) * N + col;
                float2 v0 = make_float2(d[mi][ni][0], d[mi][ni][1]);
                float2 v1 = make_float2(d[mi][ni][2], d[mi][ni][3]);
                if (OMODE == 1) {
                    float2 o0 = *(const float2*)p0, o1 = *(const float2*)p1;
                    v0.x += o0.x; v0.y += o0.y; v1.x += o1.x; v1.y += o1.y;
                }
                *(float2*)p0 = v0;
                *(float2*)p1 = v1;
            }
        }
}

// ---------------- fused weight split: all 11 tensors, one launch ----------------
struct WSrc { const float* p[11]; };
__global__ void wsplit_all_k(WSrc ws, __nv_bfloat16* __restrict__ hi,
                             __nv_bfloat16* __restrict__ lo) {
    const unsigned char segOf[27] = {0,1,2,3,4,5,6, 7,7,7,7,7,7, 8,8, 9,9,9,9,9,9,9,9, 10,10,10,10};
    const unsigned char locOf[27] = {0,0,0,0,0,0,0, 0,1,2,3,4,5, 0,1, 0,1,2,3,4,5,6,7, 0,1,2,3};
    int unit = blockIdx.y;
    const float4* src = (const float4*)ws.p[segOf[unit]] + (size_t)locOf[unit] * (MB1 >> 2);
    __nv_bfloat162* H  = (__nv_bfloat162*)(hi + (size_t)unit * MB1);
    __nv_bfloat162* Lo = (__nv_bfloat162*)(lo + (size_t)unit * MB1);
    for (int i = blockIdx.x * blockDim.x + threadIdx.x; i < (int)(MB1 >> 2);
         i += gridDim.x * blockDim.x) {
        float4 v = src[i];
        __nv_bfloat16 h0, h1, h2, h3, l0, l1, l2, l3;
        bsplit(v.x, h0, l0); bsplit(v.y, h1, l1);
        bsplit(v.z, h2, l2); bsplit(v.w, h3, l3);
        H[2 * i]      = __nv_bfloat162(h0, h1);
        H[2 * i + 1]  = __nv_bfloat162(h2, h3);
        Lo[2 * i]     = __nv_bfloat162(l0, l1);
        Lo[2 * i + 1] = __nv_bfloat162(l2, l3);
    }
}

// ---------------- one-time inv_freq table ----------------
__global__ void init_invf_k() {
    int j = threadIdx.x;
    if (j < 64) {
        double invf_d = exp(-(double)j * (9.210340371976184 / 64.0));
        g_invf[j] = (float)invf_d;
    }
}

// ---------------- rmsnorm -> split bf16 ----------------
__global__ void rmsnorm_k(const float* __restrict__ in, const float* __restrict__ w,
                          __nv_bfloat16* __restrict__ oh, __nv_bfloat16* __restrict__ ol,
                          int gsize, int gstride, int goff) {
    __shared__ float red[32];
    int r = blockIdx.x;
    int inrow = (r / gsize) * gstride + goff + (r % gsize);
    const float* x = in + (size_t)inrow * 1024;
    float v[4]; float ss = 0.f;
#pragma unroll
    for (int i = 0; i < 4; i++) { v[i] = x[threadIdx.x + i * 256]; ss += v[i] * v[i]; }
    ss = blk_sum(ss, red);
    float sc = rsqrtf(ss * (1.f / 1024.f) + EPS_);
#pragma unroll
    for (int i = 0; i < 4; i++) {
        int idx = threadIdx.x + i * 256;
        float f = v[i] * sc * w[idx];
        __nv_bfloat16 h, l; bsplit(f, h, l);
        size_t o = (size_t)r * 1024 + idx;
        oh[o] = h; ol[o] = l;
    }
}

// ---------------- fused shifted-y + rmsnorm (refresh) -> split ----------------
__global__ void yfrms_k(const float* __restrict__ y, const int* __restrict__ begin,
                        const float* __restrict__ pad_emb, const float* __restrict__ w,
                        __nv_bfloat16* __restrict__ oh, __nv_bfloat16* __restrict__ ol) {
    __shared__ float red[32];
    int r = blockIdx.x;
    int b = r >> 9, t = r & 511;
    int n = t & 15, l = t >> 4;
    bool cond = (n == 0) && (begin[b * 32 + l] != 0);
    const float* x = cond ? pad_emb : (y + ((size_t)b * 512 + ((t + 511) & 511)) * 1024);
    float v[4]; float ss = 0.f;
#pragma unroll
    for (int i = 0; i < 4; i++) { v[i] = x[threadIdx.x + i * 256]; ss += v[i] * v[i]; }
    ss = blk_sum(ss, red);
    float sc = rsqrtf(ss * (1.f / 1024.f) + EPS_);
#pragma unroll
    for (int i = 0; i < 4; i++) {
        int idx = threadIdx.x + i * 256;
        float f = v[i] * sc * w[idx];
        __nv_bfloat16 h, lo; bsplit(f, h, lo);
        size_t o = (size_t)r * 1024 + idx;
        oh[o] = h; ol[o] = lo;
    }
}

// ---------------- l2norm + rotary on q,k in-place ----------------
__global__ void qk_rope_k(float* __restrict__ qkv) {
    __shared__ float red[32];
    __shared__ float sh[128];
    int s = blockIdx.x, hk = blockIdx.y, b = blockIdx.z;
    int h = hk >> 1;
    int off = (hk & 1) ? 1024 : 0;
    float* p = qkv + ((size_t)(b * 2048 + s)) * 3072 + off + h * 128;
    int tid = threadIdx.x;
    float v = p[tid];
    float ss = blk_sum(v * v, red);
    float scl = 1.f / fmaxf(sqrtf(ss), EPS_);
    sh[tid] = v * scl;
    __syncthreads();
    int j = tid & 63;
    float ang = (float)s * g_invf[j];
    float c = cosf(ang), sn = sinf(ang);
    float x1 = sh[j], x2 = sh[j + 64];
    p[tid] = (tid < 64) ? (x1 * c + x2 * sn) : (-x1 * sn + x2 * c);
}

// ---------------- attention v2: CTA per (b, role*8+h, qb) ----------------
__global__ void __launch_bounds__(128) attn2_k(const float* __restrict__ qkv,
                                               const int* __restrict__ doc,
                                               __nv_bfloat16* __restrict__ oh,
                                               __nv_bfloat16* __restrict__ ol) {
    __shared__ __align__(16) float sbuf[8752];
    int qb = blockIdx.x;
    int role = blockIdx.y >> 3;
    int h = blockIdx.y & 7;
    int b = blockIdx.z;
    int t = threadIdx.x;
    int lane = t & 31, w = t >> 5;
    const float* base = qkv + (size_t)b * 2048 * 3072;
    const float* Qb = base + (size_t)h * 128;
    const float* Kb = base + 1024 + (size_t)h * 128;
    const float* Vb = base + 2048 + (size_t)h * 128;
    const float scale = 0.088388347648318447f;

    if (role == 0) {
        float (*qs)[132] = (float(*)[132])sbuf;
        float (*ps)[49]  = (float(*)[49])(sbuf + 6336);
        float* inv = sbuf + 6336 + 2352;
        for (int u = t; u < 48 * 32; u += 128) {
            int rr = u >> 5, c = u & 31;
            *(float4*)&qs[rr][c * 4] =
                *(const float4*)&Qb[(size_t)(qb * 64 + rr) * 3072 + c * 4];
        }
        __syncthreads();
        int tq = t & 15, tk = t >> 4;
        float acc[3][6];
#pragma unroll
        for (int j = 0; j < 3; j++)
#pragma unroll
            for (int i = 0; i < 6; i++) acc[j][i] = 0.f;
#pragma unroll
        for (int dc = 0; dc < 8; dc++) {
            float4 qv[3][4];
#pragma unroll
            for (int j = 0; j < 3; j++)
#pragma unroll
                for (int x = 0; x < 4; x++)
                    qv[j][x] = *(float4*)&qs[tq + 16 * j][dc * 16 + x * 4];
#pragma unroll
            for (int i = 0; i < 6; i++) {
                int k = tk + 8 * i;
                const float4* Kr = (const float4*)&Kb[(size_t)(qb * 64 + k) * 3072 + dc * 16];
#pragma unroll
                for (int x = 0; x < 4; x++) {
                    float4 kv = Kr[x];
#pragma unroll
                    for (int j = 0; j < 3; j++)
                        acc[j][i] += qv[j][x].x * kv.x + qv[j][x].y * kv.y
                                   + qv[j][x].z * kv.z + qv[j][x].w * kv.w;
                }
            }
        }
#pragma unroll
        for (int j = 0; j < 3; j++)
#pragma unroll
            for (int i = 0; i < 6; i++)
                ps[tq + 16 * j][tk + 8 * i] = acc[j][i] * scale;
        __syncthreads();
        for (int j = 0; j < 12; j++) {
            int q = w * 12 + j;
            float v0 = ps[q][lane];
            float v1 = (lane < 16) ? ps[q][lane + 32] : -INFINITY;
            float m = fmaxf(v0, v1);
#pragma unroll
            for (int o = 16; o; o >>= 1) m = fmaxf(m, __shfl_xor_sync(0xffffffffu, m, o));
            float p0 = expf(v0 - m);
            float p1 = (lane < 16) ? expf(v1 - m) : 0.f;
            float s = p0 + p1;
#pragma unroll
            for (int o = 16; o; o >>= 1) s += __shfl_xor_sync(0xffffffffu, s, o);
            ps[q][lane] = p0;
            if (lane < 16) ps[q][lane + 32] = p1;
            if (lane == 0) inv[q] = 1.f / s;
        }
        __syncthreads();
        int tq2 = t & 15, td = t >> 4;
        float a2[3][16];
#pragma unroll
        for (int j = 0; j < 3; j++)
#pragma unroll
            for (int x = 0; x < 16; x++) a2[j][x] = 0.f;
        for (int k = 0; k < 48; k++) {
            const float4* Vr = (const float4*)&Vb[(size_t)(qb * 64 + k) * 3072 + td * 16];
            float4 v[4];
#pragma unroll
            for (int x = 0; x < 4; x++) v[x] = Vr[x];
#pragma unroll
            for (int j = 0; j < 3; j++) {
                float p = ps[tq2 + 16 * j][k];
#pragma unroll
                for (int x = 0; x < 4; x++) {
                    a2[j][x * 4 + 0] += p * v[x].x; a2[j][x * 4 + 1] += p * v[x].y;
                    a2[j][x * 4 + 2] += p * v[x].z; a2[j][x * 4 + 3] += p * v[x].w;
                }
            }
        }
#pragma unroll
        for (int j = 0; j < 3; j++) {
            int q = tq2 + 16 * j;
            float iv = inv[q];
            size_t o = ((size_t)(b * 2048 + qb * 64 + q)) * 1024 + h * 128 + td * 16;
#pragma unroll
            for (int x = 0; x < 16; x++) {
                __nv_bfloat16 fh, fl; bsplit(a2[j][x] * iv, fh, fl);
                oh[o + x] = fh; ol[o + x] = fl;
            }
        }
    } else {
        float (*qs)[132] = (float(*)[132])sbuf;
        float (*ps)[324] = (float(*)[324])(sbuf + 2112);
        int*   kls  = (int*)(sbuf + 2112 + 5184);
        int*   docs = kls + 320;
        float* inv  = (float*)(docs + 32);
        int npb = min(16, qb), np = npb * 16, NK = np + 64;
        if (t < 32) docs[t] = doc[b * 32 + t];
        for (int i = t; i < NK; i += 128) {
            int k;
            if (i < np) { int kb = qb - npb + (i >> 4); k = kb * 64 + 48 + (i & 15); }
            else          k = qb * 64 + (i - np);
            kls[i] = k;
        }
        for (int u = t; u < 16 * 32; u += 128) {
            int rr = u >> 5, c = u & 31;
            *(float4*)&qs[rr][c * 4] =
                *(const float4*)&Qb[(size_t)(qb * 64 + 48 + rr) * 3072 + c * 4];
        }
        __syncthreads();
        int tq = t & 15, tk = t >> 4;
#pragma unroll
        for (int dc = 0; dc < 4; dc++) {
            float4 qv[8];
#pragma unroll
            for (int x = 0; x < 8; x++) qv[x] = *(float4*)&qs[tq][dc * 32 + x * 4];
            for (int ki = tk; ki < NK; ki += 8) {
                const float4* Kr = (const float4*)&Kb[(size_t)kls[ki] * 3072 + dc * 32];
                float a = 0.f;
#pragma unroll
                for (int x = 0; x < 8; x++) {
                    float4 kv = Kr[x];
                    a += qv[x].x * kv.x + qv[x].y * kv.y + qv[x].z * kv.z + qv[x].w * kv.w;
                }
                if (dc == 0) ps[tq][ki] = a; else ps[tq][ki] += a;
            }
        }
        {
            int docq = docs[qb];
            int docp = docs[qb > 0 ? qb - 1 : 0];
            int q = qb * 64 + 48 + tq;
            int posq = (48 + tq) + qb * 16;
            for (int ki = tk; ki < NK; ki += 8) {
                int k = kls[ki];
                int kb = k >> 6, kr = k & 63;
                bool newk = kr >= 48;
                int posk = kr + kb * 16;
                bool nn = newk && (q >= k) && (posq < posk + 256) && (docq == docs[kb]);
                bool ao = (!newk) && (kb == qb) && (docq == docp);
                ps[tq][ki] = (nn || ao) ? ps[tq][ki] * scale : -INFINITY;
            }
        }
        __syncthreads();
        for (int j = 0; j < 4; j++) {
            int q = w * 4 + j;
            float m = -INFINITY;
            for (int i = lane; i < NK; i += 32) m = fmaxf(m, ps[q][i]);
#pragma unroll
            for (int o = 16; o; o >>= 1) m = fmaxf(m, __shfl_xor_sync(0xffffffffu, m, o));
            float s = 0.f;
            for (int i = lane; i < NK; i += 32) {
                float v = ps[q][i];
                float p = (v > -INFINITY) ? expf(v - m) : 0.f;
                ps[q][i] = p;
                s += p;
            }
#pragma unroll
            for (int o = 16; o; o >>= 1) s += __shfl_xor_sync(0xffffffffu, s, o);
            if (lane == 0) inv[q] = 1.f / s;
        }
        __syncthreads();
        int tq3 = t >> 3, td = t & 7;
        float a2[16];
#pragma unroll
        for (int x = 0; x < 16; x++) a2[x] = 0.f;
        for (int ki = 0; ki < NK; ki++) {
            float p = ps[tq3][ki];
            if (p != 0.f) {
                const float4* Vr = (const float4*)&Vb[(size_t)kls[ki] * 3072 + td * 16];
#pragma unroll
                for (int x = 0; x < 4; x++) {
                    float4 v = Vr[x];
                    a2[x * 4 + 0] += p * v.x; a2[x * 4 + 1] += p * v.y;
                    a2[x * 4 + 2] += p * v.z; a2[x * 4 + 3] += p * v.w;
                }
            }
        }
        float iv = inv[tq3];
        size_t o = ((size_t)(b * 2048 + qb * 64 + 48 + tq3)) * 1024 + h * 128 + td * 16;
#pragma unroll
        for (int x = 0; x < 16; x++) {
            __nv_bfloat16 fh, fl; bsplit(a2[x] * iv, fh, fl);
            oh[o + x] = fh; ol[o + x] = fl;
        }
    }
}

// ---------------- silu-gate from split-bf16 up -> split bf16 gate ----------------
__global__ void silu_gate_k(const __nv_bfloat16* __restrict__ uph,
                            const __nv_bfloat16* __restrict__ upl,
                            __nv_bfloat16* __restrict__ gh, __nv_bfloat16* __restrict__ gl) {
    int i = blockIdx.x * 256 + threadIdx.x;
    if (i >= (BP_ * S_ * FH_) / 4) return;
    int r = i >> 9, c4 = i & 511;
    size_t oa = (size_t)r * 4096 + c4 * 4;
    __nv_bfloat162 ah0 = *(const __nv_bfloat162*)(uph + oa);
    __nv_bfloat162 ah1 = *(const __nv_bfloat162*)(uph + oa + 2);
    __nv_bfloat162 al0 = *(const __nv_bfloat162*)(upl + oa);
    __nv_bfloat162 al1 = *(const __nv_bfloat162*)(upl + oa + 2);
    __nv_bfloat162 bh0 = *(const __nv_bfloat162*)(uph + oa + 2048);
    __nv_bfloat162 bh1 = *(const __nv_bfloat162*)(uph + oa + 2050);
    __nv_bfloat162 bl0 = *(const __nv_bfloat162*)(upl + oa + 2048);
    __nv_bfloat162 bl1 = *(const __nv_bfloat162*)(upl + oa + 2050);
    float a[4], bb[4];
    a[0] = __bfloat162float(ah0.x) + __bfloat162float(al0.x);
    a[1] = __bfloat162float(ah0.y) + __bfloat162float(al0.y);
    a[2] = __bfloat162float(ah1.x) + __bfloat162float(al1.x);
    a[3] = __bfloat162float(ah1.y) + __bfloat162float(al1.y);
    bb[0] = __bfloat162float(bh0.x) + __bfloat162float(bl0.x);
    bb[1] = __bfloat162float(bh0.y) + __bfloat162float(bl0.y);
    bb[2] = __bfloat162float(bh1.x) + __bfloat162float(bl1.x);
    bb[3] = __bfloat162float(bh1.y) + __bfloat162float(bl1.y);
    __nv_bfloat16 h[4], l[4];
#pragma unroll
    for (int j = 0; j < 4; j++) {
        float f = (a[j] / (1.f + expf(-a[j]))) * bb[j];
        bsplit(f, h[j], l[j]);
    }
    size_t og = (size_t)r * 2048 + c4 * 4;
    *(__nv_bfloat162*)(gh + og)     = __nv_bfloat162(h[0], h[1]);
    *(__nv_bfloat162*)(gh + og + 2) = __nv_bfloat162(h[2], h[3]);
    *(__nv_bfloat162*)(gl + og)     = __nv_bfloat162(l[0], l[1]);
    *(__nv_bfloat162*)(gl + og + 2) = __nv_bfloat162(l[2], l[3]);
}

// ---------------- assemble x from x_old / x_new ----------------
__global__ void assemble_k(float* __restrict__ x, const float* __restrict__ xold,
                           const float* __restrict__ xnew) {
    int idx = blockIdx.x * blockDim.x + threadIdx.x;
    if (idx >= BP_ * S_ * 256) return;
    int d4 = idx & 255;
    int gr = idx >> 8;
    int b = gr >> 11, s = gr & 2047;
    int l = s >> 6, rr = s & 63;
    float4 v;
    if (rr < 48)
        v = ((const float4*)xold)[((size_t)((b * 32 + l) * 48 + rr)) * 256 + d4];
    else
        v = ((const float4*)xnew)[((size_t)((b * 32 + l) * 16 + (rr - 48))) * 256 + d4];
    ((float4*)x)[idx] = v;
}

// ---------------- extract y = x[:,:,M:,:] (fp32 + split) ----------------
__global__ void extract_y_k(const float* __restrict__ x, float* __restrict__ y,
                            __nv_bfloat16* __restrict__ yh, __nv_bfloat16* __restrict__ yl) {
    int idx = blockIdx.x * blockDim.x + threadIdx.x;
    if (idx >= BP_ * 512 * 256) return;
    int d4 = idx & 255;
    int r = idx >> 8;
    int b = r >> 9, t = r & 511;
    int l = t >> 4, n = t & 15;
    int xr = b * 2048 + l * 64 + 48 + n;
    float4 v = ((const float4*)x)[(size_t)xr * 256 + d4];
    ((float4*)y)[idx] = v;
    __nv_bfloat16 h0, h1, h2, h3, l0, l1, l2, l3;
    bsplit(v.x, h0, l0); bsplit(v.y, h1, l1); bsplit(v.z, h2, l2); bsplit(v.w, h3, l3);
    ((__nv_bfloat162*)yh)[2 * idx]     = __nv_bfloat162(h0, h1);
    ((__nv_bfloat162*)yh)[2 * idx + 1] = __nv_bfloat162(h2, h3);
    ((__nv_bfloat162*)yl)[2 * idx]     = __nv_bfloat162(l0, l1);
    ((__nv_bfloat162*)yl)[2 * idx + 1] = __nv_bfloat162(l2, l3);
}

// ---------------- host helpers ----------------
#define TG_SMEM (3 * 32768)

static void tgemm(const __nv_bfloat16* Ah, const __nv_bfloat16* Al,
                  const __nv_bfloat16* Bh, const __nv_bfloat16* Bl,
                  float* C, __nv_bfloat16* Ch, __nv_bfloat16* Cl,
                  int M, int N, int K, int mode) {
    dim3 grid(N >> 7, M >> 7);
    if (mode == 0) {
        cudaFuncSetAttribute(tgemm_k<0>, cudaFuncAttributeMaxDynamicSharedMemorySize, TG_SMEM);
        tgemm_k<0><<<grid, 128, TG_SMEM>>>(Ah, Al, Bh, Bl, C, Ch, Cl, M, N, K);
    } else if (mode == 1) {
        cudaFuncSetAttribute(tgemm_k<1>, cudaFuncAttributeMaxDynamicSharedMemorySize, TG_SMEM);
        tgemm_k<1><<<grid, 128, TG_SMEM>>>(Ah, Al, Bh, Bl, C, Ch, Cl, M, N, K);
    } else {
        cudaFuncSetAttribute(tgemm_k<2>, cudaFuncAttributeMaxDynamicSharedMemorySize, TG_SMEM);
        tgemm_k<2><<<grid, 128, TG_SMEM>>>(Ah, Al, Bh, Bl, C, Ch, Cl, M, N, K);
    }
}

extern "C" void kernel_launch(void* const* d_in, const int* in_sizes, int n_in,
                              void* d_out, int out_size) {
    (void)in_sizes; (void)n_in; (void)out_size;
    const float* x_input     = (const float*)d_in[0];
    const float* x_ar        = (const float*)d_in[1];
    const int*   doc         = (const int*)d_in[2];
    const int*   begin       = (const int*)d_in[3];
    const float* old_norm_w  = (const float*)d_in[4];
    const float* new_norm_w  = (const float*)d_in[5];
    const float* pad_emb     = (const float*)d_in[12];
    const float* attn_norm_w = (const float*)d_in[14];
    const float* ffn_norm_w  = (const float*)d_in[15];
    float* out = (float*)d_out;

    float *x, *qkv, *xold, *xnew, *y;
    __nv_bfloat16 *hh, *hl, *ah, *al, *uph, *upl, *gh, *gl;
    __nv_bfloat16 *xarnh, *xarnl, *xdenh, *xdenl, *y2h, *y2l, *yh, *yl, *whi, *wlo;
    cudaGetSymbolAddress((void**)&x,    g_x);
    cudaGetSymbolAddress((void**)&qkv,  g_qkv);
    cudaGetSymbolAddress((void**)&xold, g_xold);
    cudaGetSymbolAddress((void**)&xnew, g_xnew);
    cudaGetSymbolAddress((void**)&y,    g_y);
    cudaGetSymbolAddress((void**)&hh,   g_hh);
    cudaGetSymbolAddress((void**)&hl,   g_hl);
    cudaGetSymbolAddress((void**)&ah,   g_ah);
    cudaGetSymbolAddress((void**)&al,   g_al);
    cudaGetSymbolAddress((void**)&uph,  g_uph);
    cudaGetSymbolAddress((void**)&upl,  g_upl);
    cudaGetSymbolAddress((void**)&gh,   g_gh);
    cudaGetSymbolAddress((void**)&gl,   g_gl);
    cudaGetSymbolAddress((void**)&xarnh, g_xarnh);
    cudaGetSymbolAddress((void**)&xarnl, g_xarnl);
    cudaGetSymbolAddress((void**)&xdenh, g_xdenh);
    cudaGetSymbolAddress((void**)&xdenl, g_xdenl);
    cudaGetSymbolAddress((void**)&y2h,  g_y2h);
    cudaGetSymbolAddress((void**)&y2l,  g_y2l);
    cudaGetSymbolAddress((void**)&yh,   g_yh);
    cudaGetSymbolAddress((void**)&yl,   g_yl);
    cudaGetSymbolAddress((void**)&whi,  g_whi);
    cudaGetSymbolAddress((void**)&wlo,  g_wlo);

    init_invf_k<<<1, 64>>>();

    WSrc ws;
    ws.p[0]  = (const float*)d_in[6];
    ws.p[1]  = (const float*)d_in[7];
    ws.p[2]  = (const float*)d_in[8];
    ws.p[3]  = (const float*)d_in[9];
    ws.p[4]  = (const float*)d_in[10];
    ws.p[5]  = (const float*)d_in[11];
    ws.p[6]  = (const float*)d_in[13];
    ws.p[7]  = (const float*)d_in[16];
    ws.p[8]  = (const float*)d_in[17];
    ws.p[9]  = (const float*)d_in[18];
    ws.p[10] = (const float*)d_in[19];
    wsplit_all_k<<<dim3(64, 27), 256>>>(ws, whi, wlo);

    // input projections
    rmsnorm_k<<<3072, 256>>>(x_input, old_norm_w, hh, hl, 48, 64, 0);
    tgemm(hh, hl, whi + (size_t)OFF_WOLD * MB1, wlo + (size_t)OFF_WOLD * MB1,
          xold, 0, 0, 3072, 1024, 1024, 0);
    rmsnorm_k<<<1024, 256>>>(x_ar,    new_norm_w, xarnh, xarnl, 16, 16, 0);
    rmsnorm_k<<<1024, 256>>>(x_input, new_norm_w, xdenh, xdenl, 16, 64, 48);
    tgemm(xarnh, xarnl, whi + (size_t)OFF_WAR * MB1, wlo + (size_t)OFF_WAR * MB1,
          xnew, 0, 0, 1024, 1024, 1024, 0);
    tgemm(xdenh, xdenl, whi + (size_t)OFF_WDE * MB1, wlo + (size_t)OFF_WDE * MB1,
          xnew, 0, 0, 1024, 1024, 1024, 1);
    assemble_k<<<(BP_ * S_ * 256 + 255) / 256, 256>>>(x, xold, xnew);

    for (int it = 0; it < 2; it++) {
        for (int li = 0; li < 2; li++) {
            const __nv_bfloat16* wq_h = whi + (size_t)(OFF_WQKV + 3 * li) * MB1;
            const __nv_bfloat16* wq_l = wlo + (size_t)(OFF_WQKV + 3 * li) * MB1;
            const __nv_bfloat16* wo_h = whi + (size_t)(OFF_WO + li) * MB1;
            const __nv_bfloat16* wo_l = wlo + (size_t)(OFF_WO + li) * MB1;
            const __nv_bfloat16* wu_h = whi + (size_t)(OFF_WUP + 4 * li) * MB1;
            const __nv_bfloat16* wu_l = wlo + (size_t)(OFF_WUP + 4 * li) * MB1;
            const __nv_bfloat16* wd_h = whi + (size_t)(OFF_WDOWN + 2 * li) * MB1;
            const __nv_bfloat16* wd_l = wlo + (size_t)(OFF_WDOWN + 2 * li) * MB1;

            rmsnorm_k<<<4096, 256>>>(x, attn_norm_w + li * 1024, hh, hl, 1, 1, 0);
            tgemm(hh, hl, wq_h, wq_l, qkv, 0, 0, 4096, 3072, 1024, 0);
            qk_rope_k<<<dim3(2048, 16, 2), 128>>>(qkv);
            attn2_k<<<dim3(32, 16, 2), 128>>>(qkv, doc, ah, al);
            tgemm(ah, al, wo_h, wo_l, x, 0, 0, 4096, 1024, 1024, 1);
            rmsnorm_k<<<4096, 256>>>(x, ffn_norm_w + li * 1024, hh, hl, 1, 1, 0);
            tgemm(hh, hl, wu_h, wu_l, 0, uph, upl, 4096, 4096, 1024, 2);
            silu_gate_k<<<(BP_ * S_ * FH_ / 4 + 255) / 256, 256>>>(uph, upl, gh, gl);
            tgemm(gh, gl, wd_h, wd_l, x, 0, 0, 4096, 1024, 2048, 1);
        }
        extract_y_k<<<(BP_ * 512 * 256 + 255) / 256, 256>>>(x, y, yh, yl);
        if (it == 0) {
            yfrms_k<<<1024, 256>>>(y, begin, pad_emb, new_norm_w, y2h, y2l);
            tgemm(xarnh, xarnl, whi + (size_t)OFF_WAR1 * MB1, wlo + (size_t)OFF_WAR1 * MB1,
                  xnew, 0, 0, 1024, 1024, 1024, 0);
            tgemm(y2h, y2l, whi + (size_t)OFF_WY1 * MB1, wlo + (size_t)OFF_WY1 * MB1,
                  xnew, 0, 0, 1024, 1024, 1024, 1);
            tgemm(xdenh, xdenl, whi + (size_t)OFF_WDE1 * MB1, wlo + (size_t)OFF_WDE1 * MB1,
                  xnew, 0, 0, 1024, 1024, 1024, 1);
            assemble_k<<<(BP_ * S_ * 256 + 255) / 256, 256>>>(x, xold, xnew);
        }
    }

    tgemm(yh, yl, whi + (size_t)OFF_WAGG * MB1, wlo + (size_t)OFF_WAGG * MB1,
          out, 0, 0, 1024, 1024, 1024, 0);
}

// round 10
// speedup vs baseline: 6.5325x; 1.0195x over previous
#include <cuda_runtime.h>
#include <cuda_bf16.h>
#include <math.h>
#include <stdint.h>

// ---------------- problem constants ----------------
#define BP_  2
#define L_   32
#define N_   16
#define O_   64
#define D_   1024
#define AD_  1024
#define HEAD_ 128
#define W_   256
#define FH_  2048
#define M_   48
#define E_   64
#define S_   2048
#define EPS_ 1e-5f
#define MB1 (1u<<20)

// ---------------- device scratch (allocation-free) ----------------
__device__ float g_x   [BP_ * S_ * AD_];
__device__ float g_qkv [BP_ * S_ * 3 * AD_];
__device__ float g_xold[BP_ * L_ * M_ * AD_];
__device__ float g_xnew[BP_ * L_ * N_ * AD_];
__device__ float g_y   [BP_ * L_ * N_ * AD_];
__device__ float g_invf[64];

// bf16 split activation buffers
__device__ __nv_bfloat16 g_hh[BP_ * S_ * AD_],  g_hl[BP_ * S_ * AD_];
__device__ __nv_bfloat16 g_ah[BP_ * S_ * AD_],  g_al[BP_ * S_ * AD_];
__device__ __nv_bfloat16 g_uph[BP_ * S_ * 2 * FH_], g_upl[BP_ * S_ * 2 * FH_];
__device__ __nv_bfloat16 g_gh[BP_ * S_ * FH_],  g_gl[BP_ * S_ * FH_];
__device__ __nv_bfloat16 g_ach[3u * MB1], g_acl[3u * MB1];   // [xarn|xden|y2] rows x 3072
__device__ __nv_bfloat16 g_yh[MB1],    g_yl[MB1];
// bf16 split weights: 27 MB1 units (22 contiguous + packed wp2 at 22, wp3 at 24)
__device__ __nv_bfloat16 g_whi[27u * MB1], g_wlo[27u * MB1];

#define OFF_WOLD  0
#define OFF_WAGG  1
#define OFF_WQKV  2   /* 3 per layer */
#define OFF_WO    8
#define OFF_WUP   10  /* 4 per layer */
#define OFF_WDOWN 18  /* 2 per layer */
#define OFF_WP2   22  /* [w_ar|w_de]   rows x 2048 */
#define OFF_WP3   24  /* [w_ar1|w_de1|w_y1] rows x 3072 */

// ---------------- small helpers ----------------
__device__ __forceinline__ void bsplit(float f, __nv_bfloat16& h, __nv_bfloat16& l) {
    h = __float2bfloat16(f);
    l = __float2bfloat16(f - __bfloat162float(h));
}

__device__ __forceinline__ float blk_sum(float v, float* red) {
    int lane = threadIdx.x & 31, w = threadIdx.x >> 5;
#pragma unroll
    for (int o = 16; o; o >>= 1) v += __shfl_xor_sync(0xffffffffu, v, o);
    if (lane == 0) red[w] = v;
    __syncthreads();
    int nw = (blockDim.x + 31) >> 5;
    if (threadIdx.x < 32) {
        float r = (threadIdx.x < nw) ? red[threadIdx.x] : 0.f;
#pragma unroll
        for (int o = 16; o; o >>= 1) r += __shfl_xor_sync(0xffffffffu, r, o);
        if (lane == 0) red[0] = r;
    }
    __syncthreads();
    float r = red[0];
    __syncthreads();
    return r;
}

// ---------------- PTX helpers (compute_103-legal) ----------------
#define SWZ64(o) ((o) ^ (((o) >> 3) & 0x30))

static __device__ __forceinline__ uint32_t smem_u32(const void* p) {
    uint32_t a;
    asm("{ .reg .u64 t; cvta.to.shared.u64 t, %1; cvt.u32.u64 %0, t; }" : "=r"(a) : "l"(p));
    return a;
}
static __device__ __forceinline__ void cpa16(uint32_t dst, const void* src) {
    asm volatile("cp.async.cg.shared.global [%0], [%1], 16;" :: "r"(dst), "l"(src) : "memory");
}
static __device__ __forceinline__ void ldm4(uint32_t& r0, uint32_t& r1, uint32_t& r2,
                                            uint32_t& r3, uint32_t addr) {
    asm volatile("ldmatrix.sync.aligned.m8n8.x4.shared.b16 {%0,%1,%2,%3}, [%4];"
                 : "=r"(r0), "=r"(r1), "=r"(r2), "=r"(r3) : "r"(addr));
}
#define MMA16816(d, a, b) \
    asm volatile("mma.sync.aligned.m16n8k16.row.col.f32.bf16.bf16.f32 " \
        "{%0,%1,%2,%3}, {%4,%5,%6,%7}, {%8,%9}, {%0,%1,%2,%3};" \
        : "+f"((d)[0]), "+f"((d)[1]), "+f"((d)[2]), "+f"((d)[3]) \
        : "r"((a)[0]), "r"((a)[1]), "r"((a)[2]), "r"((a)[3]), "r"((b)[0]), "r"((b)[1]))

// ---------------- tensor-core split-bf16 GEMM ----------------
// 128x128 CTA tile, 128 threads, 2x2 warp grid, 64x64 warp tile,
// 3-stage cp.async pipeline, 2 CTA/SM. Supports lda/ldb row strides.
// OMODE: 0 = store fp32, 1 = accumulate fp32, 2 = store split bf16.
template<int OMODE>
__global__ void __launch_bounds__(128, 2) tgemm_k(
    const __nv_bfloat16* __restrict__ Ah, const __nv_bfloat16* __restrict__ Al,
    const __nv_bfloat16* __restrict__ Bh, const __nv_bfloat16* __restrict__ Bl,
    float* __restrict__ C, __nv_bfloat16* __restrict__ Ch, __nv_bfloat16* __restrict__ Cl,
    int M, int N, int K, int lda, int ldb)
{
    extern __shared__ char smem[];
    uint32_t sb = smem_u32(smem);
    int tid = threadIdx.x, lane = tid & 31, wid = tid >> 5;
    int wm = wid & 1, wn = wid >> 1;
    int brow = blockIdx.y << 7, bcol = blockIdx.x << 7;

    const __nv_bfloat16* src0 = Ah + (size_t)brow * lda;
    const __nv_bfloat16* src1 = Al + (size_t)brow * lda;
    const __nv_bfloat16* src2 = Bh + (size_t)bcol * ldb;
    const __nv_bfloat16* src3 = Bl + (size_t)bcol * ldb;

    float d[4][8][4];
#pragma unroll
    for (int mi = 0; mi < 4; mi++)
#pragma unroll
        for (int ni = 0; ni < 8; ni++)
#pragma unroll
            for (int q = 0; q < 4; q++) d[mi][ni][q] = 0.f;

    const int nch = K >> 5;

    auto load_stage = [&](uint32_t stb, int k0) {
#pragma unroll
        for (int j = 0; j < 4; j++) {
            int u = tid + (j << 7);
            int row = u >> 2, un = u & 3;
            uint32_t doff = SWZ64((uint32_t)(row * 64 + un * 16));
            size_t ga = (size_t)row * lda + k0 + un * 8;
            size_t gb = (size_t)row * ldb + k0 + un * 8;
            cpa16(stb +     0 + doff, src0 + ga);
            cpa16(stb +  8192 + doff, src1 + ga);
            cpa16(stb + 16384 + doff, src2 + gb);
            cpa16(stb + 24576 + doff, src3 + gb);
        }
        asm volatile("cp.async.commit_group;" ::: "memory");
    };

    load_stage(sb, 0);
    if (nch > 1) load_stage(sb + 32768, 32);

    int g = lane >> 3, r = lane & 7;
    for (int i = 0; i < nch; i++) {
        if (i + 1 < nch) { asm volatile("cp.async.wait_group 1;" ::: "memory"); }
        else             { asm volatile("cp.async.wait_group 0;" ::: "memory"); }
        __syncthreads();
        if (i + 2 < nch) {
            int s = (i + 2) % 3;
            load_stage(sb + (uint32_t)(s * 32768), (i + 2) << 5);
        }
        uint32_t stb = sb + (uint32_t)((i % 3) * 32768);

#pragma unroll
        for (int ks = 0; ks < 2; ks++) {
            uint32_t ah[4][4], al[4][4], bh[8][2], bl[8][2];
#pragma unroll
            for (int mi = 0; mi < 4; mi++) {
                int row = wm * 64 + mi * 16 + (g & 1) * 8 + r;
                int colb = ks * 32 + (g >> 1) * 16;
                uint32_t off = SWZ64((uint32_t)(row * 64 + colb));
                ldm4(ah[mi][0], ah[mi][1], ah[mi][2], ah[mi][3], stb + off);
                ldm4(al[mi][0], al[mi][1], al[mi][2], al[mi][3], stb + 8192 + off);
            }
#pragma unroll
            for (int n2 = 0; n2 < 4; n2++) {
                int rown = wn * 64 + n2 * 16 + (g >> 1) * 8 + r;
                int colb = ks * 32 + (g & 1) * 16;
                uint32_t off = SWZ64((uint32_t)(rown * 64 + colb));
                ldm4(bh[2*n2][0], bh[2*n2][1], bh[2*n2+1][0], bh[2*n2+1][1], stb + 16384 + off);
                ldm4(bl[2*n2][0], bl[2*n2][1], bl[2*n2+1][0], bl[2*n2+1][1], stb + 24576 + off);
            }
#pragma unroll
            for (int mi = 0; mi < 4; mi++)
#pragma unroll
                for (int ni = 0; ni < 8; ni++) MMA16816(d[mi][ni], ah[mi], bh[ni]);
#pragma unroll
            for (int mi = 0; mi < 4; mi++)
#pragma unroll
                for (int ni = 0; ni < 8; ni++) MMA16816(d[mi][ni], ah[mi], bl[ni]);
#pragma unroll
            for (int mi = 0; mi < 4; mi++)
#pragma unroll
                for (int ni = 0; ni < 8; ni++) MMA16816(d[mi][ni], al[mi], bh[ni]);
        }
    }

    // epilogue
#pragma unroll
    for (int mi = 0; mi < 4; mi++)
#pragma unroll
        for (int ni = 0; ni < 8; ni++) {
            int row = brow + wm * 64 + mi * 16 + (lane >> 2);
            int col = bcol + wn * 64 + ni * 8 + 2 * (lane & 3);
            if (OMODE == 2) {
                __nv_bfloat16 h0, h1, l0, l1;
                bsplit(d[mi][ni][0], h0, l0); bsplit(d[mi][ni][1], h1, l1);
                *(__nv_bfloat162*)(Ch + (size_t)row * N + col) = __nv_bfloat162(h0, h1);
                *(__nv_bfloat162*)(Cl + (size_t)row * N + col) = __nv_bfloat162(l0, l1);
                bsplit(d[mi][ni][2], h0, l0); bsplit(d[mi][ni][3], h1, l1);
                *(__nv_bfloat162*)(Ch + (size_t)(row + 8) * N + col) = __nv_bfloat162(h0, h1);
                *(__nv_bfloat162*)(Cl + (size_t)(row + 8) * N + col) = __nv_bfloat162(l0, l1);
            } else {
                float* p0 = C + (size_t)row * N + col;
                float* p1 = C + (size_t)(row + 8) * N + col;
                float2 v0 = make_float2(d[mi][ni][0], d[mi][ni][1]);
                float2 v1 = make_float2(d[mi][ni][2], d[mi][ni][3]);
                if (OMODE == 1) {
                    float2 o0 = *(const float2*)p0, o1 = *(const float2*)p1;
                    v0.x += o0.x; v0.y += o0.y; v1.x += o1.x; v1.y += o1.y;
                }
                *(float2*)p0 = v0;
                *(float2*)p1 = v1;
            }
        }
}

// ---------------- fused weight split (27 units incl. packed layouts) ----------------
struct WSrc { const float* p[11]; };
// unit tables: src segment, row-block within source, dst base (MB1 units),
// dst row stride (elems), dst column offset.
__global__ void wsplit_all_k(WSrc ws, __nv_bfloat16* __restrict__ hi,
                             __nv_bfloat16* __restrict__ lo) {
    const unsigned char segOf[27] = {0,1, 2,2,2,2,2,2, 3,3, 4,4,4,4,4,4,4,4, 5,5,5,5, 6,7, 8,9,10};
    const unsigned char locOf[27] = {0,0, 0,1,2,3,4,5, 0,1, 0,1,2,3,4,5,6,7, 0,1,2,3, 0,0, 0,0,0};
    const unsigned char baseOf[27]= {0,1, 2,3,4,5,6,7, 8,9, 10,11,12,13,14,15,16,17, 18,19,20,21, 22,22, 24,24,24};
    const unsigned short strOf[27]= {1024,1024, 1024,1024,1024,1024,1024,1024, 1024,1024,
                                     1024,1024,1024,1024,1024,1024,1024,1024, 1024,1024,1024,1024,
                                     2048,2048, 3072,3072,3072};
    const unsigned short colOf[27]= {0,0, 0,0,0,0,0,0, 0,0, 0,0,0,0,0,0,0,0, 0,0,0,0,
                                     0,1024, 0,1024,2048};
    int unit = blockIdx.y;
    const float4* src = (const float4*)ws.p[segOf[unit]] + (size_t)locOf[unit] * (MB1 >> 2);
    size_t dbase = (size_t)baseOf[unit] * MB1;
    int stride = strOf[unit], coloff = colOf[unit];
    for (int i = blockIdx.x * blockDim.x + threadIdx.x; i < (int)(MB1 >> 2);
         i += gridDim.x * blockDim.x) {
        float4 v = src[i];
        int row = i >> 8, c4 = i & 255;
        size_t e = dbase + (size_t)row * stride + coloff + c4 * 4;
        __nv_bfloat16 h0, h1, h2, h3, l0, l1, l2, l3;
        bsplit(v.x, h0, l0); bsplit(v.y, h1, l1);
        bsplit(v.z, h2, l2); bsplit(v.w, h3, l3);
        *(__nv_bfloat162*)(hi + e)     = __nv_bfloat162(h0, h1);
        *(__nv_bfloat162*)(hi + e + 2) = __nv_bfloat162(h2, h3);
        *(__nv_bfloat162*)(lo + e)     = __nv_bfloat162(l0, l1);
        *(__nv_bfloat162*)(lo + e + 2) = __nv_bfloat162(l2, l3);
    }
}

// ---------------- one-time inv_freq table ----------------
__global__ void init_invf_k() {
    int j = threadIdx.x;
    if (j < 64) {
        double invf_d = exp(-(double)j * (9.210340371976184 / 64.0));
        g_invf[j] = (float)invf_d;
    }
}

// ---------------- rmsnorm -> split bf16 (with output stride/offset) ----------------
__global__ void rmsnorm_k(const float* __restrict__ in, const float* __restrict__ w,
                          __nv_bfloat16* __restrict__ oh, __nv_bfloat16* __restrict__ ol,
                          int gsize, int gstride, int goff, int ostride, int ooff) {
    __shared__ float red[32];
    int r = blockIdx.x;
    int inrow = (r / gsize) * gstride + goff + (r % gsize);
    const float* x = in + (size_t)inrow * 1024;
    float v[4]; float ss = 0.f;
#pragma unroll
    for (int i = 0; i < 4; i++) { v[i] = x[threadIdx.x + i * 256]; ss += v[i] * v[i]; }
    ss = blk_sum(ss, red);
    float sc = rsqrtf(ss * (1.f / 1024.f) + EPS_);
#pragma unroll
    for (int i = 0; i < 4; i++) {
        int idx = threadIdx.x + i * 256;
        float f = v[i] * sc * w[idx];
        __nv_bfloat16 h, l; bsplit(f, h, l);
        size_t o = (size_t)r * ostride + ooff + idx;
        oh[o] = h; ol[o] = l;
    }
}

// ---------------- fused shifted-y + rmsnorm -> ach cols 2048..3071 ----------------
__global__ void yfrms_k(const float* __restrict__ y, const int* __restrict__ begin,
                        const float* __restrict__ pad_emb, const float* __restrict__ w,
                        __nv_bfloat16* __restrict__ oh, __nv_bfloat16* __restrict__ ol) {
    __shared__ float red[32];
    int r = blockIdx.x;
    int b = r >> 9, t = r & 511;
    int n = t & 15, l = t >> 4;
    bool cond = (n == 0) && (begin[b * 32 + l] != 0);
    const float* x = cond ? pad_emb : (y + ((size_t)b * 512 + ((t + 511) & 511)) * 1024);
    float v[4]; float ss = 0.f;
#pragma unroll
    for (int i = 0; i < 4; i++) { v[i] = x[threadIdx.x + i * 256]; ss += v[i] * v[i]; }
    ss = blk_sum(ss, red);
    float sc = rsqrtf(ss * (1.f / 1024.f) + EPS_);
#pragma unroll
    for (int i = 0; i < 4; i++) {
        int idx = threadIdx.x + i * 256;
        float f = v[i] * sc * w[idx];
        __nv_bfloat16 h, lo; bsplit(f, h, lo);
        size_t o = (size_t)r * 3072 + 2048 + idx;
        oh[o] = h; ol[o] = lo;
    }
}

// ---------------- l2norm + rotary v2: block per (s, b), warp per 2 segments ----------------
__global__ void __launch_bounds__(256) qk_rope_k(float* __restrict__ qkv) {
    int s = blockIdx.x, b = blockIdx.y;
    int t = threadIdx.x, w = t >> 5, lane = t & 31;
#pragma unroll
    for (int si = 0; si < 2; si++) {
        int sg = w * 2 + si;             // 0..15
        int h = sg >> 1;
        int off = (sg & 1) ? 1024 : 0;
        float* p = qkv + ((size_t)(b * 2048 + s)) * 3072 + off + h * 128;
        float4 v = *(float4*)&p[lane * 4];
        float ss = v.x * v.x + v.y * v.y + v.z * v.z + v.w * v.w;
#pragma unroll
        for (int o = 16; o; o >>= 1) ss += __shfl_xor_sync(0xffffffffu, ss, o);
        float scl = 1.f / fmaxf(sqrtf(ss), EPS_);
        v.x *= scl; v.y *= scl; v.z *= scl; v.w *= scl;
        float4 u;
        u.x = __shfl_xor_sync(0xffffffffu, v.x, 16);
        u.y = __shfl_xor_sync(0xffffffffu, v.y, 16);
        u.z = __shfl_xor_sync(0xffffffffu, v.z, 16);
        u.w = __shfl_xor_sync(0xffffffffu, v.w, 16);
        bool lohalf = lane < 16;
        int jb = (lane & 15) * 4;
        float ov[4], vv[4] = {v.x, v.y, v.z, v.w}, uu[4] = {u.x, u.y, u.z, u.w};
#pragma unroll
        for (int i = 0; i < 4; i++) {
            float ang = (float)s * g_invf[jb + i];
            float c = cosf(ang), sn = sinf(ang);
            ov[i] = lohalf ? (vv[i] * c + uu[i] * sn) : (-uu[i] * sn + vv[i] * c);
        }
        *(float4*)&p[lane * 4] = make_float4(ov[0], ov[1], ov[2], ov[3]);
    }
}

// ---------------- attention v2: CTA per (b, role*8+h, qb) ----------------
__global__ void __launch_bounds__(128) attn2_k(const float* __restrict__ qkv,
                                               const int* __restrict__ doc,
                                               __nv_bfloat16* __restrict__ oh,
                                               __nv_bfloat16* __restrict__ ol) {
    __shared__ __align__(16) float sbuf[8752];
    int qb = blockIdx.x;
    int role = blockIdx.y >> 3;
    int h = blockIdx.y & 7;
    int b = blockIdx.z;
    int t = threadIdx.x;
    int lane = t & 31, w = t >> 5;
    const float* base = qkv + (size_t)b * 2048 * 3072;
    const float* Qb = base + (size_t)h * 128;
    const float* Kb = base + 1024 + (size_t)h * 128;
    const float* Vb = base + 2048 + (size_t)h * 128;
    const float scale = 0.088388347648318447f;

    if (role == 0) {
        float (*qs)[132] = (float(*)[132])sbuf;
        float (*ps)[49]  = (float(*)[49])(sbuf + 6336);
        float* inv = sbuf + 6336 + 2352;
        for (int u = t; u < 48 * 32; u += 128) {
            int rr = u >> 5, c = u & 31;
            *(float4*)&qs[rr][c * 4] =
                *(const float4*)&Qb[(size_t)(qb * 64 + rr) * 3072 + c * 4];
        }
        __syncthreads();
        int tq = t & 15, tk = t >> 4;
        float acc[3][6];
#pragma unroll
        for (int j = 0; j < 3; j++)
#pragma unroll
            for (int i = 0; i < 6; i++) acc[j][i] = 0.f;
#pragma unroll
        for (int dc = 0; dc < 8; dc++) {
            float4 qv[3][4];
#pragma unroll
            for (int j = 0; j < 3; j++)
#pragma unroll
                for (int x = 0; x < 4; x++)
                    qv[j][x] = *(float4*)&qs[tq + 16 * j][dc * 16 + x * 4];
#pragma unroll
            for (int i = 0; i < 6; i++) {
                int k = tk + 8 * i;
                const float4* Kr = (const float4*)&Kb[(size_t)(qb * 64 + k) * 3072 + dc * 16];
#pragma unroll
                for (int x = 0; x < 4; x++) {
                    float4 kv = Kr[x];
#pragma unroll
                    for (int j = 0; j < 3; j++)
                        acc[j][i] += qv[j][x].x * kv.x + qv[j][x].y * kv.y
                                   + qv[j][x].z * kv.z + qv[j][x].w * kv.w;
                }
            }
        }
#pragma unroll
        for (int j = 0; j < 3; j++)
#pragma unroll
            for (int i = 0; i < 6; i++)
                ps[tq + 16 * j][tk + 8 * i] = acc[j][i] * scale;
        __syncthreads();
        for (int j = 0; j < 12; j++) {
            int q = w * 12 + j;
            float v0 = ps[q][lane];
            float v1 = (lane < 16) ? ps[q][lane + 32] : -INFINITY;
            float m = fmaxf(v0, v1);
#pragma unroll
            for (int o = 16; o; o >>= 1) m = fmaxf(m, __shfl_xor_sync(0xffffffffu, m, o));
            float p0 = expf(v0 - m);
            float p1 = (lane < 16) ? expf(v1 - m) : 0.f;
            float s = p0 + p1;
#pragma unroll
            for (int o = 16; o; o >>= 1) s += __shfl_xor_sync(0xffffffffu, s, o);
            ps[q][lane] = p0;
            if (lane < 16) ps[q][lane + 32] = p1;
            if (lane == 0) inv[q] = 1.f / s;
        }
        __syncthreads();
        int tq2 = t & 15, td = t >> 4;
        float a2[3][16];
#pragma unroll
        for (int j = 0; j < 3; j++)
#pragma unroll
            for (int x = 0; x < 16; x++) a2[j][x] = 0.f;
        for (int k = 0; k < 48; k++) {
            const float4* Vr = (const float4*)&Vb[(size_t)(qb * 64 + k) * 3072 + td * 16];
            float4 v[4];
#pragma unroll
            for (int x = 0; x < 4; x++) v[x] = Vr[x];
#pragma unroll
            for (int j = 0; j < 3; j++) {
                float p = ps[tq2 + 16 * j][k];
#pragma unroll
                for (int x = 0; x < 4; x++) {
                    a2[j][x * 4 + 0] += p * v[x].x; a2[j][x * 4 + 1] += p * v[x].y;
                    a2[j][x * 4 + 2] += p * v[x].z; a2[j][x * 4 + 3] += p * v[x].w;
                }
            }
        }
#pragma unroll
        for (int j = 0; j < 3; j++) {
            int q = tq2 + 16 * j;
            float iv = inv[q];
            size_t o = ((size_t)(b * 2048 + qb * 64 + q)) * 1024 + h * 128 + td * 16;
#pragma unroll
            for (int x = 0; x < 16; x++) {
                __nv_bfloat16 fh, fl; bsplit(a2[j][x] * iv, fh, fl);
                oh[o + x] = fh; ol[o + x] = fl;
            }
        }
    } else {
        float (*qs)[132] = (float(*)[132])sbuf;
        float (*ps)[324] = (float(*)[324])(sbuf + 2112);
        int*   kls  = (int*)(sbuf + 2112 + 5184);
        int*   docs = kls + 320;
        float* inv  = (float*)(docs + 32);
        int npb = min(16, qb), np = npb * 16, NK = np + 64;
        if (t < 32) docs[t] = doc[b * 32 + t];
        for (int i = t; i < NK; i += 128) {
            int k;
            if (i < np) { int kb = qb - npb + (i >> 4); k = kb * 64 + 48 + (i & 15); }
            else          k = qb * 64 + (i - np);
            kls[i] = k;
        }
        for (int u = t; u < 16 * 32; u += 128) {
            int rr = u >> 5, c = u & 31;
            *(float4*)&qs[rr][c * 4] =
                *(const float4*)&Qb[(size_t)(qb * 64 + 48 + rr) * 3072 + c * 4];
        }
        __syncthreads();
        int tq = t & 15, tk = t >> 4;
#pragma unroll
        for (int dc = 0; dc < 4; dc++) {
            float4 qv[8];
#pragma unroll
            for (int x = 0; x < 8; x++) qv[x] = *(float4*)&qs[tq][dc * 32 + x * 4];
            for (int ki = tk; ki < NK; ki += 8) {
                const float4* Kr = (const float4*)&Kb[(size_t)kls[ki] * 3072 + dc * 32];
                float a = 0.f;
#pragma unroll
                for (int x = 0; x < 8; x++) {
                    float4 kv = Kr[x];
                    a += qv[x].x * kv.x + qv[x].y * kv.y + qv[x].z * kv.z + qv[x].w * kv.w;
                }
                if (dc == 0) ps[tq][ki] = a; else ps[tq][ki] += a;
            }
        }
        {
            int docq = docs[qb];
            int docp = docs[qb > 0 ? qb - 1 : 0];
            int q = qb * 64 + 48 + tq;
            int posq = (48 + tq) + qb * 16;
            for (int ki = tk; ki < NK; ki += 8) {
                int k = kls[ki];
                int kb = k >> 6, kr = k & 63;
                bool newk = kr >= 48;
                int posk = kr + kb * 16;
                bool nn = newk && (q >= k) && (posq < posk + 256) && (docq == docs[kb]);
                bool ao = (!newk) && (kb == qb) && (docq == docp);
                ps[tq][ki] = (nn || ao) ? ps[tq][ki] * scale : -INFINITY;
            }
        }
        __syncthreads();
        for (int j = 0; j < 4; j++) {
            int q = w * 4 + j;
            float m = -INFINITY;
            for (int i = lane; i < NK; i += 32) m = fmaxf(m, ps[q][i]);
#pragma unroll
            for (int o = 16; o; o >>= 1) m = fmaxf(m, __shfl_xor_sync(0xffffffffu, m, o));
            float s = 0.f;
            for (int i = lane; i < NK; i += 32) {
                float v = ps[q][i];
                float p = (v > -INFINITY) ? expf(v - m) : 0.f;
                ps[q][i] = p;
                s += p;
            }
#pragma unroll
            for (int o = 16; o; o >>= 1) s += __shfl_xor_sync(0xffffffffu, s, o);
            if (lane == 0) inv[q] = 1.f / s;
        }
        __syncthreads();
        int tq3 = t >> 3, td = t & 7;
        float a2[16];
#pragma unroll
        for (int x = 0; x < 16; x++) a2[x] = 0.f;
        for (int ki = 0; ki < NK; ki++) {
            float p = ps[tq3][ki];
            if (p != 0.f) {
                const float4* Vr = (const float4*)&Vb[(size_t)kls[ki] * 3072 + td * 16];
#pragma unroll
                for (int x = 0; x < 4; x++) {
                    float4 v = Vr[x];
                    a2[x * 4 + 0] += p * v.x; a2[x * 4 + 1] += p * v.y;
                    a2[x * 4 + 2] += p * v.z; a2[x * 4 + 3] += p * v.w;
                }
            }
        }
        float iv = inv[tq3];
        size_t o = ((size_t)(b * 2048 + qb * 64 + 48 + tq3)) * 1024 + h * 128 + td * 16;
#pragma unroll
        for (int x = 0; x < 16; x++) {
            __nv_bfloat16 fh, fl; bsplit(a2[x] * iv, fh, fl);
            oh[o + x] = fh; ol[o + x] = fl;
        }
    }
}

// ---------------- silu-gate from split-bf16 up -> split bf16 gate ----------------
__global__ void silu_gate_k(const __nv_bfloat16* __restrict__ uph,
                            const __nv_bfloat16* __restrict__ upl,
                            __nv_bfloat16* __restrict__ gh, __nv_bfloat16* __restrict__ gl) {
    int i = blockIdx.x * 256 + threadIdx.x;
    if (i >= (BP_ * S_ * FH_) / 4) return;
    int r = i >> 9, c4 = i & 511;
    size_t oa = (size_t)r * 4096 + c4 * 4;
    __nv_bfloat162 ah0 = *(const __nv_bfloat162*)(uph + oa);
    __nv_bfloat162 ah1 = *(const __nv_bfloat162*)(uph + oa + 2);
    __nv_bfloat162 al0 = *(const __nv_bfloat162*)(upl + oa);
    __nv_bfloat162 al1 = *(const __nv_bfloat162*)(upl + oa + 2);
    __nv_bfloat162 bh0 = *(const __nv_bfloat162*)(uph + oa + 2048);
    __nv_bfloat162 bh1 = *(const __nv_bfloat162*)(uph + oa + 2050);
    __nv_bfloat162 bl0 = *(const __nv_bfloat162*)(upl + oa + 2048);
    __nv_bfloat162 bl1 = *(const __nv_bfloat162*)(upl + oa + 2050);
    float a[4], bb[4];
    a[0] = __bfloat162float(ah0.x) + __bfloat162float(al0.x);
    a[1] = __bfloat162float(ah0.y) + __bfloat162float(al0.y);
    a[2] = __bfloat162float(ah1.x) + __bfloat162float(al1.x);
    a[3] = __bfloat162float(ah1.y) + __bfloat162float(al1.y);
    bb[0] = __bfloat162float(bh0.x) + __bfloat162float(bl0.x);
    bb[1] = __bfloat162float(bh0.y) + __bfloat162float(bl0.y);
    bb[2] = __bfloat162float(bh1.x) + __bfloat162float(bl1.x);
    bb[3] = __bfloat162float(bh1.y) + __bfloat162float(bl1.y);
    __nv_bfloat16 h[4], l[4];
#pragma unroll
    for (int j = 0; j < 4; j++) {
        float f = (a[j] / (1.f + expf(-a[j]))) * bb[j];
        bsplit(f, h[j], l[j]);
    }
    size_t og = (size_t)r * 2048 + c4 * 4;
    *(__nv_bfloat162*)(gh + og)     = __nv_bfloat162(h[0], h[1]);
    *(__nv_bfloat162*)(gh + og + 2) = __nv_bfloat162(h[2], h[3]);
    *(__nv_bfloat162*)(gl + og)     = __nv_bfloat162(l[0], l[1]);
    *(__nv_bfloat162*)(gl + og + 2) = __nv_bfloat162(l[2], l[3]);
}

// ---------------- assemble x from x_old / x_new ----------------
__global__ void assemble_k(float* __restrict__ x, const float* __restrict__ xold,
                           const float* __restrict__ xnew) {
    int idx = blockIdx.x * blockDim.x + threadIdx.x;
    if (idx >= BP_ * S_ * 256) return;
    int d4 = idx & 255;
    int gr = idx >> 8;
    int b = gr >> 11, s = gr & 2047;
    int l = s >> 6, rr = s & 63;
    float4 v;
    if (rr < 48)
        v = ((const float4*)xold)[((size_t)((b * 32 + l) * 48 + rr)) * 256 + d4];
    else
        v = ((const float4*)xnew)[((size_t)((b * 32 + l) * 16 + (rr - 48))) * 256 + d4];
    ((float4*)x)[idx] = v;
}

// ---------------- extract y = x[:,:,M:,:] (fp32 + split) ----------------
__global__ void extract_y_k(const float* __restrict__ x, float* __restrict__ y,
                            __nv_bfloat16* __restrict__ yh, __nv_bfloat16* __restrict__ yl) {
    int idx = blockIdx.x * blockDim.x + threadIdx.x;
    if (idx >= BP_ * 512 * 256) return;
    int d4 = idx & 255;
    int r = idx >> 8;
    int b = r >> 9, t = r & 511;
    int l = t >> 4, n = t & 15;
    int xr = b * 2048 + l * 64 + 48 + n;
    float4 v = ((const float4*)x)[(size_t)xr * 256 + d4];
    ((float4*)y)[idx] = v;
    __nv_bfloat16 h0, h1, h2, h3, l0, l1, l2, l3;
    bsplit(v.x, h0, l0); bsplit(v.y, h1, l1); bsplit(v.z, h2, l2); bsplit(v.w, h3, l3);
    ((__nv_bfloat162*)yh)[2 * idx]     = __nv_bfloat162(h0, h1);
    ((__nv_bfloat162*)yh)[2 * idx + 1] = __nv_bfloat162(h2, h3);
    ((__nv_bfloat162*)yl)[2 * idx]     = __nv_bfloat162(l0, l1);
    ((__nv_bfloat162*)yl)[2 * idx + 1] = __nv_bfloat162(l2, l3);
}

// ---------------- host helpers ----------------
#define TG_SMEM (3 * 32768)

static void tgemm(const __nv_bfloat16* Ah, const __nv_bfloat16* Al,
                  const __nv_bfloat16* Bh, const __nv_bfloat16* Bl,
                  float* C, __nv_bfloat16* Ch, __nv_bfloat16* Cl,
                  int M, int N, int K, int lda, int ldb, int mode) {
    dim3 grid(N >> 7, M >> 7);
    if (mode == 0) {
        cudaFuncSetAttribute(tgemm_k<0>, cudaFuncAttributeMaxDynamicSharedMemorySize, TG_SMEM);
        tgemm_k<0><<<grid, 128, TG_SMEM>>>(Ah, Al, Bh, Bl, C, Ch, Cl, M, N, K, lda, ldb);
    } else if (mode == 1) {
        cudaFuncSetAttribute(tgemm_k<1>, cudaFuncAttributeMaxDynamicSharedMemorySize, TG_SMEM);
        tgemm_k<1><<<grid, 128, TG_SMEM>>>(Ah, Al, Bh, Bl, C, Ch, Cl, M, N, K, lda, ldb);
    } else {
        cudaFuncSetAttribute(tgemm_k<2>, cudaFuncAttributeMaxDynamicSharedMemorySize, TG_SMEM);
        tgemm_k<2><<<grid, 128, TG_SMEM>>>(Ah, Al, Bh, Bl, C, Ch, Cl, M, N, K, lda, ldb);
    }
}

extern "C" void kernel_launch(void* const* d_in, const int* in_sizes, int n_in,
                              void* d_out, int out_size) {
    (void)in_sizes; (void)n_in; (void)out_size;
    const float* x_input     = (const float*)d_in[0];
    const float* x_ar        = (const float*)d_in[1];
    const int*   doc         = (const int*)d_in[2];
    const int*   begin       = (const int*)d_in[3];
    const float* old_norm_w  = (const float*)d_in[4];
    const float* new_norm_w  = (const float*)d_in[5];
    const float* pad_emb     = (const float*)d_in[12];
    const float* attn_norm_w = (const float*)d_in[14];
    const float* ffn_norm_w  = (const float*)d_in[15];
    float* out = (float*)d_out;

    float *x, *qkv, *xold, *xnew, *y;
    __nv_bfloat16 *hh, *hl, *ah, *al, *uph, *upl, *gh, *gl;
    __nv_bfloat16 *ach, *acl, *yh, *yl, *whi, *wlo;
    cudaGetSymbolAddress((void**)&x,    g_x);
    cudaGetSymbolAddress((void**)&qkv,  g_qkv);
    cudaGetSymbolAddress((void**)&xold, g_xold);
    cudaGetSymbolAddress((void**)&xnew, g_xnew);
    cudaGetSymbolAddress((void**)&y,    g_y);
    cudaGetSymbolAddress((void**)&hh,   g_hh);
    cudaGetSymbolAddress((void**)&hl,   g_hl);
    cudaGetSymbolAddress((void**)&ah,   g_ah);
    cudaGetSymbolAddress((void**)&al,   g_al);
    cudaGetSymbolAddress((void**)&uph,  g_uph);
    cudaGetSymbolAddress((void**)&upl,  g_upl);
    cudaGetSymbolAddress((void**)&gh,   g_gh);
    cudaGetSymbolAddress((void**)&gl,   g_gl);
    cudaGetSymbolAddress((void**)&ach,  g_ach);
    cudaGetSymbolAddress((void**)&acl,  g_acl);
    cudaGetSymbolAddress((void**)&yh,   g_yh);
    cudaGetSymbolAddress((void**)&yl,   g_yl);
    cudaGetSymbolAddress((void**)&whi,  g_whi);
    cudaGetSymbolAddress((void**)&wlo,  g_wlo);

    init_invf_k<<<1, 64>>>();

    WSrc ws;
    ws.p[0]  = (const float*)d_in[6];   // w_old
    ws.p[1]  = (const float*)d_in[13];  // w_agg
    ws.p[2]  = (const float*)d_in[16];  // w_qkv
    ws.p[3]  = (const float*)d_in[17];  // w_o
    ws.p[4]  = (const float*)d_in[18];  // w_up
    ws.p[5]  = (const float*)d_in[19];  // w_down
    ws.p[6]  = (const float*)d_in[7];   // w_ar   -> packed wp2 col 0
    ws.p[7]  = (const float*)d_in[8];   // w_de   -> packed wp2 col 1024
    ws.p[8]  = (const float*)d_in[9];   // w_ar1  -> packed wp3 col 0
    ws.p[9]  = (const float*)d_in[10];  // w_de1  -> packed wp3 col 1024
    ws.p[10] = (const float*)d_in[11];  // w_y1   -> packed wp3 col 2048
    wsplit_all_k<<<dim3(64, 27), 256>>>(ws, whi, wlo);

    // input projections
    rmsnorm_k<<<3072, 256>>>(x_input, old_norm_w, hh, hl, 48, 64, 0, 1024, 0);
    tgemm(hh, hl, whi + (size_t)OFF_WOLD * MB1, wlo + (size_t)OFF_WOLD * MB1,
          xold, 0, 0, 3072, 1024, 1024, 1024, 1024, 0);
    rmsnorm_k<<<1024, 256>>>(x_ar,    new_norm_w, ach, acl, 16, 16, 0,  3072, 0);
    rmsnorm_k<<<1024, 256>>>(x_input, new_norm_w, ach, acl, 16, 64, 48, 3072, 1024);
    // xnew = [xarn|xden] @ [w_ar|w_de]^T  (K=2048, fused)
    tgemm(ach, acl, whi + (size_t)OFF_WP2 * MB1, wlo + (size_t)OFF_WP2 * MB1,
          xnew, 0, 0, 1024, 1024, 2048, 3072, 2048, 0);
    assemble_k<<<(BP_ * S_ * 256 + 255) / 256, 256>>>(x, xold, xnew);

    for (int it = 0; it < 2; it++) {
        for (int li = 0; li < 2; li++) {
            const __nv_bfloat16* wq_h = whi + (size_t)(OFF_WQKV + 3 * li) * MB1;
            const __nv_bfloat16* wq_l = wlo + (size_t)(OFF_WQKV + 3 * li) * MB1;
            const __nv_bfloat16* wo_h = whi + (size_t)(OFF_WO + li) * MB1;
            const __nv_bfloat16* wo_l = wlo + (size_t)(OFF_WO + li) * MB1;
            const __nv_bfloat16* wu_h = whi + (size_t)(OFF_WUP + 4 * li) * MB1;
            const __nv_bfloat16* wu_l = wlo + (size_t)(OFF_WUP + 4 * li) * MB1;
            const __nv_bfloat16* wd_h = whi + (size_t)(OFF_WDOWN + 2 * li) * MB1;
            const __nv_bfloat16* wd_l = wlo + (size_t)(OFF_WDOWN + 2 * li) * MB1;

            rmsnorm_k<<<4096, 256>>>(x, attn_norm_w + li * 1024, hh, hl, 1, 1, 0, 1024, 0);
            tgemm(hh, hl, wq_h, wq_l, qkv, 0, 0, 4096, 3072, 1024, 1024, 1024, 0);
            qk_rope_k<<<dim3(2048, 2), 256>>>(qkv);
            attn2_k<<<dim3(32, 16, 2), 128>>>(qkv, doc, ah, al);
            tgemm(ah, al, wo_h, wo_l, x, 0, 0, 4096, 1024, 1024, 1024, 1024, 1);
            rmsnorm_k<<<4096, 256>>>(x, ffn_norm_w + li * 1024, hh, hl, 1, 1, 0, 1024, 0);
            tgemm(hh, hl, wu_h, wu_l, 0, uph, upl, 4096, 4096, 1024, 1024, 1024, 2);
            silu_gate_k<<<(BP_ * S_ * FH_ / 4 + 255) / 256, 256>>>(uph, upl, gh, gl);
            tgemm(gh, gl, wd_h, wd_l, x, 0, 0, 4096, 1024, 2048, 2048, 2048, 1);
        }
        extract_y_k<<<(BP_ * 512 * 256 + 255) / 256, 256>>>(x, y, yh, yl);
        if (it == 0) {
            yfrms_k<<<1024, 256>>>(y, begin, pad_emb, new_norm_w, ach, acl);
            // xnew = [xarn|xden|y2] @ [w_ar1|w_de1|w_y1]^T  (K=3072, fused)
            tgemm(ach, acl, whi + (size_t)OFF_WP3 * MB1, wlo + (size_t)OFF_WP3 * MB1,
                  xnew, 0, 0, 1024, 1024, 3072, 3072, 3072, 0);
            assemble_k<<<(BP_ * S_ * 256 + 255) / 256, 256>>>(x, xold, xnew);
        }
    }

    tgemm(yh, yl, whi + (size_t)OFF_WAGG * MB1, wlo + (size_t)OFF_WAGG * MB1,
          out, 0, 0, 1024, 1024, 1024, 1024, 1024, 0);
}

// round 11
// speedup vs baseline: 6.6190x; 1.0132x over previous
#include <cuda_runtime.h>
#include <cuda_bf16.h>
#include <math.h>
#include <stdint.h>

// ---------------- problem constants ----------------
#define BP_  2
#define L_   32
#define N_   16
#define O_   64
#define D_   1024
#define AD_  1024
#define HEAD_ 128
#define W_   256
#define FH_  2048
#define M_   48
#define E_   64
#define S_   2048
#define EPS_ 1e-5f
#define MB1 (1u<<20)

// ---------------- device scratch (allocation-free) ----------------
__device__ float g_x   [BP_ * S_ * AD_];
__device__ float g_qkv [BP_ * S_ * 3 * AD_];
__device__ float g_xold[BP_ * L_ * M_ * AD_];
__device__ float g_xnew[BP_ * L_ * N_ * AD_];
__device__ float g_y   [BP_ * L_ * N_ * AD_];
__device__ float g_invf[64];

// bf16 split activation buffers
__device__ __nv_bfloat16 g_hh[BP_ * S_ * AD_],  g_hl[BP_ * S_ * AD_];
__device__ __nv_bfloat16 g_ah[BP_ * S_ * AD_],  g_al[BP_ * S_ * AD_];
__device__ __nv_bfloat16 g_gh[BP_ * S_ * FH_],  g_gl[BP_ * S_ * FH_];
__device__ __nv_bfloat16 g_ach[3u * MB1], g_acl[3u * MB1];   // [xarn|xden|y2] rows x 3072
__device__ __nv_bfloat16 g_yh[MB1],    g_yl[MB1];
// bf16 split weights: 27 MB1 units
__device__ __nv_bfloat16 g_whi[27u * MB1], g_wlo[27u * MB1];

#define OFF_WOLD  0
#define OFF_WAGG  1
#define OFF_WQKV  2   /* 3 per layer */
#define OFF_WO    8
#define OFF_WUP   10  /* 4 per layer; rows INTERLEAVED (a,b pairs) */
#define OFF_WDOWN 18  /* 2 per layer */
#define OFF_WP2   22  /* [w_ar|w_de]   rows x 2048 */
#define OFF_WP3   24  /* [w_ar1|w_de1|w_y1] rows x 3072 */

// ---------------- small helpers ----------------
__device__ __forceinline__ void bsplit(float f, __nv_bfloat16& h, __nv_bfloat16& l) {
    h = __float2bfloat16(f);
    l = __float2bfloat16(f - __bfloat162float(h));
}

__device__ __forceinline__ float blk_sum(float v, float* red) {
    int lane = threadIdx.x & 31, w = threadIdx.x >> 5;
#pragma unroll
    for (int o = 16; o; o >>= 1) v += __shfl_xor_sync(0xffffffffu, v, o);
    if (lane == 0) red[w] = v;
    __syncthreads();
    int nw = (blockDim.x + 31) >> 5;
    if (threadIdx.x < 32) {
        float r = (threadIdx.x < nw) ? red[threadIdx.x] : 0.f;
#pragma unroll
        for (int o = 16; o; o >>= 1) r += __shfl_xor_sync(0xffffffffu, r, o);
        if (lane == 0) red[0] = r;
    }
    __syncthreads();
    float r = red[0];
    __syncthreads();
    return r;
}

// ---------------- PTX helpers (compute_103-legal) ----------------
#define SWZ64(o) ((o) ^ (((o) >> 3) & 0x30))

static __device__ __forceinline__ uint32_t smem_u32(const void* p) {
    uint32_t a;
    asm("{ .reg .u64 t; cvta.to.shared.u64 t, %1; cvt.u32.u64 %0, t; }" : "=r"(a) : "l"(p));
    return a;
}
static __device__ __forceinline__ void cpa16(uint32_t dst, const void* src) {
    asm volatile("cp.async.cg.shared.global [%0], [%1], 16;" :: "r"(dst), "l"(src) : "memory");
}
static __device__ __forceinline__ void ldm4(uint32_t& r0, uint32_t& r1, uint32_t& r2,
                                            uint32_t& r3, uint32_t addr) {
    asm volatile("ldmatrix.sync.aligned.m8n8.x4.shared.b16 {%0,%1,%2,%3}, [%4];"
                 : "=r"(r0), "=r"(r1), "=r"(r2), "=r"(r3) : "r"(addr));
}
#define MMA16816(d, a, b) \
    asm volatile("mma.sync.aligned.m16n8k16.row.col.f32.bf16.bf16.f32 " \
        "{%0,%1,%2,%3}, {%4,%5,%6,%7}, {%8,%9}, {%0,%1,%2,%3};" \
        : "+f"((d)[0]), "+f"((d)[1]), "+f"((d)[2]), "+f"((d)[3]) \
        : "r"((a)[0]), "r"((a)[1]), "r"((a)[2]), "r"((a)[3]), "r"((b)[0]), "r"((b)[1]))

// ---------------- tensor-core split-bf16 GEMM ----------------
// 128x128 CTA tile, 128 threads, 2x2 warp grid, 64x64 warp tile,
// 3-stage cp.async pipeline, 2 CTA/SM. Supports lda/ldb row strides.
// OMODE: 0 = store fp32, 1 = accumulate fp32, 2 = store split bf16,
//        3 = fused silu-gate: weight rows interleaved (a,b), out cols N/2,
//            gate = silu(a)*b written split-bf16 to Ch/Cl.
template<int OMODE>
__global__ void __launch_bounds__(128, 2) tgemm_k(
    const __nv_bfloat16* __restrict__ Ah, const __nv_bfloat16* __restrict__ Al,
    const __nv_bfloat16* __restrict__ Bh, const __nv_bfloat16* __restrict__ Bl,
    float* __restrict__ C, __nv_bfloat16* __restrict__ Ch, __nv_bfloat16* __restrict__ Cl,
    int M, int N, int K, int lda, int ldb)
{
    extern __shared__ char smem[];
    uint32_t sb = smem_u32(smem);
    int tid = threadIdx.x, lane = tid & 31, wid = tid >> 5;
    int wm = wid & 1, wn = wid >> 1;
    int brow = blockIdx.y << 7, bcol = blockIdx.x << 7;

    const __nv_bfloat16* src0 = Ah + (size_t)brow * lda;
    const __nv_bfloat16* src1 = Al + (size_t)brow * lda;
    const __nv_bfloat16* src2 = Bh + (size_t)bcol * ldb;
    const __nv_bfloat16* src3 = Bl + (size_t)bcol * ldb;

    float d[4][8][4];
#pragma unroll
    for (int mi = 0; mi < 4; mi++)
#pragma unroll
        for (int ni = 0; ni < 8; ni++)
#pragma unroll
            for (int q = 0; q < 4; q++) d[mi][ni][q] = 0.f;

    const int nch = K >> 5;

    auto load_stage = [&](uint32_t stb, int k0) {
#pragma unroll
        for (int j = 0; j < 4; j++) {
            int u = tid + (j << 7);
            int row = u >> 2, un = u & 3;
            uint32_t doff = SWZ64((uint32_t)(row * 64 + un * 16));
            size_t ga = (size_t)row * lda + k0 + un * 8;
            size_t gb = (size_t)row * ldb + k0 + un * 8;
            cpa16(stb +     0 + doff, src0 + ga);
            cpa16(stb +  8192 + doff, src1 + ga);
            cpa16(stb + 16384 + doff, src2 + gb);
            cpa16(stb + 24576 + doff, src3 + gb);
        }
        asm volatile("cp.async.commit_group;" ::: "memory");
    };

    load_stage(sb, 0);
    if (nch > 1) load_stage(sb + 32768, 32);

    int g = lane >> 3, r = lane & 7;
    for (int i = 0; i < nch; i++) {
        if (i + 1 < nch) { asm volatile("cp.async.wait_group 1;" ::: "memory"); }
        else             { asm volatile("cp.async.wait_group 0;" ::: "memory"); }
        __syncthreads();
        if (i + 2 < nch) {
            int s = (i + 2) % 3;
            load_stage(sb + (uint32_t)(s * 32768), (i + 2) << 5);
        }
        uint32_t stb = sb + (uint32_t)((i % 3) * 32768);

#pragma unroll
        for (int ks = 0; ks < 2; ks++) {
            uint32_t ah[4][4], al[4][4], bh[8][2], bl[8][2];
#pragma unroll
            for (int mi = 0; mi < 4; mi++) {
                int row = wm * 64 + mi * 16 + (g & 1) * 8 + r;
                int colb = ks * 32 + (g >> 1) * 16;
                uint32_t off = SWZ64((uint32_t)(row * 64 + colb));
                ldm4(ah[mi][0], ah[mi][1], ah[mi][2], ah[mi][3], stb + off);
                ldm4(al[mi][0], al[mi][1], al[mi][2], al[mi][3], stb + 8192 + off);
            }
#pragma unroll
            for (int n2 = 0; n2 < 4; n2++) {
                int rown = wn * 64 + n2 * 16 + (g >> 1) * 8 + r;
                int colb = ks * 32 + (g & 1) * 16;
                uint32_t off = SWZ64((uint32_t)(rown * 64 + colb));
                ldm4(bh[2*n2][0], bh[2*n2][1], bh[2*n2+1][0], bh[2*n2+1][1], stb + 16384 + off);
                ldm4(bl[2*n2][0], bl[2*n2][1], bl[2*n2+1][0], bl[2*n2+1][1], stb + 24576 + off);
            }
#pragma unroll
            for (int mi = 0; mi < 4; mi++)
#pragma unroll
                for (int ni = 0; ni < 8; ni++) MMA16816(d[mi][ni], ah[mi], bh[ni]);
#pragma unroll
            for (int mi = 0; mi < 4; mi++)
#pragma unroll
                for (int ni = 0; ni < 8; ni++) MMA16816(d[mi][ni], ah[mi], bl[ni]);
#pragma unroll
            for (int mi = 0; mi < 4; mi++)
#pragma unroll
                for (int ni = 0; ni < 8; ni++) MMA16816(d[mi][ni], al[mi], bh[ni]);
        }
    }

    // epilogue
#pragma unroll
    for (int mi = 0; mi < 4; mi++)
#pragma unroll
        for (int ni = 0; ni < 8; ni++) {
            int row = brow + wm * 64 + mi * 16 + (lane >> 2);
            int col = bcol + wn * 64 + ni * 8 + 2 * (lane & 3);
            if (OMODE == 3) {
                // cols (col, col+1) = (a, b) interleaved pair -> gate col/2
                int gcol = col >> 1;
                int gn = N >> 1;
                float a0 = d[mi][ni][0], b0 = d[mi][ni][1];
                float a1 = d[mi][ni][2], b1 = d[mi][ni][3];
                float f0 = (a0 / (1.f + expf(-a0))) * b0;
                float f1 = (a1 / (1.f + expf(-a1))) * b1;
                __nv_bfloat16 h0, l0, h1, l1;
                bsplit(f0, h0, l0); bsplit(f1, h1, l1);
                Ch[(size_t)row * gn + gcol] = h0;
                Cl[(size_t)row * gn + gcol] = l0;
                Ch[(size_t)(row + 8) * gn + gcol] = h1;
                Cl[(size_t)(row + 8) * gn + gcol] = l1;
            } else if (OMODE == 2) {
                __nv_bfloat16 h0, h1, l0, l1;
                bsplit(d[mi][ni][0], h0, l0); bsplit(d[mi][ni][1], h1, l1);
                *(__nv_bfloat162*)(Ch + (size_t)row * N + col) = __nv_bfloat162(h0, h1);
                *(__nv_bfloat162*)(Cl + (size_t)row * N + col) = __nv_bfloat162(l0, l1);
                bsplit(d[mi][ni][2], h0, l0); bsplit(d[mi][ni][3], h1, l1);
                *(__nv_bfloat162*)(Ch + (size_t)(row + 8) * N + col) = __nv_bfloat162(h0, h1);
                *(__nv_bfloat162*)(Cl + (size_t)(row + 8) * N + col) = __nv_bfloat162(l0, l1);
            } else {
                float* p0 = C + (size_t)row * N + col;
                float* p1 = C + (size_t)(row + 8) * N + col;
                float2 v0 = make_float2(d[mi][ni][0], d[mi][ni][1]);
                float2 v1 = make_float2(d[mi][ni][2], d[mi][ni][3]);
                if (OMODE == 1) {
                    float2 o0 = *(const float2*)p0, o1 = *(const float2*)p1;
                    v0.x += o0.x; v0.y += o0.y; v1.x += o1.x; v1.y += o1.y;
                }
                *(float2*)p0 = v0;
                *(float2*)p1 = v1;
            }
        }
}

// ---------------- fused weight split (27 units incl. packed + interleaved) ----------------
struct WSrc { const float* p[11]; };
__global__ void wsplit_all_k(WSrc ws, __nv_bfloat16* __restrict__ hi,
                             __nv_bfloat16* __restrict__ lo) {
    const unsigned char segOf[27] = {0,1, 2,2,2,2,2,2, 3,3, 4,4,4,4,4,4,4,4, 5,5,5,5, 6,7, 8,9,10};
    const unsigned char locOf[27] = {0,0, 0,1,2,3,4,5, 0,1, 0,1,2,3,4,5,6,7, 0,1,2,3, 0,0, 0,0,0};
    const unsigned char baseOf[27]= {0,1, 2,3,4,5,6,7, 8,9, 10,11,12,13,14,15,16,17, 18,19,20,21, 22,22, 24,24,24};
    const unsigned short strOf[27]= {1024,1024, 1024,1024,1024,1024,1024,1024, 1024,1024,
                                     1024,1024,1024,1024,1024,1024,1024,1024, 1024,1024,1024,1024,
                                     2048,2048, 3072,3072,3072};
    const unsigned short colOf[27]= {0,0, 0,0,0,0,0,0, 0,0, 0,0,0,0,0,0,0,0, 0,0,0,0,
                                     0,1024, 0,1024,2048};
    int unit = blockIdx.y;
    bool ileave = (unit >= 10 && unit <= 17);   // w_up: interleave (a,b) rows
    const float4* src = (const float4*)ws.p[segOf[unit]] + (size_t)locOf[unit] * (MB1 >> 2);
    for (int i = blockIdx.x * blockDim.x + threadIdx.x; i < (int)(MB1 >> 2);
         i += gridDim.x * blockDim.x) {
        float4 v = src[i];
        int row = i >> 8, c4 = i & 255;
        size_t e;
        if (ileave) {
            int layer = (unit - 10) >> 2, loc = (unit - 10) & 3;
            int grow = loc * 1024 + row;
            int drow = (grow < 2048) ? (grow * 2) : ((grow - 2048) * 2 + 1);
            e = (size_t)(OFF_WUP + 4 * layer) * MB1 + (size_t)drow * 1024 + c4 * 4;
        } else {
            e = (size_t)baseOf[unit] * MB1 + (size_t)row * strOf[unit] + colOf[unit] + c4 * 4;
        }
        __nv_bfloat16 h0, h1, h2, h3, l0, l1, l2, l3;
        bsplit(v.x, h0, l0); bsplit(v.y, h1, l1);
        bsplit(v.z, h2, l2); bsplit(v.w, h3, l3);
        *(__nv_bfloat162*)(hi + e)     = __nv_bfloat162(h0, h1);
        *(__nv_bfloat162*)(hi + e + 2) = __nv_bfloat162(h2, h3);
        *(__nv_bfloat162*)(lo + e)     = __nv_bfloat162(l0, l1);
        *(__nv_bfloat162*)(lo + e + 2) = __nv_bfloat162(l2, l3);
    }
}

// ---------------- one-time inv_freq table ----------------
__global__ void init_invf_k() {
    int j = threadIdx.x;
    if (j < 64) {
        double invf_d = exp(-(double)j * (9.210340371976184 / 64.0));
        g_invf[j] = (float)invf_d;
    }
}

// ---------------- rmsnorm -> split bf16 (float4-vectorized) ----------------
__global__ void rmsnorm_k(const float* __restrict__ in, const float* __restrict__ w,
                          __nv_bfloat16* __restrict__ oh, __nv_bfloat16* __restrict__ ol,
                          int gsize, int gstride, int goff, int ostride, int ooff) {
    __shared__ float red[32];
    int r = blockIdx.x;
    int inrow = (r / gsize) * gstride + goff + (r % gsize);
    float4 v = ((const float4*)(in + (size_t)inrow * 1024))[threadIdx.x];
    float ss = v.x * v.x + v.y * v.y + v.z * v.z + v.w * v.w;
    ss = blk_sum(ss, red);
    float sc = rsqrtf(ss * (1.f / 1024.f) + EPS_);
    float4 wv = ((const float4*)w)[threadIdx.x];
    __nv_bfloat16 h0, h1, h2, h3, l0, l1, l2, l3;
    bsplit(v.x * sc * wv.x, h0, l0); bsplit(v.y * sc * wv.y, h1, l1);
    bsplit(v.z * sc * wv.z, h2, l2); bsplit(v.w * sc * wv.w, h3, l3);
    size_t o = (size_t)r * ostride + ooff + threadIdx.x * 4;
    *(__nv_bfloat162*)(oh + o)     = __nv_bfloat162(h0, h1);
    *(__nv_bfloat162*)(oh + o + 2) = __nv_bfloat162(h2, h3);
    *(__nv_bfloat162*)(ol + o)     = __nv_bfloat162(l0, l1);
    *(__nv_bfloat162*)(ol + o + 2) = __nv_bfloat162(l2, l3);
}

// ---------------- fused shifted-y + rmsnorm -> ach cols 2048..3071 ----------------
__global__ void yfrms_k(const float* __restrict__ y, const int* __restrict__ begin,
                        const float* __restrict__ pad_emb, const float* __restrict__ w,
                        __nv_bfloat16* __restrict__ oh, __nv_bfloat16* __restrict__ ol) {
    __shared__ float red[32];
    int r = blockIdx.x;
    int b = r >> 9, t = r & 511;
    int n = t & 15, l = t >> 4;
    bool cond = (n == 0) && (begin[b * 32 + l] != 0);
    const float* x = cond ? pad_emb : (y + ((size_t)b * 512 + ((t + 511) & 511)) * 1024);
    float4 v = ((const float4*)x)[threadIdx.x];
    float ss = v.x * v.x + v.y * v.y + v.z * v.z + v.w * v.w;
    ss = blk_sum(ss, red);
    float sc = rsqrtf(ss * (1.f / 1024.f) + EPS_);
    float4 wv = ((const float4*)w)[threadIdx.x];
    __nv_bfloat16 h0, h1, h2, h3, l0, l1, l2, l3;
    bsplit(v.x * sc * wv.x, h0, l0); bsplit(v.y * sc * wv.y, h1, l1);
    bsplit(v.z * sc * wv.z, h2, l2); bsplit(v.w * sc * wv.w, h3, l3);
    size_t o = (size_t)r * 3072 + 2048 + threadIdx.x * 4;
    *(__nv_bfloat162*)(oh + o)     = __nv_bfloat162(h0, h1);
    *(__nv_bfloat162*)(oh + o + 2) = __nv_bfloat162(h2, h3);
    *(__nv_bfloat162*)(ol + o)     = __nv_bfloat162(l0, l1);
    *(__nv_bfloat162*)(ol + o + 2) = __nv_bfloat162(l2, l3);
}

// ---------------- l2norm + rotary v2: block per (s, b), warp per 2 segments ----------------
__global__ void __launch_bounds__(256) qk_rope_k(float* __restrict__ qkv) {
    int s = blockIdx.x, b = blockIdx.y;
    int t = threadIdx.x, w = t >> 5, lane = t & 31;
#pragma unroll
    for (int si = 0; si < 2; si++) {
        int sg = w * 2 + si;
        int h = sg >> 1;
        int off = (sg & 1) ? 1024 : 0;
        float* p = qkv + ((size_t)(b * 2048 + s)) * 3072 + off + h * 128;
        float4 v = *(float4*)&p[lane * 4];
        float ss = v.x * v.x + v.y * v.y + v.z * v.z + v.w * v.w;
#pragma unroll
        for (int o = 16; o; o >>= 1) ss += __shfl_xor_sync(0xffffffffu, ss, o);
        float scl = 1.f / fmaxf(sqrtf(ss), EPS_);
        v.x *= scl; v.y *= scl; v.z *= scl; v.w *= scl;
        float4 u;
        u.x = __shfl_xor_sync(0xffffffffu, v.x, 16);
        u.y = __shfl_xor_sync(0xffffffffu, v.y, 16);
        u.z = __shfl_xor_sync(0xffffffffu, v.z, 16);
        u.w = __shfl_xor_sync(0xffffffffu, v.w, 16);
        bool lohalf = lane < 16;
        int jb = (lane & 15) * 4;
        float ov[4], vv[4] = {v.x, v.y, v.z, v.w}, uu[4] = {u.x, u.y, u.z, u.w};
#pragma unroll
        for (int i = 0; i < 4; i++) {
            float ang = (float)s * g_invf[jb + i];
            float c = cosf(ang), sn = sinf(ang);
            ov[i] = lohalf ? (vv[i] * c + uu[i] * sn) : (-uu[i] * sn + vv[i] * c);
        }
        *(float4*)&p[lane * 4] = make_float4(ov[0], ov[1], ov[2], ov[3]);
    }
}

// ---------------- attention v2: CTA per (b, role*8+h, qb) ----------------
__global__ void __launch_bounds__(128) attn2_k(const float* __restrict__ qkv,
                                               const int* __restrict__ doc,
                                               __nv_bfloat16* __restrict__ oh,
                                               __nv_bfloat16* __restrict__ ol) {
    __shared__ __align__(16) float sbuf[8752];
    int qb = blockIdx.x;
    int role = blockIdx.y >> 3;
    int h = blockIdx.y & 7;
    int b = blockIdx.z;
    int t = threadIdx.x;
    int lane = t & 31, w = t >> 5;
    const float* base = qkv + (size_t)b * 2048 * 3072;
    const float* Qb = base + (size_t)h * 128;
    const float* Kb = base + 1024 + (size_t)h * 128;
    const float* Vb = base + 2048 + (size_t)h * 128;
    const float scale = 0.088388347648318447f;

    if (role == 0) {
        float (*qs)[132] = (float(*)[132])sbuf;
        float (*ps)[49]  = (float(*)[49])(sbuf + 6336);
        float* inv = sbuf + 6336 + 2352;
        for (int u = t; u < 48 * 32; u += 128) {
            int rr = u >> 5, c = u & 31;
            *(float4*)&qs[rr][c * 4] =
                *(const float4*)&Qb[(size_t)(qb * 64 + rr) * 3072 + c * 4];
        }
        __syncthreads();
        int tq = t & 15, tk = t >> 4;
        float acc[3][6];
#pragma unroll
        for (int j = 0; j < 3; j++)
#pragma unroll
            for (int i = 0; i < 6; i++) acc[j][i] = 0.f;
#pragma unroll
        for (int dc = 0; dc < 8; dc++) {
            float4 qv[3][4];
#pragma unroll
            for (int j = 0; j < 3; j++)
#pragma unroll
                for (int x = 0; x < 4; x++)
                    qv[j][x] = *(float4*)&qs[tq + 16 * j][dc * 16 + x * 4];
#pragma unroll
            for (int i = 0; i < 6; i++) {
                int k = tk + 8 * i;
                const float4* Kr = (const float4*)&Kb[(size_t)(qb * 64 + k) * 3072 + dc * 16];
#pragma unroll
                for (int x = 0; x < 4; x++) {
                    float4 kv = Kr[x];
#pragma unroll
                    for (int j = 0; j < 3; j++)
                        acc[j][i] += qv[j][x].x * kv.x + qv[j][x].y * kv.y
                                   + qv[j][x].z * kv.z + qv[j][x].w * kv.w;
                }
            }
        }
#pragma unroll
        for (int j = 0; j < 3; j++)
#pragma unroll
            for (int i = 0; i < 6; i++)
                ps[tq + 16 * j][tk + 8 * i] = acc[j][i] * scale;
        __syncthreads();
        for (int j = 0; j < 12; j++) {
            int q = w * 12 + j;
            float v0 = ps[q][lane];
            float v1 = (lane < 16) ? ps[q][lane + 32] : -INFINITY;
            float m = fmaxf(v0, v1);
#pragma unroll
            for (int o = 16; o; o >>= 1) m = fmaxf(m, __shfl_xor_sync(0xffffffffu, m, o));
            float p0 = expf(v0 - m);
            float p1 = (lane < 16) ? expf(v1 - m) : 0.f;
            float s = p0 + p1;
#pragma unroll
            for (int o = 16; o; o >>= 1) s += __shfl_xor_sync(0xffffffffu, s, o);
            ps[q][lane] = p0;
            if (lane < 16) ps[q][lane + 32] = p1;
            if (lane == 0) inv[q] = 1.f / s;
        }
        __syncthreads();
        int tq2 = t & 15, td = t >> 4;
        float a2[3][16];
#pragma unroll
        for (int j = 0; j < 3; j++)
#pragma unroll
            for (int x = 0; x < 16; x++) a2[j][x] = 0.f;
        for (int k = 0; k < 48; k++) {
            const float4* Vr = (const float4*)&Vb[(size_t)(qb * 64 + k) * 3072 + td * 16];
            float4 v[4];
#pragma unroll
            for (int x = 0; x < 4; x++) v[x] = Vr[x];
#pragma unroll
            for (int j = 0; j < 3; j++) {
                float p = ps[tq2 + 16 * j][k];
#pragma unroll
                for (int x = 0; x < 4; x++) {
                    a2[j][x * 4 + 0] += p * v[x].x; a2[j][x * 4 + 1] += p * v[x].y;
                    a2[j][x * 4 + 2] += p * v[x].z; a2[j][x * 4 + 3] += p * v[x].w;
                }
            }
        }
#pragma unroll
        for (int j = 0; j < 3; j++) {
            int q = tq2 + 16 * j;
            float iv = inv[q];
            size_t o = ((size_t)(b * 2048 + qb * 64 + q)) * 1024 + h * 128 + td * 16;
#pragma unroll
            for (int x = 0; x < 16; x++) {
                __nv_bfloat16 fh, fl; bsplit(a2[j][x] * iv, fh, fl);
                oh[o + x] = fh; ol[o + x] = fl;
            }
        }
    } else {
        float (*qs)[132] = (float(*)[132])sbuf;
        float (*ps)[324] = (float(*)[324])(sbuf + 2112);
        int*   kls  = (int*)(sbuf + 2112 + 5184);
        int*   docs = kls + 320;
        float* inv  = (float*)(docs + 32);
        int npb = min(16, qb), np = npb * 16, NK = np + 64;
        if (t < 32) docs[t] = doc[b * 32 + t];
        for (int i = t; i < NK; i += 128) {
            int k;
            if (i < np) { int kb = qb - npb + (i >> 4); k = kb * 64 + 48 + (i & 15); }
            else          k = qb * 64 + (i - np);
            kls[i] = k;
        }
        for (int u = t; u < 16 * 32; u += 128) {
            int rr = u >> 5, c = u & 31;
            *(float4*)&qs[rr][c * 4] =
                *(const float4*)&Qb[(size_t)(qb * 64 + 48 + rr) * 3072 + c * 4];
        }
        __syncthreads();
        int tq = t & 15, tk = t >> 4;
#pragma unroll
        for (int dc = 0; dc < 4; dc++) {
            float4 qv[8];
#pragma unroll
            for (int x = 0; x < 8; x++) qv[x] = *(float4*)&qs[tq][dc * 32 + x * 4];
            for (int ki = tk; ki < NK; ki += 8) {
                const float4* Kr = (const float4*)&Kb[(size_t)kls[ki] * 3072 + dc * 32];
                float a = 0.f;
#pragma unroll
                for (int x = 0; x < 8; x++) {
                    float4 kv = Kr[x];
                    a += qv[x].x * kv.x + qv[x].y * kv.y + qv[x].z * kv.z + qv[x].w * kv.w;
                }
                if (dc == 0) ps[tq][ki] = a; else ps[tq][ki] += a;
            }
        }
        {
            int docq = docs[qb];
            int docp = docs[qb > 0 ? qb - 1 : 0];
            int q = qb * 64 + 48 + tq;
            int posq = (48 + tq) + qb * 16;
            for (int ki = tk; ki < NK; ki += 8) {
                int k = kls[ki];
                int kb = k >> 6, kr = k & 63;
                bool newk = kr >= 48;
                int posk = kr + kb * 16;
                bool nn = newk && (q >= k) && (posq < posk + 256) && (docq == docs[kb]);
                bool ao = (!newk) && (kb == qb) && (docq == docp);
                ps[tq][ki] = (nn || ao) ? ps[tq][ki] * scale : -INFINITY;
            }
        }
        __syncthreads();
        for (int j = 0; j < 4; j++) {
            int q = w * 4 + j;
            float m = -INFINITY;
            for (int i = lane; i < NK; i += 32) m = fmaxf(m, ps[q][i]);
#pragma unroll
            for (int o = 16; o; o >>= 1) m = fmaxf(m, __shfl_xor_sync(0xffffffffu, m, o));
            float s = 0.f;
            for (int i = lane; i < NK; i += 32) {
                float v = ps[q][i];
                float p = (v > -INFINITY) ? expf(v - m) : 0.f;
                ps[q][i] = p;
                s += p;
            }
#pragma unroll
            for (int o = 16; o; o >>= 1) s += __shfl_xor_sync(0xffffffffu, s, o);
            if (lane == 0) inv[q] = 1.f / s;
        }
        __syncthreads();
        int tq3 = t >> 3, td = t & 7;
        float a2[16];
#pragma unroll
        for (int x = 0; x < 16; x++) a2[x] = 0.f;
        for (int ki = 0; ki < NK; ki++) {
            float p = ps[tq3][ki];
            if (p != 0.f) {
                const float4* Vr = (const float4*)&Vb[(size_t)kls[ki] * 3072 + td * 16];
#pragma unroll
                for (int x = 0; x < 4; x++) {
                    float4 v = Vr[x];
                    a2[x * 4 + 0] += p * v.x; a2[x * 4 + 1] += p * v.y;
                    a2[x * 4 + 2] += p * v.z; a2[x * 4 + 3] += p * v.w;
                }
            }
        }
        float iv = inv[tq3];
        size_t o = ((size_t)(b * 2048 + qb * 64 + 48 + tq3)) * 1024 + h * 128 + td * 16;
#pragma unroll
        for (int x = 0; x < 16; x++) {
            __nv_bfloat16 fh, fl; bsplit(a2[x] * iv, fh, fl);
            oh[o + x] = fh; ol[o + x] = fl;
        }
    }
}

// ---------------- assemble x from x_old / x_new ----------------
__global__ void assemble_k(float* __restrict__ x, const float* __restrict__ xold,
                           const float* __restrict__ xnew) {
    int idx = blockIdx.x * blockDim.x + threadIdx.x;
    if (idx >= BP_ * S_ * 256) return;
    int d4 = idx & 255;
    int gr = idx >> 8;
    int b = gr >> 11, s = gr & 2047;
    int l = s >> 6, rr = s & 63;
    float4 v;
    if (rr < 48)
        v = ((const float4*)xold)[((size_t)((b * 32 + l) * 48 + rr)) * 256 + d4];
    else
        v = ((const float4*)xnew)[((size_t)((b * 32 + l) * 16 + (rr - 48))) * 256 + d4];
    ((float4*)x)[idx] = v;
}

// ---------------- extract y = x[:,:,M:,:] (fp32 + split) ----------------
__global__ void extract_y_k(const float* __restrict__ x, float* __restrict__ y,
                            __nv_bfloat16* __restrict__ yh, __nv_bfloat16* __restrict__ yl) {
    int idx = blockIdx.x * blockDim.x + threadIdx.x;
    if (idx >= BP_ * 512 * 256) return;
    int d4 = idx & 255;
    int r = idx >> 8;
    int b = r >> 9, t = r & 511;
    int l = t >> 4, n = t & 15;
    int xr = b * 2048 + l * 64 + 48 + n;
    float4 v = ((const float4*)x)[(size_t)xr * 256 + d4];
    ((float4*)y)[idx] = v;
    __nv_bfloat16 h0, h1, h2, h3, l0, l1, l2, l3;
    bsplit(v.x, h0, l0); bsplit(v.y, h1, l1); bsplit(v.z, h2, l2); bsplit(v.w, h3, l3);
    ((__nv_bfloat162*)yh)[2 * idx]     = __nv_bfloat162(h0, h1);
    ((__nv_bfloat162*)yh)[2 * idx + 1] = __nv_bfloat162(h2, h3);
    ((__nv_bfloat162*)yl)[2 * idx]     = __nv_bfloat162(l0, l1);
    ((__nv_bfloat162*)yl)[2 * idx + 1] = __nv_bfloat162(l2, l3);
}

// ---------------- host helpers ----------------
#define TG_SMEM (3 * 32768)

static void tgemm(const __nv_bfloat16* Ah, const __nv_bfloat16* Al,
                  const __nv_bfloat16* Bh, const __nv_bfloat16* Bl,
                  float* C, __nv_bfloat16* Ch, __nv_bfloat16* Cl,
                  int M, int N, int K, int lda, int ldb, int mode) {
    dim3 grid(N >> 7, M >> 7);
    if (mode == 0) {
        cudaFuncSetAttribute(tgemm_k<0>, cudaFuncAttributeMaxDynamicSharedMemorySize, TG_SMEM);
        tgemm_k<0><<<grid, 128, TG_SMEM>>>(Ah, Al, Bh, Bl, C, Ch, Cl, M, N, K, lda, ldb);
    } else if (mode == 1) {
        cudaFuncSetAttribute(tgemm_k<1>, cudaFuncAttributeMaxDynamicSharedMemorySize, TG_SMEM);
        tgemm_k<1><<<grid, 128, TG_SMEM>>>(Ah, Al, Bh, Bl, C, Ch, Cl, M, N, K, lda, ldb);
    } else if (mode == 2) {
        cudaFuncSetAttribute(tgemm_k<2>, cudaFuncAttributeMaxDynamicSharedMemorySize, TG_SMEM);
        tgemm_k<2><<<grid, 128, TG_SMEM>>>(Ah, Al, Bh, Bl, C, Ch, Cl, M, N, K, lda, ldb);
    } else {
        cudaFuncSetAttribute(tgemm_k<3>, cudaFuncAttributeMaxDynamicSharedMemorySize, TG_SMEM);
        tgemm_k<3><<<grid, 128, TG_SMEM>>>(Ah, Al, Bh, Bl, C, Ch, Cl, M, N, K, lda, ldb);
    }
}

extern "C" void kernel_launch(void* const* d_in, const int* in_sizes, int n_in,
                              void* d_out, int out_size) {
    (void)in_sizes; (void)n_in; (void)out_size;
    const float* x_input     = (const float*)d_in[0];
    const float* x_ar        = (const float*)d_in[1];
    const int*   doc         = (const int*)d_in[2];
    const int*   begin       = (const int*)d_in[3];
    const float* old_norm_w  = (const float*)d_in[4];
    const float* new_norm_w  = (const float*)d_in[5];
    const float* pad_emb     = (const float*)d_in[12];
    const float* attn_norm_w = (const float*)d_in[14];
    const float* ffn_norm_w  = (const float*)d_in[15];
    float* out = (float*)d_out;

    float *x, *qkv, *xold, *xnew, *y;
    __nv_bfloat16 *hh, *hl, *ah, *al, *gh, *gl;
    __nv_bfloat16 *ach, *acl, *yh, *yl, *whi, *wlo;
    cudaGetSymbolAddress((void**)&x,    g_x);
    cudaGetSymbolAddress((void**)&qkv,  g_qkv);
    cudaGetSymbolAddress((void**)&xold, g_xold);
    cudaGetSymbolAddress((void**)&xnew, g_xnew);
    cudaGetSymbolAddress((void**)&y,    g_y);
    cudaGetSymbolAddress((void**)&hh,   g_hh);
    cudaGetSymbolAddress((void**)&hl,   g_hl);
    cudaGetSymbolAddress((void**)&ah,   g_ah);
    cudaGetSymbolAddress((void**)&al,   g_al);
    cudaGetSymbolAddress((void**)&gh,   g_gh);
    cudaGetSymbolAddress((void**)&gl,   g_gl);
    cudaGetSymbolAddress((void**)&ach,  g_ach);
    cudaGetSymbolAddress((void**)&acl,  g_acl);
    cudaGetSymbolAddress((void**)&yh,   g_yh);
    cudaGetSymbolAddress((void**)&yl,   g_yl);
    cudaGetSymbolAddress((void**)&whi,  g_whi);
    cudaGetSymbolAddress((void**)&wlo,  g_wlo);

    init_invf_k<<<1, 64>>>();

    WSrc ws;
    ws.p[0]  = (const float*)d_in[6];   // w_old
    ws.p[1]  = (const float*)d_in[13];  // w_agg
    ws.p[2]  = (const float*)d_in[16];  // w_qkv
    ws.p[3]  = (const float*)d_in[17];  // w_o
    ws.p[4]  = (const float*)d_in[18];  // w_up (rows interleaved at split)
    ws.p[5]  = (const float*)d_in[19];  // w_down
    ws.p[6]  = (const float*)d_in[7];   // w_ar   -> wp2 col 0
    ws.p[7]  = (const float*)d_in[8];   // w_de   -> wp2 col 1024
    ws.p[8]  = (const float*)d_in[9];   // w_ar1  -> wp3 col 0
    ws.p[9]  = (const float*)d_in[10];  // w_de1  -> wp3 col 1024
    ws.p[10] = (const float*)d_in[11];  // w_y1   -> wp3 col 2048
    wsplit_all_k<<<dim3(64, 27), 256>>>(ws, whi, wlo);

    // input projections
    rmsnorm_k<<<3072, 256>>>(x_input, old_norm_w, hh, hl, 48, 64, 0, 1024, 0);
    tgemm(hh, hl, whi + (size_t)OFF_WOLD * MB1, wlo + (size_t)OFF_WOLD * MB1,
          xold, 0, 0, 3072, 1024, 1024, 1024, 1024, 0);
    rmsnorm_k<<<1024, 256>>>(x_ar,    new_norm_w, ach, acl, 16, 16, 0,  3072, 0);
    rmsnorm_k<<<1024, 256>>>(x_input, new_norm_w, ach, acl, 16, 64, 48, 3072, 1024);
    tgemm(ach, acl, whi + (size_t)OFF_WP2 * MB1, wlo + (size_t)OFF_WP2 * MB1,
          xnew, 0, 0, 1024, 1024, 2048, 3072, 2048, 0);
    assemble_k<<<(BP_ * S_ * 256 + 255) / 256, 256>>>(x, xold, xnew);

    for (int it = 0; it < 2; it++) {
        for (int li = 0; li < 2; li++) {
            const __nv_bfloat16* wq_h = whi + (size_t)(OFF_WQKV + 3 * li) * MB1;
            const __nv_bfloat16* wq_l = wlo + (size_t)(OFF_WQKV + 3 * li) * MB1;
            const __nv_bfloat16* wo_h = whi + (size_t)(OFF_WO + li) * MB1;
            const __nv_bfloat16* wo_l = wlo + (size_t)(OFF_WO + li) * MB1;
            const __nv_bfloat16* wu_h = whi + (size_t)(OFF_WUP + 4 * li) * MB1;
            const __nv_bfloat16* wu_l = wlo + (size_t)(OFF_WUP + 4 * li) * MB1;
            const __nv_bfloat16* wd_h = whi + (size_t)(OFF_WDOWN + 2 * li) * MB1;
            const __nv_bfloat16* wd_l = wlo + (size_t)(OFF_WDOWN + 2 * li) * MB1;

            rmsnorm_k<<<4096, 256>>>(x, attn_norm_w + li * 1024, hh, hl, 1, 1, 0, 1024, 0);
            tgemm(hh, hl, wq_h, wq_l, qkv, 0, 0, 4096, 3072, 1024, 1024, 1024, 0);
            qk_rope_k<<<dim3(2048, 2), 256>>>(qkv);
            attn2_k<<<dim3(32, 16, 2), 128>>>(qkv, doc, ah, al);
            tgemm(ah, al, wo_h, wo_l, x, 0, 0, 4096, 1024, 1024, 1024, 1024, 1);
            rmsnorm_k<<<4096, 256>>>(x, ffn_norm_w + li * 1024, hh, hl, 1, 1, 0, 1024, 0);
            // fused up + silu-gate: writes split-bf16 gate (4096 x 2048) directly
            tgemm(hh, hl, wu_h, wu_l, 0, gh, gl, 4096, 4096, 1024, 1024, 1024, 3);
            tgemm(gh, gl, wd_h, wd_l, x, 0, 0, 4096, 1024, 2048, 2048, 2048, 1);
        }
        extract_y_k<<<(BP_ * 512 * 256 + 255) / 256, 256>>>(x, y, yh, yl);
        if (it == 0) {
            yfrms_k<<<1024, 256>>>(y, begin, pad_emb, new_norm_w, ach, acl);
            tgemm(ach, acl, whi + (size_t)OFF_WP3 * MB1, wlo + (size_t)OFF_WP3 * MB1,
                  xnew, 0, 0, 1024, 1024, 3072, 3072, 3072, 0);
            assemble_k<<<(BP_ * S_ * 256 + 255) / 256, 256>>>(x, xold, xnew);
        }
    }

    tgemm(yh, yl, whi + (size_t)OFF_WAGG * MB1, wlo + (size_t)OFF_WAGG * MB1,
          out, 0, 0, 1024, 1024, 1024, 1024, 1024, 0);
}